// round 8
// baseline (speedup 1.0000x reference)
#include <cuda_runtime.h>
#include <math.h>

#define Bb      64
#define Tt      128
#define Dd      768
#define Hh      256
#define NSPANS  8256
#define KTOP    256
#define XST     68          // head/proj stride
#define RST     132         // proj xs row-stride
#define XDST    66          // scorer xsdup row-stride in u64 (64 rows + pad, keeps 16B align)

typedef unsigned long long u64;

// ---------------- packed fp32x2 helpers (sm_103a FFMA2 path) ----------------
__device__ __forceinline__ u64 dup2(float a) {
    u64 r; asm("mov.b64 %0, {%1, %2};" : "=l"(r) : "f"(a), "f"(a)); return r;
}
__device__ __forceinline__ void fma2(u64& acc, u64 a, u64 b) {
    asm("fma.rn.f32x2 %0, %1, %2, %0;" : "+l"(acc) : "l"(a), "l"(b));
}
__device__ __forceinline__ void unpack2(float& lo, float& hi, u64 v) {
    asm("mov.b64 {%0, %1}, %2;" : "=f"(lo), "=f"(hi) : "l"(v));
}
__device__ __forceinline__ void lds_pair(u64& x, u64& y, const float* p) {
    unsigned addr = (unsigned)__cvta_generic_to_shared(p);
    asm volatile("ld.shared.v2.u64 {%0, %1}, [%2];" : "=l"(x), "=l"(y) : "r"(addr));
}
__device__ __forceinline__ void lds_pair_u64(u64& x, u64& y, const u64* p) {
    unsigned addr = (unsigned)__cvta_generic_to_shared(p);
    asm volatile("ld.shared.v2.u64 {%0, %1}, [%2];" : "=l"(x), "=l"(y) : "r"(addr));
}

// ---------------- device scratch ----------------
__device__ float g_A[Bb*Tt*Hh];
__device__ float g_E[Bb*Tt*Hh];
__device__ float g_scores[Bb*NSPANS];
__device__ float g_inj[Bb*Hh];
__device__ int   g_topidx[Bb*KTOP];
__device__ float g_topscore[Bb*KTOP];
__device__ int   g_sarr[NSPANS];
__device__ int   g_earr[NSPANS];

// ---------------- span index decode ----------------
__global__ void build_span_idx_kernel() {
    int n = blockIdx.x * blockDim.x + threadIdx.x;
    if (n >= NSPANS) return;
    int s = 0, off = 0;
    while (n >= off + (Tt - s)) { off += (Tt - s); s++; }
    g_sarr[n] = s;
    g_earr[n] = s + (n - off);
}

// ---------------- projections: X[8192,768]@W[768,256]+b ----------------
__global__ __launch_bounds__(256)
void proj_kernel(const float* __restrict__ X,
                 const float* __restrict__ Wst, const float* __restrict__ bst,
                 const float* __restrict__ Wen, const float* __restrict__ ben) {
    const float* W    = blockIdx.z ? Wen : Wst;
    const float* bias = blockIdx.z ? ben : bst;
    float*       Out  = blockIdx.z ? g_E : g_A;

    __shared__ float xs[32 * RST];
    __shared__ float wsm[32 * XST];

    const int row0 = blockIdx.y * 128;
    const int col0 = blockIdx.x * 64;
    const int tid  = threadIdx.x;
    const int tx   = tid & 15, ty = tid >> 4;

    u64 acc[8][2] = {};
    for (int k0 = 0; k0 < Dd; k0 += 32) {
        __syncthreads();
        #pragma unroll
        for (int idx = tid; idx < 128 * 32; idx += 256) {
            int r = idx >> 5, k = idx & 31;
            xs[k * RST + r] = X[(row0 + r) * Dd + k0 + k];
        }
        #pragma unroll
        for (int idx = tid; idx < 32 * 64; idx += 256) {
            int k = idx >> 6, cc = idx & 63;
            wsm[k * XST + cc] = W[(k0 + k) * Hh + col0 + cc];
        }
        __syncthreads();
        #pragma unroll 4
        for (int k = 0; k < 32; k++) {
            const float4 a0 = *(const float4*)(xs + k * RST + (ty << 3));
            const float4 a1 = *(const float4*)(xs + k * RST + (ty << 3) + 4);
            u64 w0, w1;
            lds_pair(w0, w1, wsm + k * XST + (tx << 2));
            u64 d0 = dup2(a0.x), d1 = dup2(a0.y), d2 = dup2(a0.z), d3 = dup2(a0.w);
            u64 d4 = dup2(a1.x), d5 = dup2(a1.y), d6 = dup2(a1.z), d7 = dup2(a1.w);
            fma2(acc[0][0], d0, w0); fma2(acc[0][1], d0, w1);
            fma2(acc[1][0], d1, w0); fma2(acc[1][1], d1, w1);
            fma2(acc[2][0], d2, w0); fma2(acc[2][1], d2, w1);
            fma2(acc[3][0], d3, w0); fma2(acc[3][1], d3, w1);
            fma2(acc[4][0], d4, w0); fma2(acc[4][1], d4, w1);
            fma2(acc[5][0], d5, w0); fma2(acc[5][1], d5, w1);
            fma2(acc[6][0], d6, w0); fma2(acc[6][1], d6, w1);
            fma2(acc[7][0], d7, w0); fma2(acc[7][1], d7, w1);
        }
    }
    #pragma unroll
    for (int i = 0; i < 8; i++) {
        int row = row0 + (ty << 3) + i;
        #pragma unroll
        for (int p = 0; p < 2; p++) {
            float lo, hi; unpack2(lo, hi, acc[i][p]);
            int col = col0 + (tx << 2) + 2 * p;
            Out[row * Hh + col]     = lo + bias[col];
            Out[row * Hh + col + 1] = hi + bias[col + 1];
        }
    }
}

// ---------------- injection projection ----------------
__global__ void inj_kernel(const float* __restrict__ tie,
                           const float* __restrict__ Winj, const float* __restrict__ binj) {
    int b = blockIdx.x;
    int j = threadIdx.x;
    __shared__ float t[128];
    if (j < 128) t[j] = tie[b * 128 + j];
    __syncthreads();
    float acc = binj[j];
    #pragma unroll 8
    for (int k = 0; k < 128; k++) acc = fmaf(t[k], Winj[k * Hh + j], acc);
    g_inj[b * Hh + j] = acc;
}

// ---------------- fused span scorer: 256 thr, 64 spans x 256 cols, MOV-free inner loop ----------------
// dynamic smem (floats):
//   xsdup: 32kk x XDST u64 (pre-duplicated activations)   = 4224 floats
//   wsL:   32kk x 128                                     = 4096
//   wsH:   32kk x 128                                     = 4096
//   bias:  256,  w2: 256
// red (64 x 33) aliases wsL after last chunk.
#define SC_XD_FLOATS   (32 * XDST * 2)
#define SC_WSL_OFF     SC_XD_FLOATS
#define SC_WSH_OFF     (SC_WSL_OFF + 32 * 128)
#define SC_BIAS_OFF    (SC_WSH_OFF + 32 * 128)
#define SC_W2_OFF      (SC_BIAS_OFF + 256)
#define SC_SMEM_FLOATS (SC_W2_OFF + 256)
static const int SC_SMEM_BYTES = SC_SMEM_FLOATS * 4;   // 51,712 B

__global__ __launch_bounds__(256, 2)
void scorer_kernel(const float* __restrict__ Ws1, const float* __restrict__ bs1,
                   const float* __restrict__ Ws2, const float* __restrict__ bs2) {
    extern __shared__ float sm[];
    u64*   xd   = (u64*)sm;                  // [kk=32][XDST u64] packed (x,x)
    float* wsL  = sm + SC_WSL_OFF;           // [kk=32][128] cols 8g..8g+3
    float* wsH  = sm + SC_WSH_OFF;           // [kk=32][128] cols 8g+4..8g+7
    float* bs1c = sm + SC_BIAS_OFF;          // 256
    float* w2c  = sm + SC_W2_OFF;            // 256
    float* red  = wsL;                       // aliased after last chunk
    __shared__ int sS[64], sE[64];

    const int b   = blockIdx.y;
    const int n0  = blockIdx.x * 64;
    const int tid = threadIdx.x;
    const int tx  = tid & 31;        // 32 col-groups of 8
    const int ty  = tid >> 5;        // 8 row-groups of 8 (warp id)

    if (tid < 64) {
        sS[tid] = g_sarr[n0 + tid]; sE[tid] = g_earr[n0 + tid];
    }
    bs1c[tid] = bs1[tid];
    w2c[tid]  = Ws2[tid];

    const float* Ag = g_A + b * Tt * Hh;
    const float* Eg = g_E + b * Tt * Hh;

    u64 acc[8][4] = {};

    const int kkl   = tid & 31;      // lane -> k within chunk (coalesced global gather)
    const int rbase = tid >> 5;

    #pragma unroll 1
    for (int kc = 0; kc < 8; kc++) {
        const int k0 = kc << 5;
        __syncthreads();

        // ---- stage activations: gather relu(A+E) from global, store duplicated u64 ----
        {
            const float* Ap = Ag + k0 + kkl;
            const float* Ep = Eg + k0 + kkl;
            #pragma unroll
            for (int it = 0; it < 8; it++) {
                int r = rbase + (it << 3);
                float v = Ap[sS[r] * Hh] + Ep[sE[r] * Hh];
                v = v > 0.f ? v : 0.f;
                xd[kkl * XDST + r] = dup2(v);
            }
        }
        // ---- stage 32k x 256c weights, even/odd float4 split into wsL/wsH ----
        #pragma unroll
        for (int idx = tid; idx < 2048; idx += 256) {
            int kk = idx >> 6, c4 = idx & 63;
            float4 f = ((const float4*)(Ws1 + (k0 + kk) * Hh))[c4];
            float4* dst = (c4 & 1) ? (float4*)wsH : (float4*)wsL;
            dst[kk * 32 + (c4 >> 1)] = f;
        }
        __syncthreads();

        const u64*   xp = xd + (ty << 3);
        const float* wl = wsL + (tx << 2);
        const float* wh = wsH + (tx << 2);
        #pragma unroll 2
        for (int k = 0; k < 32; k++) {
            u64 d0, d1, d2, d3, d4, d5, d6, d7;
            const u64* xr = xp + k * XDST;
            lds_pair_u64(d0, d1, xr);        // broadcast, 16B-aligned
            lds_pair_u64(d2, d3, xr + 2);
            lds_pair_u64(d4, d5, xr + 4);
            lds_pair_u64(d6, d7, xr + 6);
            u64 w0, w1, w2, w3;
            lds_pair(w0, w1, wl + (k << 7)); // 16B/lane stride, conflict-free
            lds_pair(w2, w3, wh + (k << 7));
            fma2(acc[0][0], d0, w0); fma2(acc[0][1], d0, w1);
            fma2(acc[0][2], d0, w2); fma2(acc[0][3], d0, w3);
            fma2(acc[1][0], d1, w0); fma2(acc[1][1], d1, w1);
            fma2(acc[1][2], d1, w2); fma2(acc[1][3], d1, w3);
            fma2(acc[2][0], d2, w0); fma2(acc[2][1], d2, w1);
            fma2(acc[2][2], d2, w2); fma2(acc[2][3], d2, w3);
            fma2(acc[3][0], d3, w0); fma2(acc[3][1], d3, w1);
            fma2(acc[3][2], d3, w2); fma2(acc[3][3], d3, w3);
            fma2(acc[4][0], d4, w0); fma2(acc[4][1], d4, w1);
            fma2(acc[4][2], d4, w2); fma2(acc[4][3], d4, w3);
            fma2(acc[5][0], d5, w0); fma2(acc[5][1], d5, w1);
            fma2(acc[5][2], d5, w2); fma2(acc[5][3], d5, w3);
            fma2(acc[6][0], d6, w0); fma2(acc[6][1], d6, w1);
            fma2(acc[6][2], d6, w2); fma2(acc[6][3], d6, w3);
            fma2(acc[7][0], d7, w0); fma2(acc[7][1], d7, w1);
            fma2(acc[7][2], d7, w2); fma2(acc[7][3], d7, w3);
        }
    }

    // layer-2 epilogue; acc[i][p] -> cols 8tx+2p, 8tx+2p+1
    float scacc[8] = {0.f, 0.f, 0.f, 0.f, 0.f, 0.f, 0.f, 0.f};
    #pragma unroll
    for (int i = 0; i < 8; i++) {
        #pragma unroll
        for (int p = 0; p < 4; p++) {
            float lo, hi; unpack2(lo, hi, acc[i][p]);
            int cb = (tx << 3) + 2 * p;
            float h0 = lo + bs1c[cb];
            if (h0 > 0.f) scacc[i] = fmaf(h0, w2c[cb], scacc[i]);
            float h1 = hi + bs1c[cb + 1];
            if (h1 > 0.f) scacc[i] = fmaf(h1, w2c[cb + 1], scacc[i]);
        }
    }

    __syncthreads();   // ws no longer needed; red aliases it
    #pragma unroll
    for (int i = 0; i < 8; i++) red[((ty << 3) + i) * 33 + tx] = scacc[i];
    __syncthreads();
    if (tid < 64) {
        float ssum = bs2[0];
        const float* rp = red + tid * 33;
        #pragma unroll
        for (int t = 0; t < 32; t++) ssum += rp[t];
        g_scores[b * NSPANS + n0 + tid] = ssum;
    }
}

// ---------------- per-batch radix top-k, parallel stable extraction ----------------
__global__ void topk_kernel(const int* __restrict__ mask) {
    const int b   = blockIdx.x;
    const int tid = threadIdx.x;
    __shared__ unsigned keys[NSPANS];
    __shared__ int hist[256];
    __shared__ unsigned sh_prefix;
    __shared__ int sh_kk;
    __shared__ int sgt[256], seqv[256];

    const int* mb = mask + b * Tt;
    for (int i = tid; i < NSPANS; i += 256) {
        int s = g_sarr[i], e = g_earr[i];
        float v = (mb[s] != 0 && mb[e] != 0) ? g_scores[b * NSPANS + i]
                                             : __int_as_float(0xff800000);
        unsigned u = __float_as_uint(v);
        keys[i] = (u & 0x80000000u) ? ~u : (u | 0x80000000u);
    }

    unsigned prefix = 0;
    int kk = KTOP;
    for (int level = 3; level >= 0; level--) {
        hist[tid] = 0;
        __syncthreads();
        const unsigned himask = (level == 3) ? 0u : (0xFFFFFFFFu << ((level + 1) * 8));
        for (int i = tid; i < NSPANS; i += 256) {
            unsigned kv = keys[i];
            if ((kv & himask) == (prefix & himask))
                atomicAdd(&hist[(kv >> (level * 8)) & 255], 1);
        }
        __syncthreads();
        if (tid == 0) {
            int cum = 0, chosen = 0, kknew = kk;
            for (int t = 255; t >= 0; t--) {
                int c = hist[t];
                if (cum + c >= kk) { chosen = t; kknew = kk - cum; break; }
                cum += c;
            }
            sh_prefix = prefix | ((unsigned)chosen << (level * 8));
            sh_kk = kknew;
        }
        __syncthreads();
        prefix = sh_prefix;
        kk = sh_kk;
        __syncthreads();
    }

    const unsigned Kstar = prefix;
    const int CH = (NSPANS + 255) / 256;
    int lo = tid * CH; if (lo > NSPANS) lo = NSPANS;
    int hi = lo + CH;  if (hi > NSPANS) hi = NSPANS;

    int cgt = 0, ceq = 0;
    for (int i = lo; i < hi; i++) {
        unsigned kv = keys[i];
        cgt += (kv > Kstar);
        ceq += (kv == Kstar);
    }
    sgt[tid] = cgt; seqv[tid] = ceq;
    __syncthreads();
    if (tid == 0) {
        int ag = 0, ae = 0;
        for (int t = 0; t < 256; t++) {
            int g = sgt[t], e = seqv[t];
            sgt[t] = ag; seqv[t] = ae;
            ag += g; ae += e;
        }
    }
    __syncthreads();

    int gtb = sgt[tid], eqb = seqv[tid];
    for (int i = lo; i < hi; i++) {
        unsigned kv = keys[i];
        bool isgt = (kv > Kstar);
        bool iseq = (kv == Kstar);
        if (isgt || (iseq && eqb < kk)) {
            int eqt = eqb < kk ? eqb : kk;
            int pos = gtb + eqt;
            unsigned u = (kv & 0x80000000u) ? (kv & 0x7FFFFFFFu) : ~kv;
            g_topidx[b * KTOP + pos]   = i;
            g_topscore[b * KTOP + pos] = __uint_as_float(u);
        }
        gtb += isgt;
        eqb += iseq;
    }
}

// ---------------- fused head ----------------
#define HD_SMEM_FLOATS (256*XST + 256*128 + 128 + 128 + 64*16)
static const int HD_SMEM_BYTES = HD_SMEM_FLOATS * 4;

__global__ __launch_bounds__(256, 1)
void head_kernel(const float* __restrict__ Wsec, const float* __restrict__ bsec,
                 const float* __restrict__ Wpred, const float* __restrict__ bpred,
                 const int* __restrict__ mask, float* __restrict__ out) {
    extern __shared__ float sm[];
    float* xs  = sm;
    float* ws  = xs + 256 * XST;
    float* bc  = ws + 256 * 128;
    float* wpc = bc + 128;
    float* red = wpc + 128;
    __shared__ int sS[64], sE[64];
    __shared__ float sMask[64], sScore[64];

    const int b   = blockIdx.y;
    const int k0  = blockIdx.x * 64;
    const int tid = threadIdx.x;
    const int tx  = tid & 15, ty = tid >> 4;

    if (tid < 64) {
        int n = g_topidx[b * KTOP + k0 + tid];
        int s = g_sarr[n], e = g_earr[n];
        sS[tid] = s; sE[tid] = e;
        sMask[tid] = (mask[b * Tt + s] != 0 && mask[b * Tt + e] != 0) ? 1.f : 0.f;
        float sc = g_topscore[b * KTOP + k0 + tid];
        sScore[tid] = isinf(sc) ? -1.f : sc;
    }
    __syncthreads();

    const float* Ab = g_A + b * Tt * Hh;
    const float* Eb = g_E + b * Tt * Hh;
    for (int r = 0; r < 64; r++)
        xs[tid * XST + r] = Ab[sS[r] * Hh + tid] + Eb[sE[r] * Hh + tid];

    float scacc[4] = {0.f, 0.f, 0.f, 0.f};

    #pragma unroll 1
    for (int jb = 0; jb < 2; jb++) {
        const int jbase = jb * 128;
        __syncthreads();
        #pragma unroll
        for (int idx = tid; idx < 8192; idx += 256) {
            int k = idx >> 5, c4 = idx & 31;
            ((float4*)ws)[idx] = ((const float4*)(Wsec + k * Hh + jbase))[c4];
        }
        if (tid < 128) {
            bc[tid]  = bsec[jbase + tid] + g_inj[b * Hh + jbase + tid];
            wpc[tid] = Wpred[jbase + tid];
        }
        __syncthreads();

        u64 acc[4][4] = {};
        const float* xp = xs + (ty << 2);
        const float* wl = ws + (tx << 2);
        const float* wh = wl + 64;
        #pragma unroll 4
        for (int k = 0; k < Hh; k++) {
            const float4 a = *(const float4*)(xp + k * XST);
            u64 w0, w1, w2, w3;
            lds_pair(w0, w1, wl + (k << 7));
            lds_pair(w2, w3, wh + (k << 7));
            u64 d0 = dup2(a.x), d1 = dup2(a.y), d2 = dup2(a.z), d3 = dup2(a.w);
            fma2(acc[0][0], d0, w0); fma2(acc[0][1], d0, w1);
            fma2(acc[0][2], d0, w2); fma2(acc[0][3], d0, w3);
            fma2(acc[1][0], d1, w0); fma2(acc[1][1], d1, w1);
            fma2(acc[1][2], d1, w2); fma2(acc[1][3], d1, w3);
            fma2(acc[2][0], d2, w0); fma2(acc[2][1], d2, w1);
            fma2(acc[2][2], d2, w2); fma2(acc[2][3], d2, w3);
            fma2(acc[3][0], d3, w0); fma2(acc[3][1], d3, w1);
            fma2(acc[3][2], d3, w2); fma2(acc[3][3], d3, w3);
        }
        #pragma unroll
        for (int i = 0; i < 4; i++) {
            #pragma unroll
            for (int p = 0; p < 4; p++) {
                float lo, hi; unpack2(lo, hi, acc[i][p]);
                int cb = (p < 2) ? ((tx << 2) + 2 * p) : (64 + (tx << 2) + 2 * (p - 2));
                float h0 = lo + bc[cb];
                if (h0 > 0.f) scacc[i] = fmaf(h0, wpc[cb], scacc[i]);
                float h1 = hi + bc[cb + 1];
                if (h1 > 0.f) scacc[i] = fmaf(h1, wpc[cb + 1], scacc[i]);
            }
        }
    }

    __syncthreads();
    #pragma unroll
    for (int i = 0; i < 4; i++) red[((ty << 2) + i) * 16 + tx] = scacc[i];
    __syncthreads();
    if (tid < 64) {
        float ssum = bpred[0] + sScore[tid];
        #pragma unroll
        for (int t = 0; t < 16; t++) ssum += red[tid * 16 + t];
        float p = 1.f / (1.f + expf(-ssum));
        out[b * KTOP + k0 + tid] = p * sMask[tid];
    }
}

// ---------------- launch ----------------
extern "C" void kernel_launch(void* const* d_in, const int* in_sizes, int n_in,
                              void* d_out, int out_size) {
    const float* inputs   = (const float*)d_in[0];
    const int*   in_mask  = (const int*)  d_in[1];
    const float* tie      = (const float*)d_in[2];
    const float* W_start  = (const float*)d_in[3];
    const float* b_start  = (const float*)d_in[4];
    const float* W_end    = (const float*)d_in[5];
    const float* b_end    = (const float*)d_in[6];
    const float* W_s1     = (const float*)d_in[7];
    const float* b_s1     = (const float*)d_in[8];
    const float* W_s2     = (const float*)d_in[9];
    const float* b_s2     = (const float*)d_in[10];
    const float* W_inj    = (const float*)d_in[11];
    const float* b_inj    = (const float*)d_in[12];
    const float* W_sec    = (const float*)d_in[13];
    const float* b_sec    = (const float*)d_in[14];
    const float* W_pred   = (const float*)d_in[15];
    const float* b_pred   = (const float*)d_in[16];
    float* out = (float*)d_out;

    cudaFuncSetAttribute(scorer_kernel, cudaFuncAttributeMaxDynamicSharedMemorySize, SC_SMEM_BYTES);
    cudaFuncSetAttribute(head_kernel,   cudaFuncAttributeMaxDynamicSharedMemorySize, HD_SMEM_BYTES);

    build_span_idx_kernel<<<(NSPANS + 255) / 256, 256>>>();
    proj_kernel<<<dim3(Hh / 64, (Bb * Tt) / 128, 2), 256>>>(inputs, W_start, b_start, W_end, b_end);
    inj_kernel<<<Bb, 256>>>(tie, W_inj, b_inj);
    scorer_kernel<<<dim3(NSPANS / 64, Bb), 256, SC_SMEM_BYTES>>>(W_s1, b_s1, W_s2, b_s2);
    topk_kernel<<<Bb, 256>>>(in_mask);
    head_kernel<<<dim3(KTOP / 64, Bb), 256, HD_SMEM_BYTES>>>(W_sec, b_sec, W_pred, b_pred, in_mask, out);
}

// round 9
// speedup vs baseline: 1.2581x; 1.2581x over previous
#include <cuda_runtime.h>
#include <math.h>

#define Bb      64
#define Tt      128
#define Dd      768
#define Hh      256
#define NSPANS  8256
#define KTOP    256
#define XST     68          // head/proj stride
#define RST     132         // proj xs row-stride
#define SXST    68          // scorer xs row-stride (64 rows + pad, 16B-aligned)

typedef unsigned long long u64;

// ---------------- packed fp32x2 helpers (sm_103a FFMA2 path) ----------------
__device__ __forceinline__ u64 dup2(float a) {
    u64 r; asm("mov.b64 %0, {%1, %2};" : "=l"(r) : "f"(a), "f"(a)); return r;
}
__device__ __forceinline__ void fma2(u64& acc, u64 a, u64 b) {
    asm("fma.rn.f32x2 %0, %1, %2, %0;" : "+l"(acc) : "l"(a), "l"(b));
}
__device__ __forceinline__ void unpack2(float& lo, float& hi, u64 v) {
    asm("mov.b64 {%0, %1}, %2;" : "=f"(lo), "=f"(hi) : "l"(v));
}
__device__ __forceinline__ void lds_pair(u64& x, u64& y, const float* p) {
    unsigned addr = (unsigned)__cvta_generic_to_shared(p);
    asm volatile("ld.shared.v2.u64 {%0, %1}, [%2];" : "=l"(x), "=l"(y) : "r"(addr));
}

// ---------------- device scratch ----------------
__device__ float g_A[Bb*Tt*Hh];
__device__ float g_E[Bb*Tt*Hh];
__device__ float g_scores[Bb*NSPANS];
__device__ float g_inj[Bb*Hh];
__device__ int   g_topidx[Bb*KTOP];
__device__ float g_topscore[Bb*KTOP];
__device__ int   g_sarr[NSPANS];
__device__ int   g_earr[NSPANS];

// ---------------- span index decode ----------------
__global__ void build_span_idx_kernel() {
    int n = blockIdx.x * blockDim.x + threadIdx.x;
    if (n >= NSPANS) return;
    int s = 0, off = 0;
    while (n >= off + (Tt - s)) { off += (Tt - s); s++; }
    g_sarr[n] = s;
    g_earr[n] = s + (n - off);
}

// ---------------- projections: X[8192,768]@W[768,256]+b ----------------
__global__ __launch_bounds__(256)
void proj_kernel(const float* __restrict__ X,
                 const float* __restrict__ Wst, const float* __restrict__ bst,
                 const float* __restrict__ Wen, const float* __restrict__ ben) {
    const float* W    = blockIdx.z ? Wen : Wst;
    const float* bias = blockIdx.z ? ben : bst;
    float*       Out  = blockIdx.z ? g_E : g_A;

    __shared__ float xs[32 * RST];
    __shared__ float wsm[32 * XST];

    const int row0 = blockIdx.y * 128;
    const int col0 = blockIdx.x * 64;
    const int tid  = threadIdx.x;
    const int tx   = tid & 15, ty = tid >> 4;

    u64 acc[8][2] = {};
    for (int k0 = 0; k0 < Dd; k0 += 32) {
        __syncthreads();
        #pragma unroll
        for (int idx = tid; idx < 128 * 32; idx += 256) {
            int r = idx >> 5, k = idx & 31;
            xs[k * RST + r] = X[(row0 + r) * Dd + k0 + k];
        }
        #pragma unroll
        for (int idx = tid; idx < 32 * 64; idx += 256) {
            int k = idx >> 6, cc = idx & 63;
            wsm[k * XST + cc] = W[(k0 + k) * Hh + col0 + cc];
        }
        __syncthreads();
        #pragma unroll 4
        for (int k = 0; k < 32; k++) {
            const float4 a0 = *(const float4*)(xs + k * RST + (ty << 3));
            const float4 a1 = *(const float4*)(xs + k * RST + (ty << 3) + 4);
            u64 w0, w1;
            lds_pair(w0, w1, wsm + k * XST + (tx << 2));
            u64 d0 = dup2(a0.x), d1 = dup2(a0.y), d2 = dup2(a0.z), d3 = dup2(a0.w);
            u64 d4 = dup2(a1.x), d5 = dup2(a1.y), d6 = dup2(a1.z), d7 = dup2(a1.w);
            fma2(acc[0][0], d0, w0); fma2(acc[0][1], d0, w1);
            fma2(acc[1][0], d1, w0); fma2(acc[1][1], d1, w1);
            fma2(acc[2][0], d2, w0); fma2(acc[2][1], d2, w1);
            fma2(acc[3][0], d3, w0); fma2(acc[3][1], d3, w1);
            fma2(acc[4][0], d4, w0); fma2(acc[4][1], d4, w1);
            fma2(acc[5][0], d5, w0); fma2(acc[5][1], d5, w1);
            fma2(acc[6][0], d6, w0); fma2(acc[6][1], d6, w1);
            fma2(acc[7][0], d7, w0); fma2(acc[7][1], d7, w1);
        }
    }
    #pragma unroll
    for (int i = 0; i < 8; i++) {
        int row = row0 + (ty << 3) + i;
        #pragma unroll
        for (int p = 0; p < 2; p++) {
            float lo, hi; unpack2(lo, hi, acc[i][p]);
            int col = col0 + (tx << 2) + 2 * p;
            Out[row * Hh + col]     = lo + bias[col];
            Out[row * Hh + col + 1] = hi + bias[col + 1];
        }
    }
}

// ---------------- injection projection ----------------
__global__ void inj_kernel(const float* __restrict__ tie,
                           const float* __restrict__ Winj, const float* __restrict__ binj) {
    int b = blockIdx.x;
    int j = threadIdx.x;
    __shared__ float t[128];
    if (j < 128) t[j] = tie[b * 128 + j];
    __syncthreads();
    float acc = binj[j];
    #pragma unroll 8
    for (int k = 0; k < 128; k++) acc = fmaf(t[k], Winj[k * Hh + j], acc);
    g_inj[b * Hh + j] = acc;
}

// ---------------- fused span scorer: 256 thr, 64 spans x 256 cols, pipelined inner loop ----------------
#define SC_XS_FLOATS   (256 * SXST)
#define SC_WSL_OFF     SC_XS_FLOATS
#define SC_WSH_OFF     (SC_WSL_OFF + 32 * 128)
#define SC_BIAS_OFF    (SC_WSH_OFF + 32 * 128)
#define SC_W2_OFF      (SC_BIAS_OFF + 256)
#define SC_SMEM_FLOATS (SC_W2_OFF + 256)
static const int SC_SMEM_BYTES = SC_SMEM_FLOATS * 4;   // 104,448 B -> 2 CTAs/SM

__global__ __launch_bounds__(256, 2)
void scorer_kernel(const float* __restrict__ Ws1, const float* __restrict__ bs1,
                   const float* __restrict__ Ws2, const float* __restrict__ bs2) {
    extern __shared__ float sm[];
    float* xs   = sm;                        // [k=256][r, stride SXST]
    float* wsL  = sm + SC_WSL_OFF;           // [kk=32][128] cols 8g..8g+3
    float* wsH  = sm + SC_WSH_OFF;           // [kk=32][128] cols 8g+4..8g+7
    float* bs1c = sm + SC_BIAS_OFF;          // 256
    float* w2c  = sm + SC_W2_OFF;            // 256
    float* red  = wsL;                       // aliased after last chunk
    __shared__ int sS[64], sE[64];

    const int b   = blockIdx.y;
    const int n0  = blockIdx.x * 64;
    const int tid = threadIdx.x;
    const int tx  = tid & 31;        // 32 col-groups of 8
    const int ty  = tid >> 5;        // 8 row-groups of 8

    if (tid < 64) {
        sS[tid] = g_sarr[n0 + tid]; sE[tid] = g_earr[n0 + tid];
    }
    bs1c[tid] = bs1[tid];
    w2c[tid]  = Ws2[tid];
    __syncthreads();

    // fill xs[k][r] = relu(A[s_r][k] + E[e_r][k]); thread owns column k = tid
    {
        const float* Ab = g_A + b * Tt * Hh + tid;
        const float* Eb = g_E + b * Tt * Hh + tid;
        float* xp = xs + tid * SXST;
        #pragma unroll 4
        for (int r = 0; r < 64; r++) {
            float v = Ab[sS[r] * Hh] + Eb[sE[r] * Hh];
            xp[r] = v > 0.f ? v : 0.f;
        }
    }

    u64 acc[8][4] = {};

    #pragma unroll 1
    for (int kc = 0; kc < 8; kc++) {
        const int k0 = kc << 5;
        __syncthreads();
        // stage 32k x 256c weights, even/odd float4 split into wsL/wsH
        #pragma unroll
        for (int idx = tid; idx < 2048; idx += 256) {
            int kk = idx >> 6, c4 = idx & 63;
            float4 f = ((const float4*)(Ws1 + (k0 + kk) * Hh))[c4];
            float4* dst = (c4 & 1) ? (float4*)wsH : (float4*)wsL;
            dst[kk * 32 + (c4 >> 1)] = f;
        }
        __syncthreads();

        const float* xp = xs + k0 * SXST + (ty << 3);
        const float* wl = wsL + (tx << 2);
        const float* wh = wsH + (tx << 2);

        // ---- explicit 1-deep software pipeline, plain (schedulable) loads ----
        float4 a0 = *(const float4*)(xp);
        float4 a1 = *(const float4*)(xp + 4);
        ulonglong2 wA = *(const ulonglong2*)(wl);
        ulonglong2 wB = *(const ulonglong2*)(wh);

        #pragma unroll
        for (int k = 0; k < 32; k++) {
            float4 na0, na1;
            ulonglong2 nA, nB;
            if (k < 31) {
                na0 = *(const float4*)(xp + (k + 1) * SXST);
                na1 = *(const float4*)(xp + (k + 1) * SXST + 4);
                nA  = *(const ulonglong2*)(wl + ((k + 1) << 7));
                nB  = *(const ulonglong2*)(wh + ((k + 1) << 7));
            }
            u64 w0 = wA.x, w1 = wA.y, w2 = wB.x, w3 = wB.y;
            u64 d0 = dup2(a0.x), d1 = dup2(a0.y), d2 = dup2(a0.z), d3 = dup2(a0.w);
            u64 d4 = dup2(a1.x), d5 = dup2(a1.y), d6 = dup2(a1.z), d7 = dup2(a1.w);
            fma2(acc[0][0], d0, w0); fma2(acc[0][1], d0, w1);
            fma2(acc[0][2], d0, w2); fma2(acc[0][3], d0, w3);
            fma2(acc[1][0], d1, w0); fma2(acc[1][1], d1, w1);
            fma2(acc[1][2], d1, w2); fma2(acc[1][3], d1, w3);
            fma2(acc[2][0], d2, w0); fma2(acc[2][1], d2, w1);
            fma2(acc[2][2], d2, w2); fma2(acc[2][3], d2, w3);
            fma2(acc[3][0], d3, w0); fma2(acc[3][1], d3, w1);
            fma2(acc[3][2], d3, w2); fma2(acc[3][3], d3, w3);
            fma2(acc[4][0], d4, w0); fma2(acc[4][1], d4, w1);
            fma2(acc[4][2], d4, w2); fma2(acc[4][3], d4, w3);
            fma2(acc[5][0], d5, w0); fma2(acc[5][1], d5, w1);
            fma2(acc[5][2], d5, w2); fma2(acc[5][3], d5, w3);
            fma2(acc[6][0], d6, w0); fma2(acc[6][1], d6, w1);
            fma2(acc[6][2], d6, w2); fma2(acc[6][3], d6, w3);
            fma2(acc[7][0], d7, w0); fma2(acc[7][1], d7, w1);
            fma2(acc[7][2], d7, w2); fma2(acc[7][3], d7, w3);
            a0 = na0; a1 = na1; wA = nA; wB = nB;
        }
    }

    // layer-2 epilogue; acc[i][p] -> cols 8tx+2p, 8tx+2p+1
    float scacc[8] = {0.f, 0.f, 0.f, 0.f, 0.f, 0.f, 0.f, 0.f};
    #pragma unroll
    for (int i = 0; i < 8; i++) {
        #pragma unroll
        for (int p = 0; p < 4; p++) {
            float lo, hi; unpack2(lo, hi, acc[i][p]);
            int cb = (tx << 3) + 2 * p;
            float h0 = lo + bs1c[cb];
            if (h0 > 0.f) scacc[i] = fmaf(h0, w2c[cb], scacc[i]);
            float h1 = hi + bs1c[cb + 1];
            if (h1 > 0.f) scacc[i] = fmaf(h1, w2c[cb + 1], scacc[i]);
        }
    }

    __syncthreads();   // ws no longer needed; red aliases it
    #pragma unroll
    for (int i = 0; i < 8; i++) red[((ty << 3) + i) * 33 + tx] = scacc[i];
    __syncthreads();
    if (tid < 64) {
        float ssum = bs2[0];
        const float* rp = red + tid * 33;
        #pragma unroll
        for (int t = 0; t < 32; t++) ssum += rp[t];
        g_scores[b * NSPANS + n0 + tid] = ssum;
    }
}

// ---------------- per-batch radix top-k, parallel stable extraction ----------------
__global__ void topk_kernel(const int* __restrict__ mask) {
    const int b   = blockIdx.x;
    const int tid = threadIdx.x;
    __shared__ unsigned keys[NSPANS];
    __shared__ int hist[256];
    __shared__ unsigned sh_prefix;
    __shared__ int sh_kk;
    __shared__ int sgt[256], seqv[256];

    const int* mb = mask + b * Tt;
    for (int i = tid; i < NSPANS; i += 256) {
        int s = g_sarr[i], e = g_earr[i];
        float v = (mb[s] != 0 && mb[e] != 0) ? g_scores[b * NSPANS + i]
                                             : __int_as_float(0xff800000);
        unsigned u = __float_as_uint(v);
        keys[i] = (u & 0x80000000u) ? ~u : (u | 0x80000000u);
    }

    unsigned prefix = 0;
    int kk = KTOP;
    for (int level = 3; level >= 0; level--) {
        hist[tid] = 0;
        __syncthreads();
        const unsigned himask = (level == 3) ? 0u : (0xFFFFFFFFu << ((level + 1) * 8));
        for (int i = tid; i < NSPANS; i += 256) {
            unsigned kv = keys[i];
            if ((kv & himask) == (prefix & himask))
                atomicAdd(&hist[(kv >> (level * 8)) & 255], 1);
        }
        __syncthreads();
        if (tid == 0) {
            int cum = 0, chosen = 0, kknew = kk;
            for (int t = 255; t >= 0; t--) {
                int c = hist[t];
                if (cum + c >= kk) { chosen = t; kknew = kk - cum; break; }
                cum += c;
            }
            sh_prefix = prefix | ((unsigned)chosen << (level * 8));
            sh_kk = kknew;
        }
        __syncthreads();
        prefix = sh_prefix;
        kk = sh_kk;
        __syncthreads();
    }

    const unsigned Kstar = prefix;
    const int CH = (NSPANS + 255) / 256;
    int lo = tid * CH; if (lo > NSPANS) lo = NSPANS;
    int hi = lo + CH;  if (hi > NSPANS) hi = NSPANS;

    int cgt = 0, ceq = 0;
    for (int i = lo; i < hi; i++) {
        unsigned kv = keys[i];
        cgt += (kv > Kstar);
        ceq += (kv == Kstar);
    }
    sgt[tid] = cgt; seqv[tid] = ceq;
    __syncthreads();
    if (tid == 0) {
        int ag = 0, ae = 0;
        for (int t = 0; t < 256; t++) {
            int g = sgt[t], e = seqv[t];
            sgt[t] = ag; seqv[t] = ae;
            ag += g; ae += e;
        }
    }
    __syncthreads();

    int gtb = sgt[tid], eqb = seqv[tid];
    for (int i = lo; i < hi; i++) {
        unsigned kv = keys[i];
        bool isgt = (kv > Kstar);
        bool iseq = (kv == Kstar);
        if (isgt || (iseq && eqb < kk)) {
            int eqt = eqb < kk ? eqb : kk;
            int pos = gtb + eqt;
            unsigned u = (kv & 0x80000000u) ? (kv & 0x7FFFFFFFu) : ~kv;
            g_topidx[b * KTOP + pos]   = i;
            g_topscore[b * KTOP + pos] = __uint_as_float(u);
        }
        gtb += isgt;
        eqb += iseq;
    }
}

// ---------------- fused head ----------------
#define HD_SMEM_FLOATS (256*XST + 256*128 + 128 + 128 + 64*16)
static const int HD_SMEM_BYTES = HD_SMEM_FLOATS * 4;

__global__ __launch_bounds__(256, 1)
void head_kernel(const float* __restrict__ Wsec, const float* __restrict__ bsec,
                 const float* __restrict__ Wpred, const float* __restrict__ bpred,
                 const int* __restrict__ mask, float* __restrict__ out) {
    extern __shared__ float sm[];
    float* xs  = sm;
    float* ws  = xs + 256 * XST;
    float* bc  = ws + 256 * 128;
    float* wpc = bc + 128;
    float* red = wpc + 128;
    __shared__ int sS[64], sE[64];
    __shared__ float sMask[64], sScore[64];

    const int b   = blockIdx.y;
    const int k0  = blockIdx.x * 64;
    const int tid = threadIdx.x;
    const int tx  = tid & 15, ty = tid >> 4;

    if (tid < 64) {
        int n = g_topidx[b * KTOP + k0 + tid];
        int s = g_sarr[n], e = g_earr[n];
        sS[tid] = s; sE[tid] = e;
        sMask[tid] = (mask[b * Tt + s] != 0 && mask[b * Tt + e] != 0) ? 1.f : 0.f;
        float sc = g_topscore[b * KTOP + k0 + tid];
        sScore[tid] = isinf(sc) ? -1.f : sc;
    }
    __syncthreads();

    const float* Ab = g_A + b * Tt * Hh;
    const float* Eb = g_E + b * Tt * Hh;
    for (int r = 0; r < 64; r++)
        xs[tid * XST + r] = Ab[sS[r] * Hh + tid] + Eb[sE[r] * Hh + tid];

    float scacc[4] = {0.f, 0.f, 0.f, 0.f};

    #pragma unroll 1
    for (int jb = 0; jb < 2; jb++) {
        const int jbase = jb * 128;
        __syncthreads();
        #pragma unroll
        for (int idx = tid; idx < 8192; idx += 256) {
            int k = idx >> 5, c4 = idx & 31;
            ((float4*)ws)[idx] = ((const float4*)(Wsec + k * Hh + jbase))[c4];
        }
        if (tid < 128) {
            bc[tid]  = bsec[jbase + tid] + g_inj[b * Hh + jbase + tid];
            wpc[tid] = Wpred[jbase + tid];
        }
        __syncthreads();

        u64 acc[4][4] = {};
        const float* xp = xs + (ty << 2);
        const float* wl = ws + (tx << 2);
        const float* wh = wl + 64;
        #pragma unroll 4
        for (int k = 0; k < Hh; k++) {
            const float4 a = *(const float4*)(xp + k * XST);
            u64 w0, w1, w2, w3;
            lds_pair(w0, w1, wl + (k << 7));
            lds_pair(w2, w3, wh + (k << 7));
            u64 d0 = dup2(a.x), d1 = dup2(a.y), d2 = dup2(a.z), d3 = dup2(a.w);
            fma2(acc[0][0], d0, w0); fma2(acc[0][1], d0, w1);
            fma2(acc[0][2], d0, w2); fma2(acc[0][3], d0, w3);
            fma2(acc[1][0], d1, w0); fma2(acc[1][1], d1, w1);
            fma2(acc[1][2], d1, w2); fma2(acc[1][3], d1, w3);
            fma2(acc[2][0], d2, w0); fma2(acc[2][1], d2, w1);
            fma2(acc[2][2], d2, w2); fma2(acc[2][3], d2, w3);
            fma2(acc[3][0], d3, w0); fma2(acc[3][1], d3, w1);
            fma2(acc[3][2], d3, w2); fma2(acc[3][3], d3, w3);
        }
        #pragma unroll
        for (int i = 0; i < 4; i++) {
            #pragma unroll
            for (int p = 0; p < 4; p++) {
                float lo, hi; unpack2(lo, hi, acc[i][p]);
                int cb = (p < 2) ? ((tx << 2) + 2 * p) : (64 + (tx << 2) + 2 * (p - 2));
                float h0 = lo + bc[cb];
                if (h0 > 0.f) scacc[i] = fmaf(h0, wpc[cb], scacc[i]);
                float h1 = hi + bc[cb + 1];
                if (h1 > 0.f) scacc[i] = fmaf(h1, wpc[cb + 1], scacc[i]);
            }
        }
    }

    __syncthreads();
    #pragma unroll
    for (int i = 0; i < 4; i++) red[((ty << 2) + i) * 16 + tx] = scacc[i];
    __syncthreads();
    if (tid < 64) {
        float ssum = bpred[0] + sScore[tid];
        #pragma unroll
        for (int t = 0; t < 16; t++) ssum += red[tid * 16 + t];
        float p = 1.f / (1.f + expf(-ssum));
        out[b * KTOP + k0 + tid] = p * sMask[tid];
    }
}

// ---------------- launch ----------------
extern "C" void kernel_launch(void* const* d_in, const int* in_sizes, int n_in,
                              void* d_out, int out_size) {
    const float* inputs   = (const float*)d_in[0];
    const int*   in_mask  = (const int*)  d_in[1];
    const float* tie      = (const float*)d_in[2];
    const float* W_start  = (const float*)d_in[3];
    const float* b_start  = (const float*)d_in[4];
    const float* W_end    = (const float*)d_in[5];
    const float* b_end    = (const float*)d_in[6];
    const float* W_s1     = (const float*)d_in[7];
    const float* b_s1     = (const float*)d_in[8];
    const float* W_s2     = (const float*)d_in[9];
    const float* b_s2     = (const float*)d_in[10];
    const float* W_inj    = (const float*)d_in[11];
    const float* b_inj    = (const float*)d_in[12];
    const float* W_sec    = (const float*)d_in[13];
    const float* b_sec    = (const float*)d_in[14];
    const float* W_pred   = (const float*)d_in[15];
    const float* b_pred   = (const float*)d_in[16];
    float* out = (float*)d_out;

    cudaFuncSetAttribute(scorer_kernel, cudaFuncAttributeMaxDynamicSharedMemorySize, SC_SMEM_BYTES);
    cudaFuncSetAttribute(head_kernel,   cudaFuncAttributeMaxDynamicSharedMemorySize, HD_SMEM_BYTES);

    build_span_idx_kernel<<<(NSPANS + 255) / 256, 256>>>();
    proj_kernel<<<dim3(Hh / 64, (Bb * Tt) / 128, 2), 256>>>(inputs, W_start, b_start, W_end, b_end);
    inj_kernel<<<Bb, 256>>>(tie, W_inj, b_inj);
    scorer_kernel<<<dim3(NSPANS / 64, Bb), 256, SC_SMEM_BYTES>>>(W_s1, b_s1, W_s2, b_s2);
    topk_kernel<<<Bb, 256>>>(in_mask);
    head_kernel<<<dim3(KTOP / 64, Bb), 256, HD_SMEM_BYTES>>>(W_sec, b_sec, W_pred, b_pred, in_mask, out);
}

// round 10
// speedup vs baseline: 1.2762x; 1.0144x over previous
#include <cuda_runtime.h>
#include <math.h>

#define Bb      64
#define Tt      128
#define Dd      768
#define Hh      256
#define NSPANS  8256
#define KTOP    256
#define XST     68          // head/proj stride
#define RST     132         // proj xs row-stride
#define SXST    68          // scorer xs row-stride (64 rows + pad, 16B-aligned)
#define SCH     16          // scorer k-chunk size (16 chunks, double-buffered)

typedef unsigned long long u64;

// ---------------- packed fp32x2 helpers (sm_103a FFMA2 path) ----------------
__device__ __forceinline__ u64 dup2(float a) {
    u64 r; asm("mov.b64 %0, {%1, %2};" : "=l"(r) : "f"(a), "f"(a)); return r;
}
__device__ __forceinline__ void fma2(u64& acc, u64 a, u64 b) {
    asm("fma.rn.f32x2 %0, %1, %2, %0;" : "+l"(acc) : "l"(a), "l"(b));
}
__device__ __forceinline__ void unpack2(float& lo, float& hi, u64 v) {
    asm("mov.b64 {%0, %1}, %2;" : "=f"(lo), "=f"(hi) : "l"(v));
}
__device__ __forceinline__ void lds_pair(u64& x, u64& y, const float* p) {
    unsigned addr = (unsigned)__cvta_generic_to_shared(p);
    asm volatile("ld.shared.v2.u64 {%0, %1}, [%2];" : "=l"(x), "=l"(y) : "r"(addr));
}

// ---------------- device scratch ----------------
__device__ float g_A[Bb*Tt*Hh];
__device__ float g_E[Bb*Tt*Hh];
__device__ float g_scores[Bb*NSPANS];
__device__ float g_inj[Bb*Hh];
__device__ int   g_topidx[Bb*KTOP];
__device__ float g_topscore[Bb*KTOP];
__device__ int   g_sarr[NSPANS];
__device__ int   g_earr[NSPANS];

// ---------------- span index decode ----------------
__global__ void build_span_idx_kernel() {
    int n = blockIdx.x * blockDim.x + threadIdx.x;
    if (n >= NSPANS) return;
    int s = 0, off = 0;
    while (n >= off + (Tt - s)) { off += (Tt - s); s++; }
    g_sarr[n] = s;
    g_earr[n] = s + (n - off);
}

// ---------------- projections: X[8192,768]@W[768,256]+b ----------------
__global__ __launch_bounds__(256)
void proj_kernel(const float* __restrict__ X,
                 const float* __restrict__ Wst, const float* __restrict__ bst,
                 const float* __restrict__ Wen, const float* __restrict__ ben) {
    const float* W    = blockIdx.z ? Wen : Wst;
    const float* bias = blockIdx.z ? ben : bst;
    float*       Out  = blockIdx.z ? g_E : g_A;

    __shared__ float xs[32 * RST];
    __shared__ float wsm[32 * XST];

    const int row0 = blockIdx.y * 128;
    const int col0 = blockIdx.x * 64;
    const int tid  = threadIdx.x;
    const int tx   = tid & 15, ty = tid >> 4;

    u64 acc[8][2] = {};
    for (int k0 = 0; k0 < Dd; k0 += 32) {
        __syncthreads();
        #pragma unroll
        for (int idx = tid; idx < 128 * 32; idx += 256) {
            int r = idx >> 5, k = idx & 31;
            xs[k * RST + r] = X[(row0 + r) * Dd + k0 + k];
        }
        #pragma unroll
        for (int idx = tid; idx < 32 * 64; idx += 256) {
            int k = idx >> 6, cc = idx & 63;
            wsm[k * XST + cc] = W[(k0 + k) * Hh + col0 + cc];
        }
        __syncthreads();
        #pragma unroll 4
        for (int k = 0; k < 32; k++) {
            const float4 a0 = *(const float4*)(xs + k * RST + (ty << 3));
            const float4 a1 = *(const float4*)(xs + k * RST + (ty << 3) + 4);
            u64 w0, w1;
            lds_pair(w0, w1, wsm + k * XST + (tx << 2));
            u64 d0 = dup2(a0.x), d1 = dup2(a0.y), d2 = dup2(a0.z), d3 = dup2(a0.w);
            u64 d4 = dup2(a1.x), d5 = dup2(a1.y), d6 = dup2(a1.z), d7 = dup2(a1.w);
            fma2(acc[0][0], d0, w0); fma2(acc[0][1], d0, w1);
            fma2(acc[1][0], d1, w0); fma2(acc[1][1], d1, w1);
            fma2(acc[2][0], d2, w0); fma2(acc[2][1], d2, w1);
            fma2(acc[3][0], d3, w0); fma2(acc[3][1], d3, w1);
            fma2(acc[4][0], d4, w0); fma2(acc[4][1], d4, w1);
            fma2(acc[5][0], d5, w0); fma2(acc[5][1], d5, w1);
            fma2(acc[6][0], d6, w0); fma2(acc[6][1], d6, w1);
            fma2(acc[7][0], d7, w0); fma2(acc[7][1], d7, w1);
        }
    }
    #pragma unroll
    for (int i = 0; i < 8; i++) {
        int row = row0 + (ty << 3) + i;
        #pragma unroll
        for (int p = 0; p < 2; p++) {
            float lo, hi; unpack2(lo, hi, acc[i][p]);
            int col = col0 + (tx << 2) + 2 * p;
            Out[row * Hh + col]     = lo + bias[col];
            Out[row * Hh + col + 1] = hi + bias[col + 1];
        }
    }
}

// ---------------- injection projection ----------------
__global__ void inj_kernel(const float* __restrict__ tie,
                           const float* __restrict__ Winj, const float* __restrict__ binj) {
    int b = blockIdx.x;
    int j = threadIdx.x;
    __shared__ float t[128];
    if (j < 128) t[j] = tie[b * 128 + j];
    __syncthreads();
    float acc = binj[j];
    #pragma unroll 8
    for (int k = 0; k < 128; k++) acc = fmaf(t[k], Winj[k * Hh + j], acc);
    g_inj[b * Hh + j] = acc;
}

// ---------------- fused span scorer: double-buffered weight staging ----------------
// smem floats: xs 256*SXST | wsL[2][SCH*128] | wsH[2][SCH*128] | bias 256 | w2 256
#define SC_XS_FLOATS   (256 * SXST)
#define SC_WSL_OFF     SC_XS_FLOATS
#define SC_WSH_OFF     (SC_WSL_OFF + 2 * SCH * 128)
#define SC_BIAS_OFF    (SC_WSH_OFF + 2 * SCH * 128)
#define SC_W2_OFF      (SC_BIAS_OFF + 256)
#define SC_SMEM_FLOATS (SC_W2_OFF + 256)
static const int SC_SMEM_BYTES = SC_SMEM_FLOATS * 4;   // 104,448 B -> 2 CTAs/SM

__global__ __launch_bounds__(256, 2)
void scorer_kernel(const float* __restrict__ Ws1, const float* __restrict__ bs1,
                   const float* __restrict__ Ws2, const float* __restrict__ bs2) {
    extern __shared__ float sm[];
    float* xs   = sm;                        // [k=256][r, stride SXST]
    float* wsL  = sm + SC_WSL_OFF;           // [buf][SCH][128] cols 8g..8g+3
    float* wsH  = sm + SC_WSH_OFF;           // [buf][SCH][128] cols 8g+4..8g+7
    float* bs1c = sm + SC_BIAS_OFF;          // 256
    float* w2c  = sm + SC_W2_OFF;            // 256
    float* red  = wsL;                       // aliased after last chunk
    __shared__ int sS[64], sE[64];

    const int b   = blockIdx.y;
    const int n0  = blockIdx.x * 64;
    const int tid = threadIdx.x;
    const int tx  = tid & 31;        // 32 col-groups of 8
    const int ty  = tid >> 5;        // 8 row-groups of 8

    if (tid < 64) {
        sS[tid] = g_sarr[n0 + tid]; sE[tid] = g_earr[n0 + tid];
    }
    bs1c[tid] = bs1[tid];
    w2c[tid]  = Ws2[tid];
    __syncthreads();

    // fill xs[k][r] = relu(A[s_r][k] + E[e_r][k]); thread owns column k = tid
    {
        const float* Ab = g_A + b * Tt * Hh + tid;
        const float* Eb = g_E + b * Tt * Hh + tid;
        float* xp = xs + tid * SXST;
        #pragma unroll 4
        for (int r = 0; r < 64; r++) {
            float v = Ab[sS[r] * Hh] + Eb[sE[r] * Hh];
            xp[r] = v > 0.f ? v : 0.f;
        }
    }

    // per-thread staging coordinates (fixed across chunks):
    // 4 float4 per thread cover SCH(16) x 64 float4 columns
    const int kkj[4] = { tid >> 6, (tid + 256) >> 6, (tid + 512) >> 6, (tid + 768) >> 6 };
    const int c4j[4] = { tid & 63, tid & 63, tid & 63, tid & 63 };

    // prefetch + stage chunk 0 into buffer 0
    float4 pf0, pf1, pf2, pf3;
    pf0 = ((const float4*)(Ws1 + kkj[0] * Hh))[c4j[0]];
    pf1 = ((const float4*)(Ws1 + kkj[1] * Hh))[c4j[1]];
    pf2 = ((const float4*)(Ws1 + kkj[2] * Hh))[c4j[2]];
    pf3 = ((const float4*)(Ws1 + kkj[3] * Hh))[c4j[3]];
    {
        float4* dL = (float4*)wsL;
        float4* dH = (float4*)wsH;
        #pragma unroll
        for (int j = 0; j < 4; j++) {
            float4 f = (j == 0) ? pf0 : (j == 1) ? pf1 : (j == 2) ? pf2 : pf3;
            float4* dst = (c4j[j] & 1) ? dH : dL;
            dst[kkj[j] * 32 + (c4j[j] >> 1)] = f;
        }
    }
    __syncthreads();   // xs + buf0 ready

    u64 acc[8][4] = {};

    #pragma unroll 1
    for (int kc = 0; kc < 16; kc++) {
        const int buf = kc & 1;
        if (kc < 15) {
            const float* Wn = Ws1 + (kc + 1) * SCH * Hh;
            pf0 = ((const float4*)(Wn + kkj[0] * Hh))[c4j[0]];
            pf1 = ((const float4*)(Wn + kkj[1] * Hh))[c4j[1]];
            pf2 = ((const float4*)(Wn + kkj[2] * Hh))[c4j[2]];
            pf3 = ((const float4*)(Wn + kkj[3] * Hh))[c4j[3]];
        }

        const float* xp = xs + (kc * SCH) * SXST + (ty << 3);
        const float* wl = wsL + buf * (SCH * 128) + (tx << 2);
        const float* wh = wsH + buf * (SCH * 128) + (tx << 2);

        #pragma unroll
        for (int k = 0; k < SCH; k++) {
            float4 a0 = *(const float4*)(xp + k * SXST);
            float4 a1 = *(const float4*)(xp + k * SXST + 4);
            ulonglong2 wA = *(const ulonglong2*)(wl + (k << 7));
            ulonglong2 wB = *(const ulonglong2*)(wh + (k << 7));
            u64 w0 = wA.x, w1 = wA.y, w2 = wB.x, w3 = wB.y;
            u64 d0 = dup2(a0.x), d1 = dup2(a0.y), d2 = dup2(a0.z), d3 = dup2(a0.w);
            u64 d4 = dup2(a1.x), d5 = dup2(a1.y), d6 = dup2(a1.z), d7 = dup2(a1.w);
            fma2(acc[0][0], d0, w0); fma2(acc[0][1], d0, w1);
            fma2(acc[0][2], d0, w2); fma2(acc[0][3], d0, w3);
            fma2(acc[1][0], d1, w0); fma2(acc[1][1], d1, w1);
            fma2(acc[1][2], d1, w2); fma2(acc[1][3], d1, w3);
            fma2(acc[2][0], d2, w0); fma2(acc[2][1], d2, w1);
            fma2(acc[2][2], d2, w2); fma2(acc[2][3], d2, w3);
            fma2(acc[3][0], d3, w0); fma2(acc[3][1], d3, w1);
            fma2(acc[3][2], d3, w2); fma2(acc[3][3], d3, w3);
            fma2(acc[4][0], d4, w0); fma2(acc[4][1], d4, w1);
            fma2(acc[4][2], d4, w2); fma2(acc[4][3], d4, w3);
            fma2(acc[5][0], d5, w0); fma2(acc[5][1], d5, w1);
            fma2(acc[5][2], d5, w2); fma2(acc[5][3], d5, w3);
            fma2(acc[6][0], d6, w0); fma2(acc[6][1], d6, w1);
            fma2(acc[6][2], d6, w2); fma2(acc[6][3], d6, w3);
            fma2(acc[7][0], d7, w0); fma2(acc[7][1], d7, w1);
            fma2(acc[7][2], d7, w2); fma2(acc[7][3], d7, w3);
        }

        if (kc < 15) {
            __syncthreads();   // all warps done reading the other buffer
            const int nb = buf ^ 1;
            float4* dL = (float4*)(wsL + nb * (SCH * 128));
            float4* dH = (float4*)(wsH + nb * (SCH * 128));
            #pragma unroll
            for (int j = 0; j < 4; j++) {
                float4 f = (j == 0) ? pf0 : (j == 1) ? pf1 : (j == 2) ? pf2 : pf3;
                float4* dst = (c4j[j] & 1) ? dH : dL;
                dst[kkj[j] * 32 + (c4j[j] >> 1)] = f;
            }
            __syncthreads();   // next buffer ready
        }
    }

    // layer-2 epilogue; acc[i][p] -> cols 8tx+2p, 8tx+2p+1
    float scacc[8] = {0.f, 0.f, 0.f, 0.f, 0.f, 0.f, 0.f, 0.f};
    #pragma unroll
    for (int i = 0; i < 8; i++) {
        #pragma unroll
        for (int p = 0; p < 4; p++) {
            float lo, hi; unpack2(lo, hi, acc[i][p]);
            int cb = (tx << 3) + 2 * p;
            float h0 = lo + bs1c[cb];
            if (h0 > 0.f) scacc[i] = fmaf(h0, w2c[cb], scacc[i]);
            float h1 = hi + bs1c[cb + 1];
            if (h1 > 0.f) scacc[i] = fmaf(h1, w2c[cb + 1], scacc[i]);
        }
    }

    __syncthreads();   // ws no longer needed; red aliases it
    #pragma unroll
    for (int i = 0; i < 8; i++) red[((ty << 3) + i) * 33 + tx] = scacc[i];
    __syncthreads();
    if (tid < 64) {
        float ssum = bs2[0];
        const float* rp = red + tid * 33;
        #pragma unroll
        for (int t = 0; t < 32; t++) ssum += rp[t];
        g_scores[b * NSPANS + n0 + tid] = ssum;
    }
}

// ---------------- per-batch radix top-k, parallel stable extraction ----------------
__global__ void topk_kernel(const int* __restrict__ mask) {
    const int b   = blockIdx.x;
    const int tid = threadIdx.x;
    __shared__ unsigned keys[NSPANS];
    __shared__ int hist[256];
    __shared__ unsigned sh_prefix;
    __shared__ int sh_kk;
    __shared__ int sgt[256], seqv[256];

    const int* mb = mask + b * Tt;
    for (int i = tid; i < NSPANS; i += 256) {
        int s = g_sarr[i], e = g_earr[i];
        float v = (mb[s] != 0 && mb[e] != 0) ? g_scores[b * NSPANS + i]
                                             : __int_as_float(0xff800000);
        unsigned u = __float_as_uint(v);
        keys[i] = (u & 0x80000000u) ? ~u : (u | 0x80000000u);
    }

    unsigned prefix = 0;
    int kk = KTOP;
    for (int level = 3; level >= 0; level--) {
        hist[tid] = 0;
        __syncthreads();
        const unsigned himask = (level == 3) ? 0u : (0xFFFFFFFFu << ((level + 1) * 8));
        for (int i = tid; i < NSPANS; i += 256) {
            unsigned kv = keys[i];
            if ((kv & himask) == (prefix & himask))
                atomicAdd(&hist[(kv >> (level * 8)) & 255], 1);
        }
        __syncthreads();
        if (tid == 0) {
            int cum = 0, chosen = 0, kknew = kk;
            for (int t = 255; t >= 0; t--) {
                int c = hist[t];
                if (cum + c >= kk) { chosen = t; kknew = kk - cum; break; }
                cum += c;
            }
            sh_prefix = prefix | ((unsigned)chosen << (level * 8));
            sh_kk = kknew;
        }
        __syncthreads();
        prefix = sh_prefix;
        kk = sh_kk;
        __syncthreads();
    }

    const unsigned Kstar = prefix;
    const int CH = (NSPANS + 255) / 256;
    int lo = tid * CH; if (lo > NSPANS) lo = NSPANS;
    int hi = lo + CH;  if (hi > NSPANS) hi = NSPANS;

    int cgt = 0, ceq = 0;
    for (int i = lo; i < hi; i++) {
        unsigned kv = keys[i];
        cgt += (kv > Kstar);
        ceq += (kv == Kstar);
    }
    sgt[tid] = cgt; seqv[tid] = ceq;
    __syncthreads();
    if (tid == 0) {
        int ag = 0, ae = 0;
        for (int t = 0; t < 256; t++) {
            int g = sgt[t], e = seqv[t];
            sgt[t] = ag; seqv[t] = ae;
            ag += g; ae += e;
        }
    }
    __syncthreads();

    int gtb = sgt[tid], eqb = seqv[tid];
    for (int i = lo; i < hi; i++) {
        unsigned kv = keys[i];
        bool isgt = (kv > Kstar);
        bool iseq = (kv == Kstar);
        if (isgt || (iseq && eqb < kk)) {
            int eqt = eqb < kk ? eqb : kk;
            int pos = gtb + eqt;
            unsigned u = (kv & 0x80000000u) ? (kv & 0x7FFFFFFFu) : ~kv;
            g_topidx[b * KTOP + pos]   = i;
            g_topscore[b * KTOP + pos] = __uint_as_float(u);
        }
        gtb += isgt;
        eqb += iseq;
    }
}

// ---------------- fused head ----------------
#define HD_SMEM_FLOATS (256*XST + 256*128 + 128 + 128 + 64*16)
static const int HD_SMEM_BYTES = HD_SMEM_FLOATS * 4;

__global__ __launch_bounds__(256, 1)
void head_kernel(const float* __restrict__ Wsec, const float* __restrict__ bsec,
                 const float* __restrict__ Wpred, const float* __restrict__ bpred,
                 const int* __restrict__ mask, float* __restrict__ out) {
    extern __shared__ float sm[];
    float* xs  = sm;
    float* ws  = xs + 256 * XST;
    float* bc  = ws + 256 * 128;
    float* wpc = bc + 128;
    float* red = wpc + 128;
    __shared__ int sS[64], sE[64];
    __shared__ float sMask[64], sScore[64];

    const int b   = blockIdx.y;
    const int k0  = blockIdx.x * 64;
    const int tid = threadIdx.x;
    const int tx  = tid & 15, ty = tid >> 4;

    if (tid < 64) {
        int n = g_topidx[b * KTOP + k0 + tid];
        int s = g_sarr[n], e = g_earr[n];
        sS[tid] = s; sE[tid] = e;
        sMask[tid] = (mask[b * Tt + s] != 0 && mask[b * Tt + e] != 0) ? 1.f : 0.f;
        float sc = g_topscore[b * KTOP + k0 + tid];
        sScore[tid] = isinf(sc) ? -1.f : sc;
    }
    __syncthreads();

    const float* Ab = g_A + b * Tt * Hh;
    const float* Eb = g_E + b * Tt * Hh;
    for (int r = 0; r < 64; r++)
        xs[tid * XST + r] = Ab[sS[r] * Hh + tid] + Eb[sE[r] * Hh + tid];

    float scacc[4] = {0.f, 0.f, 0.f, 0.f};

    #pragma unroll 1
    for (int jb = 0; jb < 2; jb++) {
        const int jbase = jb * 128;
        __syncthreads();
        #pragma unroll
        for (int idx = tid; idx < 8192; idx += 256) {
            int k = idx >> 5, c4 = idx & 31;
            ((float4*)ws)[idx] = ((const float4*)(Wsec + k * Hh + jbase))[c4];
        }
        if (tid < 128) {
            bc[tid]  = bsec[jbase + tid] + g_inj[b * Hh + jbase + tid];
            wpc[tid] = Wpred[jbase + tid];
        }
        __syncthreads();

        u64 acc[4][4] = {};
        const float* xp = xs + (ty << 2);
        const float* wl = ws + (tx << 2);
        const float* wh = wl + 64;
        #pragma unroll 4
        for (int k = 0; k < Hh; k++) {
            const float4 a = *(const float4*)(xp + k * XST);
            u64 w0, w1, w2, w3;
            lds_pair(w0, w1, wl + (k << 7));
            lds_pair(w2, w3, wh + (k << 7));
            u64 d0 = dup2(a.x), d1 = dup2(a.y), d2 = dup2(a.z), d3 = dup2(a.w);
            fma2(acc[0][0], d0, w0); fma2(acc[0][1], d0, w1);
            fma2(acc[0][2], d0, w2); fma2(acc[0][3], d0, w3);
            fma2(acc[1][0], d1, w0); fma2(acc[1][1], d1, w1);
            fma2(acc[1][2], d1, w2); fma2(acc[1][3], d1, w3);
            fma2(acc[2][0], d2, w0); fma2(acc[2][1], d2, w1);
            fma2(acc[2][2], d2, w2); fma2(acc[2][3], d2, w3);
            fma2(acc[3][0], d3, w0); fma2(acc[3][1], d3, w1);
            fma2(acc[3][2], d3, w2); fma2(acc[3][3], d3, w3);
        }
        #pragma unroll
        for (int i = 0; i < 4; i++) {
            #pragma unroll
            for (int p = 0; p < 4; p++) {
                float lo, hi; unpack2(lo, hi, acc[i][p]);
                int cb = (p < 2) ? ((tx << 2) + 2 * p) : (64 + (tx << 2) + 2 * (p - 2));
                float h0 = lo + bc[cb];
                if (h0 > 0.f) scacc[i] = fmaf(h0, wpc[cb], scacc[i]);
                float h1 = hi + bc[cb + 1];
                if (h1 > 0.f) scacc[i] = fmaf(h1, wpc[cb + 1], scacc[i]);
            }
        }
    }

    __syncthreads();
    #pragma unroll
    for (int i = 0; i < 4; i++) red[((ty << 2) + i) * 16 + tx] = scacc[i];
    __syncthreads();
    if (tid < 64) {
        float ssum = bpred[0] + sScore[tid];
        #pragma unroll
        for (int t = 0; t < 16; t++) ssum += red[tid * 16 + t];
        float p = 1.f / (1.f + expf(-ssum));
        out[b * KTOP + k0 + tid] = p * sMask[tid];
    }
}

// ---------------- launch ----------------
extern "C" void kernel_launch(void* const* d_in, const int* in_sizes, int n_in,
                              void* d_out, int out_size) {
    const float* inputs   = (const float*)d_in[0];
    const int*   in_mask  = (const int*)  d_in[1];
    const float* tie      = (const float*)d_in[2];
    const float* W_start  = (const float*)d_in[3];
    const float* b_start  = (const float*)d_in[4];
    const float* W_end    = (const float*)d_in[5];
    const float* b_end    = (const float*)d_in[6];
    const float* W_s1     = (const float*)d_in[7];
    const float* b_s1     = (const float*)d_in[8];
    const float* W_s2     = (const float*)d_in[9];
    const float* b_s2     = (const float*)d_in[10];
    const float* W_inj    = (const float*)d_in[11];
    const float* b_inj    = (const float*)d_in[12];
    const float* W_sec    = (const float*)d_in[13];
    const float* b_sec    = (const float*)d_in[14];
    const float* W_pred   = (const float*)d_in[15];
    const float* b_pred   = (const float*)d_in[16];
    float* out = (float*)d_out;

    cudaFuncSetAttribute(scorer_kernel, cudaFuncAttributeMaxDynamicSharedMemorySize, SC_SMEM_BYTES);
    cudaFuncSetAttribute(head_kernel,   cudaFuncAttributeMaxDynamicSharedMemorySize, HD_SMEM_BYTES);

    build_span_idx_kernel<<<(NSPANS + 255) / 256, 256>>>();
    proj_kernel<<<dim3(Hh / 64, (Bb * Tt) / 128, 2), 256>>>(inputs, W_start, b_start, W_end, b_end);
    inj_kernel<<<Bb, 256>>>(tie, W_inj, b_inj);
    scorer_kernel<<<dim3(NSPANS / 64, Bb), 256, SC_SMEM_BYTES>>>(W_s1, b_s1, W_s2, b_s2);
    topk_kernel<<<Bb, 256>>>(in_mask);
    head_kernel<<<dim3(KTOP / 64, Bb), 256, HD_SMEM_BYTES>>>(W_sec, b_sec, W_pred, b_pred, in_mask, out);
}

// round 11
// speedup vs baseline: 1.3032x; 1.0211x over previous
#include <cuda_runtime.h>
#include <math.h>

#define Bb      64
#define Tt      128
#define Dd      768
#define Hh      256
#define NSPANS  8256
#define KTOP    256
#define XST     68          // head/proj stride
#define RST     132         // proj xs row-stride
#define SXST    68          // scorer xs row-stride (64 rows + pad, 16B-aligned)
#define SCH     16          // scorer k-chunk size (16 chunks, double-buffered)

typedef unsigned long long u64;

// ---------------- packed fp32x2 helpers (sm_103a FFMA2 path) ----------------
__device__ __forceinline__ u64 dup2(float a) {
    u64 r; asm("mov.b64 %0, {%1, %2};" : "=l"(r) : "f"(a), "f"(a)); return r;
}
__device__ __forceinline__ void fma2(u64& acc, u64 a, u64 b) {
    asm("fma.rn.f32x2 %0, %1, %2, %0;" : "+l"(acc) : "l"(a), "l"(b));
}
__device__ __forceinline__ void unpack2(float& lo, float& hi, u64 v) {
    asm("mov.b64 {%0, %1}, %2;" : "=f"(lo), "=f"(hi) : "l"(v));
}
__device__ __forceinline__ void lds_pair(u64& x, u64& y, const float* p) {
    unsigned addr = (unsigned)__cvta_generic_to_shared(p);
    asm volatile("ld.shared.v2.u64 {%0, %1}, [%2];" : "=l"(x), "=l"(y) : "r"(addr));
}

// ---------------- device scratch ----------------
__device__ float g_A[Bb*Tt*Hh];
__device__ float g_E[Bb*Tt*Hh];
__device__ float g_scores[Bb*NSPANS];
__device__ float g_inj[Bb*Hh];
__device__ int   g_topidx[Bb*KTOP];
__device__ float g_topscore[Bb*KTOP];
__device__ int   g_sarr[NSPANS];
__device__ int   g_earr[NSPANS];

// ---------------- span index decode ----------------
__global__ void build_span_idx_kernel() {
    int n = blockIdx.x * blockDim.x + threadIdx.x;
    if (n >= NSPANS) return;
    int s = 0, off = 0;
    while (n >= off + (Tt - s)) { off += (Tt - s); s++; }
    g_sarr[n] = s;
    g_earr[n] = s + (n - off);
}

// ---------------- projections: X[8192,768]@W[768,256]+b ----------------
__global__ __launch_bounds__(256)
void proj_kernel(const float* __restrict__ X,
                 const float* __restrict__ Wst, const float* __restrict__ bst,
                 const float* __restrict__ Wen, const float* __restrict__ ben) {
    const float* W    = blockIdx.z ? Wen : Wst;
    const float* bias = blockIdx.z ? ben : bst;
    float*       Out  = blockIdx.z ? g_E : g_A;

    __shared__ float xs[32 * RST];
    __shared__ float wsm[32 * XST];

    const int row0 = blockIdx.y * 128;
    const int col0 = blockIdx.x * 64;
    const int tid  = threadIdx.x;
    const int tx   = tid & 15, ty = tid >> 4;

    u64 acc[8][2] = {};
    for (int k0 = 0; k0 < Dd; k0 += 32) {
        __syncthreads();
        #pragma unroll
        for (int idx = tid; idx < 128 * 32; idx += 256) {
            int r = idx >> 5, k = idx & 31;
            xs[k * RST + r] = X[(row0 + r) * Dd + k0 + k];
        }
        #pragma unroll
        for (int idx = tid; idx < 32 * 64; idx += 256) {
            int k = idx >> 6, cc = idx & 63;
            wsm[k * XST + cc] = W[(k0 + k) * Hh + col0 + cc];
        }
        __syncthreads();
        #pragma unroll 4
        for (int k = 0; k < 32; k++) {
            const float4 a0 = *(const float4*)(xs + k * RST + (ty << 3));
            const float4 a1 = *(const float4*)(xs + k * RST + (ty << 3) + 4);
            u64 w0, w1;
            lds_pair(w0, w1, wsm + k * XST + (tx << 2));
            u64 d0 = dup2(a0.x), d1 = dup2(a0.y), d2 = dup2(a0.z), d3 = dup2(a0.w);
            u64 d4 = dup2(a1.x), d5 = dup2(a1.y), d6 = dup2(a1.z), d7 = dup2(a1.w);
            fma2(acc[0][0], d0, w0); fma2(acc[0][1], d0, w1);
            fma2(acc[1][0], d1, w0); fma2(acc[1][1], d1, w1);
            fma2(acc[2][0], d2, w0); fma2(acc[2][1], d2, w1);
            fma2(acc[3][0], d3, w0); fma2(acc[3][1], d3, w1);
            fma2(acc[4][0], d4, w0); fma2(acc[4][1], d4, w1);
            fma2(acc[5][0], d5, w0); fma2(acc[5][1], d5, w1);
            fma2(acc[6][0], d6, w0); fma2(acc[6][1], d6, w1);
            fma2(acc[7][0], d7, w0); fma2(acc[7][1], d7, w1);
        }
    }
    #pragma unroll
    for (int i = 0; i < 8; i++) {
        int row = row0 + (ty << 3) + i;
        #pragma unroll
        for (int p = 0; p < 2; p++) {
            float lo, hi; unpack2(lo, hi, acc[i][p]);
            int col = col0 + (tx << 2) + 2 * p;
            Out[row * Hh + col]     = lo + bias[col];
            Out[row * Hh + col + 1] = hi + bias[col + 1];
        }
    }
}

// ---------------- injection projection ----------------
__global__ void inj_kernel(const float* __restrict__ tie,
                           const float* __restrict__ Winj, const float* __restrict__ binj) {
    int b = blockIdx.x;
    int j = threadIdx.x;
    __shared__ float t[128];
    if (j < 128) t[j] = tie[b * 128 + j];
    __syncthreads();
    float acc = binj[j];
    #pragma unroll 8
    for (int k = 0; k < 128; k++) acc = fmaf(t[k], Winj[k * Hh + j], acc);
    g_inj[b * Hh + j] = acc;
}

// ---------------- fused span scorer: 16x4 tile, single-sync double buffer ----------------
// smem floats: xs 256*SXST | wbuf[2][SCH*256] | bias 256 | w2 256
// red (64 x 65) aliases wbuf after last chunk.
#define SC_XS_FLOATS   (256 * SXST)
#define SC_WB_OFF      SC_XS_FLOATS
#define SC_BIAS_OFF    (SC_WB_OFF + 2 * SCH * 256)
#define SC_W2_OFF      (SC_BIAS_OFF + 256)
#define SC_SMEM_FLOATS (SC_W2_OFF + 256)
static const int SC_SMEM_BYTES = SC_SMEM_FLOATS * 4;   // 104,448 B -> 2 CTAs/SM

__global__ __launch_bounds__(256, 2)
void scorer_kernel(const float* __restrict__ Ws1, const float* __restrict__ bs1,
                   const float* __restrict__ Ws2, const float* __restrict__ bs2) {
    extern __shared__ float sm[];
    float* xs   = sm;                        // [k=256][r, stride SXST]
    float* wbuf = sm + SC_WB_OFF;            // [2][SCH][256] row-major
    float* bs1c = sm + SC_BIAS_OFF;          // 256
    float* w2c  = sm + SC_W2_OFF;            // 256
    float* red  = wbuf;                      // aliased after last chunk: [64][65]
    __shared__ int sS[64], sE[64];

    const int b   = blockIdx.y;
    const int n0  = blockIdx.x * 64;
    const int tid = threadIdx.x;
    const int tx  = tid & 63;        // 64 col-groups of 4
    const int ty  = tid >> 6;        // 4 row-groups of 16

    if (tid < 64) {
        sS[tid] = g_sarr[n0 + tid]; sE[tid] = g_earr[n0 + tid];
    }
    bs1c[tid] = bs1[tid];
    w2c[tid]  = Ws2[tid];
    __syncthreads();

    // fill xs[k][r] = relu(A[s_r][k] + E[e_r][k]); thread owns column k = tid
    {
        const float* Ab = g_A + b * Tt * Hh + tid;
        const float* Eb = g_E + b * Tt * Hh + tid;
        float* xp = xs + tid * SXST;
        #pragma unroll 4
        for (int r = 0; r < 64; r++) {
            float v = Ab[sS[r] * Hh] + Eb[sE[r] * Hh];
            xp[r] = v > 0.f ? v : 0.f;
        }
    }

    // staging coords: chunk = SCH*256 floats = 1024 float4; 4 float4 per thread
    const int kk0 = tid >> 6,          c40 = tid & 63;
    const int kk1 = (tid + 256) >> 6,  c41 = tid & 63;
    const int kk2 = (tid + 512) >> 6,  c42 = tid & 63;
    const int kk3 = (tid + 768) >> 6,  c43 = tid & 63;

    float4 pf0 = ((const float4*)(Ws1 + kk0 * Hh))[c40];
    float4 pf1 = ((const float4*)(Ws1 + kk1 * Hh))[c41];
    float4 pf2 = ((const float4*)(Ws1 + kk2 * Hh))[c42];
    float4 pf3 = ((const float4*)(Ws1 + kk3 * Hh))[c43];
    {
        float4* dst = (float4*)wbuf;
        dst[kk0 * 64 + c40] = pf0;
        dst[kk1 * 64 + c41] = pf1;
        dst[kk2 * 64 + c42] = pf2;
        dst[kk3 * 64 + c43] = pf3;
    }
    __syncthreads();   // xs + buf0 ready

    u64 acc[16][2] = {};

    #pragma unroll 1
    for (int kc = 0; kc < 16; kc++) {
        const int buf = kc & 1;
        if (kc < 15) {
            const float* Wn = Ws1 + (kc + 1) * SCH * Hh;
            pf0 = ((const float4*)(Wn + kk0 * Hh))[c40];
            pf1 = ((const float4*)(Wn + kk1 * Hh))[c41];
            pf2 = ((const float4*)(Wn + kk2 * Hh))[c42];
            pf3 = ((const float4*)(Wn + kk3 * Hh))[c43];
        }

        const float* xp = xs + (kc * SCH) * SXST + (ty << 4);
        const float* wp = wbuf + buf * (SCH * 256) + (tx << 2);

        #pragma unroll
        for (int k = 0; k < SCH; k++) {
            float4 a0 = *(const float4*)(xp + k * SXST);       // broadcast
            float4 a1 = *(const float4*)(xp + k * SXST + 4);
            float4 a2 = *(const float4*)(xp + k * SXST + 8);
            float4 a3 = *(const float4*)(xp + k * SXST + 12);
            ulonglong2 wv = *(const ulonglong2*)(wp + (k << 8)); // 16B/lane, conflict-free
            u64 w0 = wv.x, w1 = wv.y;
            u64 d0 = dup2(a0.x), d1 = dup2(a0.y), d2 = dup2(a0.z), d3 = dup2(a0.w);
            u64 d4 = dup2(a1.x), d5 = dup2(a1.y), d6 = dup2(a1.z), d7 = dup2(a1.w);
            u64 d8 = dup2(a2.x), d9 = dup2(a2.y), dA = dup2(a2.z), dB = dup2(a2.w);
            u64 dC = dup2(a3.x), dD = dup2(a3.y), dE = dup2(a3.z), dF = dup2(a3.w);
            fma2(acc[0][0],  d0, w0); fma2(acc[0][1],  d0, w1);
            fma2(acc[1][0],  d1, w0); fma2(acc[1][1],  d1, w1);
            fma2(acc[2][0],  d2, w0); fma2(acc[2][1],  d2, w1);
            fma2(acc[3][0],  d3, w0); fma2(acc[3][1],  d3, w1);
            fma2(acc[4][0],  d4, w0); fma2(acc[4][1],  d4, w1);
            fma2(acc[5][0],  d5, w0); fma2(acc[5][1],  d5, w1);
            fma2(acc[6][0],  d6, w0); fma2(acc[6][1],  d6, w1);
            fma2(acc[7][0],  d7, w0); fma2(acc[7][1],  d7, w1);
            fma2(acc[8][0],  d8, w0); fma2(acc[8][1],  d8, w1);
            fma2(acc[9][0],  d9, w0); fma2(acc[9][1],  d9, w1);
            fma2(acc[10][0], dA, w0); fma2(acc[10][1], dA, w1);
            fma2(acc[11][0], dB, w0); fma2(acc[11][1], dB, w1);
            fma2(acc[12][0], dC, w0); fma2(acc[12][1], dC, w1);
            fma2(acc[13][0], dD, w0); fma2(acc[13][1], dD, w1);
            fma2(acc[14][0], dE, w0); fma2(acc[14][1], dE, w1);
            fma2(acc[15][0], dF, w0); fma2(acc[15][1], dF, w1);
        }

        if (kc < 15) {
            // store prefetched chunk into the other buffer; WAR-safe: its readers
            // (chunk kc-1) finished before the sync at the end of iteration kc-1.
            float4* dst = (float4*)(wbuf + (buf ^ 1) * (SCH * 256));
            dst[kk0 * 64 + c40] = pf0;
            dst[kk1 * 64 + c41] = pf1;
            dst[kk2 * 64 + c42] = pf2;
            dst[kk3 * 64 + c43] = pf3;
        }
        __syncthreads();   // single barrier per chunk
    }

    // layer-2 epilogue; acc[i][p] -> cols 4tx+2p, 4tx+2p+1
    float scacc[16];
    #pragma unroll
    for (int i = 0; i < 16; i++) {
        float s = 0.f;
        #pragma unroll
        for (int p = 0; p < 2; p++) {
            float lo, hi; unpack2(lo, hi, acc[i][p]);
            int cb = (tx << 2) + 2 * p;
            float h0 = lo + bs1c[cb];
            if (h0 > 0.f) s = fmaf(h0, w2c[cb], s);
            float h1 = hi + bs1c[cb + 1];
            if (h1 > 0.f) s = fmaf(h1, w2c[cb + 1], s);
        }
        scacc[i] = s;
    }

    // reduction: red[row][65] over 64 col-groups (wbuf no longer needed)
    #pragma unroll
    for (int i = 0; i < 16; i++) red[((ty << 4) + i) * 65 + tx] = scacc[i];
    __syncthreads();
    if (tid < 64) {
        float ssum = bs2[0];
        const float* rp = red + tid * 65;
        #pragma unroll
        for (int t = 0; t < 64; t++) ssum += rp[t];
        g_scores[b * NSPANS + n0 + tid] = ssum;
    }
}

// ---------------- per-batch radix top-k, parallel stable extraction ----------------
__global__ void topk_kernel(const int* __restrict__ mask) {
    const int b   = blockIdx.x;
    const int tid = threadIdx.x;
    __shared__ unsigned keys[NSPANS];
    __shared__ int hist[256];
    __shared__ unsigned sh_prefix;
    __shared__ int sh_kk;
    __shared__ int sgt[256], seqv[256];

    const int* mb = mask + b * Tt;
    for (int i = tid; i < NSPANS; i += 256) {
        int s = g_sarr[i], e = g_earr[i];
        float v = (mb[s] != 0 && mb[e] != 0) ? g_scores[b * NSPANS + i]
                                             : __int_as_float(0xff800000);
        unsigned u = __float_as_uint(v);
        keys[i] = (u & 0x80000000u) ? ~u : (u | 0x80000000u);
    }

    unsigned prefix = 0;
    int kk = KTOP;
    for (int level = 3; level >= 0; level--) {
        hist[tid] = 0;
        __syncthreads();
        const unsigned himask = (level == 3) ? 0u : (0xFFFFFFFFu << ((level + 1) * 8));
        for (int i = tid; i < NSPANS; i += 256) {
            unsigned kv = keys[i];
            if ((kv & himask) == (prefix & himask))
                atomicAdd(&hist[(kv >> (level * 8)) & 255], 1);
        }
        __syncthreads();
        if (tid == 0) {
            int cum = 0, chosen = 0, kknew = kk;
            for (int t = 255; t >= 0; t--) {
                int c = hist[t];
                if (cum + c >= kk) { chosen = t; kknew = kk - cum; break; }
                cum += c;
            }
            sh_prefix = prefix | ((unsigned)chosen << (level * 8));
            sh_kk = kknew;
        }
        __syncthreads();
        prefix = sh_prefix;
        kk = sh_kk;
        __syncthreads();
    }

    const unsigned Kstar = prefix;
    const int CH = (NSPANS + 255) / 256;
    int lo = tid * CH; if (lo > NSPANS) lo = NSPANS;
    int hi = lo + CH;  if (hi > NSPANS) hi = NSPANS;

    int cgt = 0, ceq = 0;
    for (int i = lo; i < hi; i++) {
        unsigned kv = keys[i];
        cgt += (kv > Kstar);
        ceq += (kv == Kstar);
    }
    sgt[tid] = cgt; seqv[tid] = ceq;
    __syncthreads();
    if (tid == 0) {
        int ag = 0, ae = 0;
        for (int t = 0; t < 256; t++) {
            int g = sgt[t], e = seqv[t];
            sgt[t] = ag; seqv[t] = ae;
            ag += g; ae += e;
        }
    }
    __syncthreads();

    int gtb = sgt[tid], eqb = seqv[tid];
    for (int i = lo; i < hi; i++) {
        unsigned kv = keys[i];
        bool isgt = (kv > Kstar);
        bool iseq = (kv == Kstar);
        if (isgt || (iseq && eqb < kk)) {
            int eqt = eqb < kk ? eqb : kk;
            int pos = gtb + eqt;
            unsigned u = (kv & 0x80000000u) ? (kv & 0x7FFFFFFFu) : ~kv;
            g_topidx[b * KTOP + pos]   = i;
            g_topscore[b * KTOP + pos] = __uint_as_float(u);
        }
        gtb += isgt;
        eqb += iseq;
    }
}

// ---------------- fused head ----------------
#define HD_SMEM_FLOATS (256*XST + 256*128 + 128 + 128 + 64*16)
static const int HD_SMEM_BYTES = HD_SMEM_FLOATS * 4;

__global__ __launch_bounds__(256, 1)
void head_kernel(const float* __restrict__ Wsec, const float* __restrict__ bsec,
                 const float* __restrict__ Wpred, const float* __restrict__ bpred,
                 const int* __restrict__ mask, float* __restrict__ out) {
    extern __shared__ float sm[];
    float* xs  = sm;
    float* ws  = xs + 256 * XST;
    float* bc  = ws + 256 * 128;
    float* wpc = bc + 128;
    float* red = wpc + 128;
    __shared__ int sS[64], sE[64];
    __shared__ float sMask[64], sScore[64];

    const int b   = blockIdx.y;
    const int k0  = blockIdx.x * 64;
    const int tid = threadIdx.x;
    const int tx  = tid & 15, ty = tid >> 4;

    if (tid < 64) {
        int n = g_topidx[b * KTOP + k0 + tid];
        int s = g_sarr[n], e = g_earr[n];
        sS[tid] = s; sE[tid] = e;
        sMask[tid] = (mask[b * Tt + s] != 0 && mask[b * Tt + e] != 0) ? 1.f : 0.f;
        float sc = g_topscore[b * KTOP + k0 + tid];
        sScore[tid] = isinf(sc) ? -1.f : sc;
    }
    __syncthreads();

    const float* Ab = g_A + b * Tt * Hh;
    const float* Eb = g_E + b * Tt * Hh;
    for (int r = 0; r < 64; r++)
        xs[tid * XST + r] = Ab[sS[r] * Hh + tid] + Eb[sE[r] * Hh + tid];

    float scacc[4] = {0.f, 0.f, 0.f, 0.f};

    #pragma unroll 1
    for (int jb = 0; jb < 2; jb++) {
        const int jbase = jb * 128;
        __syncthreads();
        #pragma unroll
        for (int idx = tid; idx < 8192; idx += 256) {
            int k = idx >> 5, c4 = idx & 31;
            ((float4*)ws)[idx] = ((const float4*)(Wsec + k * Hh + jbase))[c4];
        }
        if (tid < 128) {
            bc[tid]  = bsec[jbase + tid] + g_inj[b * Hh + jbase + tid];
            wpc[tid] = Wpred[jbase + tid];
        }
        __syncthreads();

        u64 acc[4][4] = {};
        const float* xp = xs + (ty << 2);
        const float* wl = ws + (tx << 2);
        const float* wh = wl + 64;
        #pragma unroll 4
        for (int k = 0; k < Hh; k++) {
            const float4 a = *(const float4*)(xp + k * XST);
            u64 w0, w1, w2, w3;
            lds_pair(w0, w1, wl + (k << 7));
            lds_pair(w2, w3, wh + (k << 7));
            u64 d0 = dup2(a.x), d1 = dup2(a.y), d2 = dup2(a.z), d3 = dup2(a.w);
            fma2(acc[0][0], d0, w0); fma2(acc[0][1], d0, w1);
            fma2(acc[0][2], d0, w2); fma2(acc[0][3], d0, w3);
            fma2(acc[1][0], d1, w0); fma2(acc[1][1], d1, w1);
            fma2(acc[1][2], d1, w2); fma2(acc[1][3], d1, w3);
            fma2(acc[2][0], d2, w0); fma2(acc[2][1], d2, w1);
            fma2(acc[2][2], d2, w2); fma2(acc[2][3], d2, w3);
            fma2(acc[3][0], d3, w0); fma2(acc[3][1], d3, w1);
            fma2(acc[3][2], d3, w2); fma2(acc[3][3], d3, w3);
        }
        #pragma unroll
        for (int i = 0; i < 4; i++) {
            #pragma unroll
            for (int p = 0; p < 4; p++) {
                float lo, hi; unpack2(lo, hi, acc[i][p]);
                int cb = (p < 2) ? ((tx << 2) + 2 * p) : (64 + (tx << 2) + 2 * (p - 2));
                float h0 = lo + bc[cb];
                if (h0 > 0.f) scacc[i] = fmaf(h0, wpc[cb], scacc[i]);
                float h1 = hi + bc[cb + 1];
                if (h1 > 0.f) scacc[i] = fmaf(h1, wpc[cb + 1], scacc[i]);
            }
        }
    }

    __syncthreads();
    #pragma unroll
    for (int i = 0; i < 4; i++) red[((ty << 2) + i) * 16 + tx] = scacc[i];
    __syncthreads();
    if (tid < 64) {
        float ssum = bpred[0] + sScore[tid];
        #pragma unroll
        for (int t = 0; t < 16; t++) ssum += red[tid * 16 + t];
        float p = 1.f / (1.f + expf(-ssum));
        out[b * KTOP + k0 + tid] = p * sMask[tid];
    }
}

// ---------------- launch ----------------
extern "C" void kernel_launch(void* const* d_in, const int* in_sizes, int n_in,
                              void* d_out, int out_size) {
    const float* inputs   = (const float*)d_in[0];
    const int*   in_mask  = (const int*)  d_in[1];
    const float* tie      = (const float*)d_in[2];
    const float* W_start  = (const float*)d_in[3];
    const float* b_start  = (const float*)d_in[4];
    const float* W_end    = (const float*)d_in[5];
    const float* b_end    = (const float*)d_in[6];
    const float* W_s1     = (const float*)d_in[7];
    const float* b_s1     = (const float*)d_in[8];
    const float* W_s2     = (const float*)d_in[9];
    const float* b_s2     = (const float*)d_in[10];
    const float* W_inj    = (const float*)d_in[11];
    const float* b_inj    = (const float*)d_in[12];
    const float* W_sec    = (const float*)d_in[13];
    const float* b_sec    = (const float*)d_in[14];
    const float* W_pred   = (const float*)d_in[15];
    const float* b_pred   = (const float*)d_in[16];
    float* out = (float*)d_out;

    cudaFuncSetAttribute(scorer_kernel, cudaFuncAttributeMaxDynamicSharedMemorySize, SC_SMEM_BYTES);
    cudaFuncSetAttribute(head_kernel,   cudaFuncAttributeMaxDynamicSharedMemorySize, HD_SMEM_BYTES);

    build_span_idx_kernel<<<(NSPANS + 255) / 256, 256>>>();
    proj_kernel<<<dim3(Hh / 64, (Bb * Tt) / 128, 2), 256>>>(inputs, W_start, b_start, W_end, b_end);
    inj_kernel<<<Bb, 256>>>(tie, W_inj, b_inj);
    scorer_kernel<<<dim3(NSPANS / 64, Bb), 256, SC_SMEM_BYTES>>>(W_s1, b_s1, W_s2, b_s2);
    topk_kernel<<<Bb, 256>>>(in_mask);
    head_kernel<<<dim3(KTOP / 64, Bb), 256, HD_SMEM_BYTES>>>(W_sec, b_sec, W_pred, b_pred, in_mask, out);
}

// round 12
// speedup vs baseline: 1.3590x; 1.0428x over previous
#include <cuda_runtime.h>
#include <math.h>

#define Bb      64
#define Tt      128
#define Dd      768
#define Hh      256
#define NSPANS  8256
#define KTOP    256
#define XST     68          // head/proj stride
#define RST     132         // proj xs row-stride
#define SXST    68          // scorer xs row-stride (64 rows + pad, 16B-aligned)
#define SCH     16          // scorer k-chunk size (16 chunks, double-buffered)

typedef unsigned long long u64;

// ---------------- packed fp32x2 helpers (sm_103a FFMA2 path) ----------------
__device__ __forceinline__ u64 dup2(float a) {
    u64 r; asm("mov.b64 %0, {%1, %2};" : "=l"(r) : "f"(a), "f"(a)); return r;
}
__device__ __forceinline__ void fma2(u64& acc, u64 a, u64 b) {
    asm("fma.rn.f32x2 %0, %1, %2, %0;" : "+l"(acc) : "l"(a), "l"(b));
}
__device__ __forceinline__ void unpack2(float& lo, float& hi, u64 v) {
    asm("mov.b64 {%0, %1}, %2;" : "=f"(lo), "=f"(hi) : "l"(v));
}
__device__ __forceinline__ void lds_pair(u64& x, u64& y, const float* p) {
    unsigned addr = (unsigned)__cvta_generic_to_shared(p);
    asm volatile("ld.shared.v2.u64 {%0, %1}, [%2];" : "=l"(x), "=l"(y) : "r"(addr));
}

// ---------------- device scratch ----------------
__device__ float g_A[Bb*Tt*Hh];
__device__ float g_E[Bb*Tt*Hh];
__device__ float g_scores[Bb*NSPANS];
__device__ float g_inj[Bb*Hh];
__device__ int   g_topidx[Bb*KTOP];
__device__ float g_topscore[Bb*KTOP];
__device__ int   g_sarr[NSPANS];
__device__ int   g_earr[NSPANS];

// ---------------- span index decode ----------------
__global__ void build_span_idx_kernel() {
    int n = blockIdx.x * blockDim.x + threadIdx.x;
    if (n >= NSPANS) return;
    int s = 0, off = 0;
    while (n >= off + (Tt - s)) { off += (Tt - s); s++; }
    g_sarr[n] = s;
    g_earr[n] = s + (n - off);
}

// ---------------- projections: X[8192,768]@W[768,256]+b ----------------
__global__ __launch_bounds__(256)
void proj_kernel(const float* __restrict__ X,
                 const float* __restrict__ Wst, const float* __restrict__ bst,
                 const float* __restrict__ Wen, const float* __restrict__ ben) {
    const float* W    = blockIdx.z ? Wen : Wst;
    const float* bias = blockIdx.z ? ben : bst;
    float*       Out  = blockIdx.z ? g_E : g_A;

    __shared__ float xs[32 * RST];
    __shared__ float wsm[32 * XST];

    const int row0 = blockIdx.y * 128;
    const int col0 = blockIdx.x * 64;
    const int tid  = threadIdx.x;
    const int tx   = tid & 15, ty = tid >> 4;

    u64 acc[8][2] = {};
    for (int k0 = 0; k0 < Dd; k0 += 32) {
        __syncthreads();
        #pragma unroll
        for (int idx = tid; idx < 128 * 32; idx += 256) {
            int r = idx >> 5, k = idx & 31;
            xs[k * RST + r] = X[(row0 + r) * Dd + k0 + k];
        }
        #pragma unroll
        for (int idx = tid; idx < 32 * 64; idx += 256) {
            int k = idx >> 6, cc = idx & 63;
            wsm[k * XST + cc] = W[(k0 + k) * Hh + col0 + cc];
        }
        __syncthreads();
        #pragma unroll 4
        for (int k = 0; k < 32; k++) {
            const float4 a0 = *(const float4*)(xs + k * RST + (ty << 3));
            const float4 a1 = *(const float4*)(xs + k * RST + (ty << 3) + 4);
            u64 w0, w1;
            lds_pair(w0, w1, wsm + k * XST + (tx << 2));
            u64 d0 = dup2(a0.x), d1 = dup2(a0.y), d2 = dup2(a0.z), d3 = dup2(a0.w);
            u64 d4 = dup2(a1.x), d5 = dup2(a1.y), d6 = dup2(a1.z), d7 = dup2(a1.w);
            fma2(acc[0][0], d0, w0); fma2(acc[0][1], d0, w1);
            fma2(acc[1][0], d1, w0); fma2(acc[1][1], d1, w1);
            fma2(acc[2][0], d2, w0); fma2(acc[2][1], d2, w1);
            fma2(acc[3][0], d3, w0); fma2(acc[3][1], d3, w1);
            fma2(acc[4][0], d4, w0); fma2(acc[4][1], d4, w1);
            fma2(acc[5][0], d5, w0); fma2(acc[5][1], d5, w1);
            fma2(acc[6][0], d6, w0); fma2(acc[6][1], d6, w1);
            fma2(acc[7][0], d7, w0); fma2(acc[7][1], d7, w1);
        }
    }
    #pragma unroll
    for (int i = 0; i < 8; i++) {
        int row = row0 + (ty << 3) + i;
        #pragma unroll
        for (int p = 0; p < 2; p++) {
            float lo, hi; unpack2(lo, hi, acc[i][p]);
            int col = col0 + (tx << 2) + 2 * p;
            Out[row * Hh + col]     = lo + bias[col];
            Out[row * Hh + col + 1] = hi + bias[col + 1];
        }
    }
}

// ---------------- injection projection ----------------
__global__ void inj_kernel(const float* __restrict__ tie,
                           const float* __restrict__ Winj, const float* __restrict__ binj) {
    int b = blockIdx.x;
    int j = threadIdx.x;
    __shared__ float t[128];
    if (j < 128) t[j] = tie[b * 128 + j];
    __syncthreads();
    float acc = binj[j];
    #pragma unroll 8
    for (int k = 0; k < 128; k++) acc = fmaf(t[k], Winj[k * Hh + j], acc);
    g_inj[b * Hh + j] = acc;
}

// ---------------- fused span scorer: 16x4 tile, row-pair FFMA2 (w duplicated) ----------------
// smem floats: xs 256*SXST | wbuf[2][SCH*256] | bias 256 | w2 256
// red (64 x 65) aliases wbuf after last chunk.
#define SC_XS_FLOATS   (256 * SXST)
#define SC_WB_OFF      SC_XS_FLOATS
#define SC_BIAS_OFF    (SC_WB_OFF + 2 * SCH * 256)
#define SC_W2_OFF      (SC_BIAS_OFF + 256)
#define SC_SMEM_FLOATS (SC_W2_OFF + 256)
static const int SC_SMEM_BYTES = SC_SMEM_FLOATS * 4;   // 104,448 B -> 2 CTAs/SM

__global__ __launch_bounds__(256, 2)
void scorer_kernel(const float* __restrict__ Ws1, const float* __restrict__ bs1,
                   const float* __restrict__ Ws2, const float* __restrict__ bs2) {
    extern __shared__ float sm[];
    float* xs   = sm;                        // [k=256][r, stride SXST]
    float* wbuf = sm + SC_WB_OFF;            // [2][SCH][256] row-major
    float* bs1c = sm + SC_BIAS_OFF;          // 256
    float* w2c  = sm + SC_W2_OFF;            // 256
    float* red  = wbuf;                      // aliased after last chunk: [64][65]
    __shared__ int sS[64], sE[64];

    const int b   = blockIdx.y;
    const int n0  = blockIdx.x * 64;
    const int tid = threadIdx.x;
    const int tx  = tid & 63;        // 64 col-groups of 4
    const int ty  = tid >> 6;        // 4 row-groups of 16

    if (tid < 64) {
        sS[tid] = g_sarr[n0 + tid]; sE[tid] = g_earr[n0 + tid];
    }
    bs1c[tid] = bs1[tid];
    w2c[tid]  = Ws2[tid];
    __syncthreads();

    // fill xs[k][r] = relu(A[s_r][k] + E[e_r][k]); thread owns column k = tid
    {
        const float* Ab = g_A + b * Tt * Hh + tid;
        const float* Eb = g_E + b * Tt * Hh + tid;
        float* xp = xs + tid * SXST;
        #pragma unroll 4
        for (int r = 0; r < 64; r++) {
            float v = Ab[sS[r] * Hh] + Eb[sE[r] * Hh];
            xp[r] = v > 0.f ? v : 0.f;
        }
    }

    // staging coords: chunk = SCH*256 floats = 1024 float4; 4 float4 per thread
    const int kk0 = tid >> 6,          c40 = tid & 63;
    const int kk1 = (tid + 256) >> 6,  c41 = tid & 63;
    const int kk2 = (tid + 512) >> 6,  c42 = tid & 63;
    const int kk3 = (tid + 768) >> 6,  c43 = tid & 63;

    float4 pf0 = ((const float4*)(Ws1 + kk0 * Hh))[c40];
    float4 pf1 = ((const float4*)(Ws1 + kk1 * Hh))[c41];
    float4 pf2 = ((const float4*)(Ws1 + kk2 * Hh))[c42];
    float4 pf3 = ((const float4*)(Ws1 + kk3 * Hh))[c43];
    {
        float4* dst = (float4*)wbuf;
        dst[kk0 * 64 + c40] = pf0;
        dst[kk1 * 64 + c41] = pf1;
        dst[kk2 * 64 + c42] = pf2;
        dst[kk3 * 64 + c43] = pf3;
    }
    __syncthreads();   // xs + buf0 ready

    // acc[rp][c]: row-pair rp (rows ty*16+2rp, +2rp+1), column tx*4+c
    u64 acc[8][4] = {};

    #pragma unroll 1
    for (int kc = 0; kc < 16; kc++) {
        const int buf = kc & 1;
        if (kc < 15) {
            const float* Wn = Ws1 + (kc + 1) * SCH * Hh;
            pf0 = ((const float4*)(Wn + kk0 * Hh))[c40];
            pf1 = ((const float4*)(Wn + kk1 * Hh))[c41];
            pf2 = ((const float4*)(Wn + kk2 * Hh))[c42];
            pf3 = ((const float4*)(Wn + kk3 * Hh))[c43];
        }

        const float* xp = xs + (kc * SCH) * SXST + (ty << 4);
        const float* wp = wbuf + buf * (SCH * 256) + (tx << 2);

        #pragma unroll
        for (int k = 0; k < SCH; k++) {
            // w: 4 scalar cols -> 4 dups (ONLY dups in the loop)
            float4 wv = *(const float4*)(wp + (k << 8));   // 16B/lane, conflict-free
            u64 e0 = dup2(wv.x), e1 = dup2(wv.y), e2 = dup2(wv.z), e3 = dup2(wv.w);
            // a: 8 row-pairs, natively packed in xs (broadcast within warp)
            const u64* ap = (const u64*)(xp + k * SXST);
            ulonglong2 p0 = *(const ulonglong2*)(ap);
            ulonglong2 p1 = *(const ulonglong2*)(ap + 2);
            ulonglong2 p2 = *(const ulonglong2*)(ap + 4);
            ulonglong2 p3 = *(const ulonglong2*)(ap + 6);
            u64 r0 = p0.x, r1 = p0.y, r2 = p1.x, r3 = p1.y;
            u64 r4 = p2.x, r5 = p2.y, r6 = p3.x, r7 = p3.y;
            fma2(acc[0][0], r0, e0); fma2(acc[0][1], r0, e1);
            fma2(acc[0][2], r0, e2); fma2(acc[0][3], r0, e3);
            fma2(acc[1][0], r1, e0); fma2(acc[1][1], r1, e1);
            fma2(acc[1][2], r1, e2); fma2(acc[1][3], r1, e3);
            fma2(acc[2][0], r2, e0); fma2(acc[2][1], r2, e1);
            fma2(acc[2][2], r2, e2); fma2(acc[2][3], r2, e3);
            fma2(acc[3][0], r3, e0); fma2(acc[3][1], r3, e1);
            fma2(acc[3][2], r3, e2); fma2(acc[3][3], r3, e3);
            fma2(acc[4][0], r4, e0); fma2(acc[4][1], r4, e1);
            fma2(acc[4][2], r4, e2); fma2(acc[4][3], r4, e3);
            fma2(acc[5][0], r5, e0); fma2(acc[5][1], r5, e1);
            fma2(acc[5][2], r5, e2); fma2(acc[5][3], r5, e3);
            fma2(acc[6][0], r6, e0); fma2(acc[6][1], r6, e1);
            fma2(acc[6][2], r6, e2); fma2(acc[6][3], r6, e3);
            fma2(acc[7][0], r7, e0); fma2(acc[7][1], r7, e1);
            fma2(acc[7][2], r7, e2); fma2(acc[7][3], r7, e3);
        }

        if (kc < 15) {
            // store prefetched chunk into the other buffer; WAR-safe (prev sync)
            float4* dst = (float4*)(wbuf + (buf ^ 1) * (SCH * 256));
            dst[kk0 * 64 + c40] = pf0;
            dst[kk1 * 64 + c41] = pf1;
            dst[kk2 * 64 + c42] = pf2;
            dst[kk3 * 64 + c43] = pf3;
        }
        __syncthreads();   // single barrier per chunk
    }

    // layer-2 epilogue; acc[rp][c]: lo = row 2rp, hi = row 2rp+1, col = 4tx+c
    float scacc[16];
    #pragma unroll
    for (int i = 0; i < 16; i++) scacc[i] = 0.f;
    #pragma unroll
    for (int rp = 0; rp < 8; rp++) {
        #pragma unroll
        for (int c = 0; c < 4; c++) {
            float lo, hi; unpack2(lo, hi, acc[rp][c]);
            int cb = (tx << 2) + c;
            float h0 = lo + bs1c[cb];
            if (h0 > 0.f) scacc[2 * rp]     = fmaf(h0, w2c[cb], scacc[2 * rp]);
            float h1 = hi + bs1c[cb];
            if (h1 > 0.f) scacc[2 * rp + 1] = fmaf(h1, w2c[cb], scacc[2 * rp + 1]);
        }
    }

    // reduction: red[row][65] over 64 col-groups (wbuf no longer needed)
    #pragma unroll
    for (int i = 0; i < 16; i++) red[((ty << 4) + i) * 65 + tx] = scacc[i];
    __syncthreads();
    if (tid < 64) {
        float ssum = bs2[0];
        const float* rp = red + tid * 65;
        #pragma unroll
        for (int t = 0; t < 64; t++) ssum += rp[t];
        g_scores[b * NSPANS + n0 + tid] = ssum;
    }
}

// ---------------- per-batch radix top-k, parallel stable extraction ----------------
__global__ void topk_kernel(const int* __restrict__ mask) {
    const int b   = blockIdx.x;
    const int tid = threadIdx.x;
    __shared__ unsigned keys[NSPANS];
    __shared__ int hist[256];
    __shared__ unsigned sh_prefix;
    __shared__ int sh_kk;
    __shared__ int sgt[256], seqv[256];

    const int* mb = mask + b * Tt;
    for (int i = tid; i < NSPANS; i += 256) {
        int s = g_sarr[i], e = g_earr[i];
        float v = (mb[s] != 0 && mb[e] != 0) ? g_scores[b * NSPANS + i]
                                             : __int_as_float(0xff800000);
        unsigned u = __float_as_uint(v);
        keys[i] = (u & 0x80000000u) ? ~u : (u | 0x80000000u);
    }

    unsigned prefix = 0;
    int kk = KTOP;
    for (int level = 3; level >= 0; level--) {
        hist[tid] = 0;
        __syncthreads();
        const unsigned himask = (level == 3) ? 0u : (0xFFFFFFFFu << ((level + 1) * 8));
        for (int i = tid; i < NSPANS; i += 256) {
            unsigned kv = keys[i];
            if ((kv & himask) == (prefix & himask))
                atomicAdd(&hist[(kv >> (level * 8)) & 255], 1);
        }
        __syncthreads();
        if (tid == 0) {
            int cum = 0, chosen = 0, kknew = kk;
            for (int t = 255; t >= 0; t--) {
                int c = hist[t];
                if (cum + c >= kk) { chosen = t; kknew = kk - cum; break; }
                cum += c;
            }
            sh_prefix = prefix | ((unsigned)chosen << (level * 8));
            sh_kk = kknew;
        }
        __syncthreads();
        prefix = sh_prefix;
        kk = sh_kk;
        __syncthreads();
    }

    const unsigned Kstar = prefix;
    const int CH = (NSPANS + 255) / 256;
    int lo = tid * CH; if (lo > NSPANS) lo = NSPANS;
    int hi = lo + CH;  if (hi > NSPANS) hi = NSPANS;

    int cgt = 0, ceq = 0;
    for (int i = lo; i < hi; i++) {
        unsigned kv = keys[i];
        cgt += (kv > Kstar);
        ceq += (kv == Kstar);
    }
    sgt[tid] = cgt; seqv[tid] = ceq;
    __syncthreads();
    if (tid == 0) {
        int ag = 0, ae = 0;
        for (int t = 0; t < 256; t++) {
            int g = sgt[t], e = seqv[t];
            sgt[t] = ag; seqv[t] = ae;
            ag += g; ae += e;
        }
    }
    __syncthreads();

    int gtb = sgt[tid], eqb = seqv[tid];
    for (int i = lo; i < hi; i++) {
        unsigned kv = keys[i];
        bool isgt = (kv > Kstar);
        bool iseq = (kv == Kstar);
        if (isgt || (iseq && eqb < kk)) {
            int eqt = eqb < kk ? eqb : kk;
            int pos = gtb + eqt;
            unsigned u = (kv & 0x80000000u) ? (kv & 0x7FFFFFFFu) : ~kv;
            g_topidx[b * KTOP + pos]   = i;
            g_topscore[b * KTOP + pos] = __uint_as_float(u);
        }
        gtb += isgt;
        eqb += iseq;
    }
}

// ---------------- fused head ----------------
#define HD_SMEM_FLOATS (256*XST + 256*128 + 128 + 128 + 64*16)
static const int HD_SMEM_BYTES = HD_SMEM_FLOATS * 4;

__global__ __launch_bounds__(256, 1)
void head_kernel(const float* __restrict__ Wsec, const float* __restrict__ bsec,
                 const float* __restrict__ Wpred, const float* __restrict__ bpred,
                 const int* __restrict__ mask, float* __restrict__ out) {
    extern __shared__ float sm[];
    float* xs  = sm;
    float* ws  = xs + 256 * XST;
    float* bc  = ws + 256 * 128;
    float* wpc = bc + 128;
    float* red = wpc + 128;
    __shared__ int sS[64], sE[64];
    __shared__ float sMask[64], sScore[64];

    const int b   = blockIdx.y;
    const int k0  = blockIdx.x * 64;
    const int tid = threadIdx.x;
    const int tx  = tid & 15, ty = tid >> 4;

    if (tid < 64) {
        int n = g_topidx[b * KTOP + k0 + tid];
        int s = g_sarr[n], e = g_earr[n];
        sS[tid] = s; sE[tid] = e;
        sMask[tid] = (mask[b * Tt + s] != 0 && mask[b * Tt + e] != 0) ? 1.f : 0.f;
        float sc = g_topscore[b * KTOP + k0 + tid];
        sScore[tid] = isinf(sc) ? -1.f : sc;
    }
    __syncthreads();

    const float* Ab = g_A + b * Tt * Hh;
    const float* Eb = g_E + b * Tt * Hh;
    for (int r = 0; r < 64; r++)
        xs[tid * XST + r] = Ab[sS[r] * Hh + tid] + Eb[sE[r] * Hh + tid];

    float scacc[4] = {0.f, 0.f, 0.f, 0.f};

    #pragma unroll 1
    for (int jb = 0; jb < 2; jb++) {
        const int jbase = jb * 128;
        __syncthreads();
        #pragma unroll
        for (int idx = tid; idx < 8192; idx += 256) {
            int k = idx >> 5, c4 = idx & 31;
            ((float4*)ws)[idx] = ((const float4*)(Wsec + k * Hh + jbase))[c4];
        }
        if (tid < 128) {
            bc[tid]  = bsec[jbase + tid] + g_inj[b * Hh + jbase + tid];
            wpc[tid] = Wpred[jbase + tid];
        }
        __syncthreads();

        u64 acc[4][4] = {};
        const float* xp = xs + (ty << 2);
        const float* wl = ws + (tx << 2);
        const float* wh = wl + 64;
        #pragma unroll 4
        for (int k = 0; k < Hh; k++) {
            const float4 a = *(const float4*)(xp + k * XST);
            u64 w0, w1, w2, w3;
            lds_pair(w0, w1, wl + (k << 7));
            lds_pair(w2, w3, wh + (k << 7));
            u64 d0 = dup2(a.x), d1 = dup2(a.y), d2 = dup2(a.z), d3 = dup2(a.w);
            fma2(acc[0][0], d0, w0); fma2(acc[0][1], d0, w1);
            fma2(acc[0][2], d0, w2); fma2(acc[0][3], d0, w3);
            fma2(acc[1][0], d1, w0); fma2(acc[1][1], d1, w1);
            fma2(acc[1][2], d1, w2); fma2(acc[1][3], d1, w3);
            fma2(acc[2][0], d2, w0); fma2(acc[2][1], d2, w1);
            fma2(acc[2][2], d2, w2); fma2(acc[2][3], d2, w3);
            fma2(acc[3][0], d3, w0); fma2(acc[3][1], d3, w1);
            fma2(acc[3][2], d3, w2); fma2(acc[3][3], d3, w3);
        }
        #pragma unroll
        for (int i = 0; i < 4; i++) {
            #pragma unroll
            for (int p = 0; p < 4; p++) {
                float lo, hi; unpack2(lo, hi, acc[i][p]);
                int cb = (p < 2) ? ((tx << 2) + 2 * p) : (64 + (tx << 2) + 2 * (p - 2));
                float h0 = lo + bc[cb];
                if (h0 > 0.f) scacc[i] = fmaf(h0, wpc[cb], scacc[i]);
                float h1 = hi + bc[cb + 1];
                if (h1 > 0.f) scacc[i] = fmaf(h1, wpc[cb + 1], scacc[i]);
            }
        }
    }

    __syncthreads();
    #pragma unroll
    for (int i = 0; i < 4; i++) red[((ty << 2) + i) * 16 + tx] = scacc[i];
    __syncthreads();
    if (tid < 64) {
        float ssum = bpred[0] + sScore[tid];
        #pragma unroll
        for (int t = 0; t < 16; t++) ssum += red[tid * 16 + t];
        float p = 1.f / (1.f + expf(-ssum));
        out[b * KTOP + k0 + tid] = p * sMask[tid];
    }
}

// ---------------- launch ----------------
extern "C" void kernel_launch(void* const* d_in, const int* in_sizes, int n_in,
                              void* d_out, int out_size) {
    const float* inputs   = (const float*)d_in[0];
    const int*   in_mask  = (const int*)  d_in[1];
    const float* tie      = (const float*)d_in[2];
    const float* W_start  = (const float*)d_in[3];
    const float* b_start  = (const float*)d_in[4];
    const float* W_end    = (const float*)d_in[5];
    const float* b_end    = (const float*)d_in[6];
    const float* W_s1     = (const float*)d_in[7];
    const float* b_s1     = (const float*)d_in[8];
    const float* W_s2     = (const float*)d_in[9];
    const float* b_s2     = (const float*)d_in[10];
    const float* W_inj    = (const float*)d_in[11];
    const float* b_inj    = (const float*)d_in[12];
    const float* W_sec    = (const float*)d_in[13];
    const float* b_sec    = (const float*)d_in[14];
    const float* W_pred   = (const float*)d_in[15];
    const float* b_pred   = (const float*)d_in[16];
    float* out = (float*)d_out;

    cudaFuncSetAttribute(scorer_kernel, cudaFuncAttributeMaxDynamicSharedMemorySize, SC_SMEM_BYTES);
    cudaFuncSetAttribute(head_kernel,   cudaFuncAttributeMaxDynamicSharedMemorySize, HD_SMEM_BYTES);

    build_span_idx_kernel<<<(NSPANS + 255) / 256, 256>>>();
    proj_kernel<<<dim3(Hh / 64, (Bb * Tt) / 128, 2), 256>>>(inputs, W_start, b_start, W_end, b_end);
    inj_kernel<<<Bb, 256>>>(tie, W_inj, b_inj);
    scorer_kernel<<<dim3(NSPANS / 64, Bb), 256, SC_SMEM_BYTES>>>(W_s1, b_s1, W_s2, b_s2);
    topk_kernel<<<Bb, 256>>>(in_mask);
    head_kernel<<<dim3(KTOP / 64, Bb), 256, HD_SMEM_BYTES>>>(W_sec, b_sec, W_pred, b_pred, in_mask, out);
}

// round 13
// speedup vs baseline: 1.4045x; 1.0335x over previous
#include <cuda_runtime.h>
#include <math.h>

#define Bb      64
#define Tt      128
#define Dd      768
#define Hh      256
#define NSPANS  8256
#define KTOP    256
#define XST     68          // proj w stride
#define RST     132         // proj xs row-stride
#define SXST    68          // scorer/head xs row-stride (64 rows + pad, 16B-aligned)
#define SCH     16          // k-chunk size (16 chunks, double-buffered)

typedef unsigned long long u64;

// ---------------- packed fp32x2 helpers (sm_103a FFMA2 path) ----------------
__device__ __forceinline__ u64 dup2(float a) {
    u64 r; asm("mov.b64 %0, {%1, %2};" : "=l"(r) : "f"(a), "f"(a)); return r;
}
__device__ __forceinline__ void fma2(u64& acc, u64 a, u64 b) {
    asm("fma.rn.f32x2 %0, %1, %2, %0;" : "+l"(acc) : "l"(a), "l"(b));
}
__device__ __forceinline__ void unpack2(float& lo, float& hi, u64 v) {
    asm("mov.b64 {%0, %1}, %2;" : "=f"(lo), "=f"(hi) : "l"(v));
}

// ---------------- device scratch ----------------
__device__ float g_A[Bb*Tt*Hh];
__device__ float g_E[Bb*Tt*Hh];
__device__ float g_scores[Bb*NSPANS];
__device__ float g_inj[Bb*Hh];
__device__ int   g_topidx[Bb*KTOP];
__device__ float g_topscore[Bb*KTOP];
__device__ int   g_sarr[NSPANS];
__device__ int   g_earr[NSPANS];

// ---------------- span index decode ----------------
__global__ void build_span_idx_kernel() {
    int n = blockIdx.x * blockDim.x + threadIdx.x;
    if (n >= NSPANS) return;
    int s = 0, off = 0;
    while (n >= off + (Tt - s)) { off += (Tt - s); s++; }
    g_sarr[n] = s;
    g_earr[n] = s + (n - off);
}

// ---------------- projections: X[8192,768]@W[768,256]+b, row-pair FFMA2 ----------------
__global__ __launch_bounds__(256)
void proj_kernel(const float* __restrict__ X,
                 const float* __restrict__ Wst, const float* __restrict__ bst,
                 const float* __restrict__ Wen, const float* __restrict__ ben) {
    const float* W    = blockIdx.z ? Wen : Wst;
    const float* bias = blockIdx.z ? ben : bst;
    float*       Out  = blockIdx.z ? g_E : g_A;

    __shared__ float xs[32 * RST];      // [k][r] 128 rows
    __shared__ float wsm[32 * XST];     // [k][c] 64 cols

    const int row0 = blockIdx.y * 128;
    const int col0 = blockIdx.x * 64;
    const int tid  = threadIdx.x;
    const int tx   = tid & 15, ty = tid >> 4;   // 16 colgroups x 16 rowgroups(8)

    u64 acc[4][4] = {};   // [rowpair][col]
    for (int k0 = 0; k0 < Dd; k0 += 32) {
        __syncthreads();
        #pragma unroll
        for (int idx = tid; idx < 128 * 32; idx += 256) {
            int r = idx >> 5, k = idx & 31;
            xs[k * RST + r] = X[(row0 + r) * Dd + k0 + k];
        }
        #pragma unroll
        for (int idx = tid; idx < 32 * 64; idx += 256) {
            int k = idx >> 6, cc = idx & 63;
            wsm[k * XST + cc] = W[(k0 + k) * Hh + col0 + cc];
        }
        __syncthreads();
        const float* xp = xs + (ty << 3);
        const float* wp = wsm + (tx << 2);
        #pragma unroll 8
        for (int k = 0; k < 32; k++) {
            float4 wv = *(const float4*)(wp + k * XST);
            u64 e0 = dup2(wv.x), e1 = dup2(wv.y), e2 = dup2(wv.z), e3 = dup2(wv.w);
            ulonglong2 p0 = *(const ulonglong2*)(xp + k * RST);
            ulonglong2 p1 = *(const ulonglong2*)(xp + k * RST + 4);
            u64 r0 = p0.x, r1 = p0.y, r2 = p1.x, r3 = p1.y;
            fma2(acc[0][0], r0, e0); fma2(acc[0][1], r0, e1);
            fma2(acc[0][2], r0, e2); fma2(acc[0][3], r0, e3);
            fma2(acc[1][0], r1, e0); fma2(acc[1][1], r1, e1);
            fma2(acc[1][2], r1, e2); fma2(acc[1][3], r1, e3);
            fma2(acc[2][0], r2, e0); fma2(acc[2][1], r2, e1);
            fma2(acc[2][2], r2, e2); fma2(acc[2][3], r2, e3);
            fma2(acc[3][0], r3, e0); fma2(acc[3][1], r3, e1);
            fma2(acc[3][2], r3, e2); fma2(acc[3][3], r3, e3);
        }
    }
    #pragma unroll
    for (int rp = 0; rp < 4; rp++) {
        int row = row0 + (ty << 3) + 2 * rp;
        #pragma unroll
        for (int c = 0; c < 4; c++) {
            float lo, hi; unpack2(lo, hi, acc[rp][c]);
            int col = col0 + (tx << 2) + c;
            Out[row * Hh + col]       = lo + bias[col];
            Out[(row + 1) * Hh + col] = hi + bias[col];
        }
    }
}

// ---------------- injection projection ----------------
__global__ void inj_kernel(const float* __restrict__ tie,
                           const float* __restrict__ Winj, const float* __restrict__ binj) {
    int b = blockIdx.x;
    int j = threadIdx.x;
    __shared__ float t[128];
    if (j < 128) t[j] = tie[b * 128 + j];
    __syncthreads();
    float acc = binj[j];
    #pragma unroll 8
    for (int k = 0; k < 128; k++) acc = fmaf(t[k], Winj[k * Hh + j], acc);
    g_inj[b * Hh + j] = acc;
}

// ---------------- shared smem layout for scorer & head ----------------
#define SC_XS_FLOATS   (256 * SXST)
#define SC_WB_OFF      SC_XS_FLOATS
#define SC_BIAS_OFF    (SC_WB_OFF + 2 * SCH * 256)
#define SC_W2_OFF      (SC_BIAS_OFF + 256)
#define SC_SMEM_FLOATS (SC_W2_OFF + 256)
static const int SC_SMEM_BYTES = SC_SMEM_FLOATS * 4;   // 104,448 B -> 2 CTAs/SM

// ---------------- fused span scorer (round-12, unchanged) ----------------
__global__ __launch_bounds__(256, 2)
void scorer_kernel(const float* __restrict__ Ws1, const float* __restrict__ bs1,
                   const float* __restrict__ Ws2, const float* __restrict__ bs2) {
    extern __shared__ float sm[];
    float* xs   = sm;
    float* wbuf = sm + SC_WB_OFF;
    float* bs1c = sm + SC_BIAS_OFF;
    float* w2c  = sm + SC_W2_OFF;
    float* red  = wbuf;
    __shared__ int sS[64], sE[64];

    const int b   = blockIdx.y;
    const int n0  = blockIdx.x * 64;
    const int tid = threadIdx.x;
    const int tx  = tid & 63;
    const int ty  = tid >> 6;

    if (tid < 64) {
        sS[tid] = g_sarr[n0 + tid]; sE[tid] = g_earr[n0 + tid];
    }
    bs1c[tid] = bs1[tid];
    w2c[tid]  = Ws2[tid];
    __syncthreads();

    {
        const float* Ab = g_A + b * Tt * Hh + tid;
        const float* Eb = g_E + b * Tt * Hh + tid;
        float* xp = xs + tid * SXST;
        #pragma unroll 4
        for (int r = 0; r < 64; r++) {
            float v = Ab[sS[r] * Hh] + Eb[sE[r] * Hh];
            xp[r] = v > 0.f ? v : 0.f;
        }
    }

    const int kk0 = tid >> 6,          c40 = tid & 63;
    const int kk1 = (tid + 256) >> 6,  c41 = tid & 63;
    const int kk2 = (tid + 512) >> 6,  c42 = tid & 63;
    const int kk3 = (tid + 768) >> 6,  c43 = tid & 63;

    float4 pf0 = ((const float4*)(Ws1 + kk0 * Hh))[c40];
    float4 pf1 = ((const float4*)(Ws1 + kk1 * Hh))[c41];
    float4 pf2 = ((const float4*)(Ws1 + kk2 * Hh))[c42];
    float4 pf3 = ((const float4*)(Ws1 + kk3 * Hh))[c43];
    {
        float4* dst = (float4*)wbuf;
        dst[kk0 * 64 + c40] = pf0;
        dst[kk1 * 64 + c41] = pf1;
        dst[kk2 * 64 + c42] = pf2;
        dst[kk3 * 64 + c43] = pf3;
    }
    __syncthreads();

    u64 acc[8][4] = {};

    #pragma unroll 1
    for (int kc = 0; kc < 16; kc++) {
        const int buf = kc & 1;
        if (kc < 15) {
            const float* Wn = Ws1 + (kc + 1) * SCH * Hh;
            pf0 = ((const float4*)(Wn + kk0 * Hh))[c40];
            pf1 = ((const float4*)(Wn + kk1 * Hh))[c41];
            pf2 = ((const float4*)(Wn + kk2 * Hh))[c42];
            pf3 = ((const float4*)(Wn + kk3 * Hh))[c43];
        }

        const float* xp = xs + (kc * SCH) * SXST + (ty << 4);
        const float* wp = wbuf + buf * (SCH * 256) + (tx << 2);

        #pragma unroll
        for (int k = 0; k < SCH; k++) {
            float4 wv = *(const float4*)(wp + (k << 8));
            u64 e0 = dup2(wv.x), e1 = dup2(wv.y), e2 = dup2(wv.z), e3 = dup2(wv.w);
            const u64* ap = (const u64*)(xp + k * SXST);
            ulonglong2 p0 = *(const ulonglong2*)(ap);
            ulonglong2 p1 = *(const ulonglong2*)(ap + 2);
            ulonglong2 p2 = *(const ulonglong2*)(ap + 4);
            ulonglong2 p3 = *(const ulonglong2*)(ap + 6);
            u64 r0 = p0.x, r1 = p0.y, r2 = p1.x, r3 = p1.y;
            u64 r4 = p2.x, r5 = p2.y, r6 = p3.x, r7 = p3.y;
            fma2(acc[0][0], r0, e0); fma2(acc[0][1], r0, e1);
            fma2(acc[0][2], r0, e2); fma2(acc[0][3], r0, e3);
            fma2(acc[1][0], r1, e0); fma2(acc[1][1], r1, e1);
            fma2(acc[1][2], r1, e2); fma2(acc[1][3], r1, e3);
            fma2(acc[2][0], r2, e0); fma2(acc[2][1], r2, e1);
            fma2(acc[2][2], r2, e2); fma2(acc[2][3], r2, e3);
            fma2(acc[3][0], r3, e0); fma2(acc[3][1], r3, e1);
            fma2(acc[3][2], r3, e2); fma2(acc[3][3], r3, e3);
            fma2(acc[4][0], r4, e0); fma2(acc[4][1], r4, e1);
            fma2(acc[4][2], r4, e2); fma2(acc[4][3], r4, e3);
            fma2(acc[5][0], r5, e0); fma2(acc[5][1], r5, e1);
            fma2(acc[5][2], r5, e2); fma2(acc[5][3], r5, e3);
            fma2(acc[6][0], r6, e0); fma2(acc[6][1], r6, e1);
            fma2(acc[6][2], r6, e2); fma2(acc[6][3], r6, e3);
            fma2(acc[7][0], r7, e0); fma2(acc[7][1], r7, e1);
            fma2(acc[7][2], r7, e2); fma2(acc[7][3], r7, e3);
        }

        if (kc < 15) {
            float4* dst = (float4*)(wbuf + (buf ^ 1) * (SCH * 256));
            dst[kk0 * 64 + c40] = pf0;
            dst[kk1 * 64 + c41] = pf1;
            dst[kk2 * 64 + c42] = pf2;
            dst[kk3 * 64 + c43] = pf3;
        }
        __syncthreads();
    }

    float scacc[16];
    #pragma unroll
    for (int i = 0; i < 16; i++) scacc[i] = 0.f;
    #pragma unroll
    for (int rp = 0; rp < 8; rp++) {
        #pragma unroll
        for (int c = 0; c < 4; c++) {
            float lo, hi; unpack2(lo, hi, acc[rp][c]);
            int cb = (tx << 2) + c;
            float h0 = lo + bs1c[cb];
            if (h0 > 0.f) scacc[2 * rp]     = fmaf(h0, w2c[cb], scacc[2 * rp]);
            float h1 = hi + bs1c[cb];
            if (h1 > 0.f) scacc[2 * rp + 1] = fmaf(h1, w2c[cb], scacc[2 * rp + 1]);
        }
    }

    #pragma unroll
    for (int i = 0; i < 16; i++) red[((ty << 4) + i) * 65 + tx] = scacc[i];
    __syncthreads();
    if (tid < 64) {
        float ssum = bs2[0];
        const float* rp = red + tid * 65;
        #pragma unroll
        for (int t = 0; t < 64; t++) ssum += rp[t];
        g_scores[b * NSPANS + n0 + tid] = ssum;
    }
}

// ---------------- block inclusive scan (256 threads) ----------------
__device__ __forceinline__ int block_incl_scan(int v, int tid, int* wsums) {
    __syncthreads();                      // protect wsums reuse
    int lane = tid & 31, wid = tid >> 5;
    #pragma unroll
    for (int o = 1; o < 32; o <<= 1) {
        int n = __shfl_up_sync(0xffffffffu, v, o);
        if (lane >= o) v += n;
    }
    if (lane == 31) wsums[wid] = v;
    __syncthreads();
    if (tid == 0) {
        int s = 0;
        #pragma unroll
        for (int w = 0; w < 8; w++) { int x = wsums[w]; wsums[w] = s; s += x; }
    }
    __syncthreads();
    return v + wsums[wid];
}

// ---------------- per-batch radix top-k, fully parallel scans ----------------
__global__ void topk_kernel(const int* __restrict__ mask) {
    const int b   = blockIdx.x;
    const int tid = threadIdx.x;
    __shared__ unsigned keys[NSPANS];
    __shared__ int hist[256];
    __shared__ unsigned sh_prefix;
    __shared__ int sh_kk;
    __shared__ int wsums[8];

    const int* mb = mask + b * Tt;
    for (int i = tid; i < NSPANS; i += 256) {
        int s = g_sarr[i], e = g_earr[i];
        float v = (mb[s] != 0 && mb[e] != 0) ? g_scores[b * NSPANS + i]
                                             : __int_as_float(0xff800000);
        unsigned u = __float_as_uint(v);
        keys[i] = (u & 0x80000000u) ? ~u : (u | 0x80000000u);
    }

    unsigned prefix = 0;
    int kk = KTOP;
    for (int level = 3; level >= 0; level--) {
        hist[tid] = 0;
        __syncthreads();
        const unsigned himask = (level == 3) ? 0u : (0xFFFFFFFFu << ((level + 1) * 8));
        for (int i = tid; i < NSPANS; i += 256) {
            unsigned kv = keys[i];
            if ((kv & himask) == (prefix & himask))
                atomicAdd(&hist[(kv >> (level * 8)) & 255], 1);
        }
        __syncthreads();
        // parallel suffix-sum bucket selection
        int bucket = 255 - tid;
        int v = hist[bucket];
        int S = block_incl_scan(v, tid, wsums);   // S = suffix sum from bucket up
        if (S >= kk && S - v < kk) {
            sh_prefix = prefix | ((unsigned)bucket << (level * 8));
            sh_kk = kk - (S - v);
        }
        __syncthreads();
        prefix = sh_prefix;
        kk = sh_kk;
        __syncthreads();
    }

    // parallel stable extraction
    const unsigned Kstar = prefix;
    const int CH = (NSPANS + 255) / 256;
    int lo = tid * CH; if (lo > NSPANS) lo = NSPANS;
    int hi = lo + CH;  if (hi > NSPANS) hi = NSPANS;

    int cgt = 0, ceq = 0;
    for (int i = lo; i < hi; i++) {
        unsigned kv = keys[i];
        cgt += (kv > Kstar);
        ceq += (kv == Kstar);
    }
    int Sg = block_incl_scan(cgt, tid, wsums);
    int Se = block_incl_scan(ceq, tid, wsums);
    int gtb = Sg - cgt, eqb = Se - ceq;

    for (int i = lo; i < hi; i++) {
        unsigned kv = keys[i];
        bool isgt = (kv > Kstar);
        bool iseq = (kv == Kstar);
        if (isgt || (iseq && eqb < kk)) {
            int eqt = eqb < kk ? eqb : kk;
            int pos = gtb + eqt;
            unsigned u = (kv & 0x80000000u) ? (kv & 0x7FFFFFFFu) : ~kv;
            g_topidx[b * KTOP + pos]   = i;
            g_topscore[b * KTOP + pos] = __uint_as_float(u);
        }
        gtb += isgt;
        eqb += iseq;
    }
}

// ---------------- fused head: scorer-clone (64 top spans x 256 cols) ----------------
__global__ __launch_bounds__(256, 2)
void head_kernel(const float* __restrict__ Wsec, const float* __restrict__ bsec,
                 const float* __restrict__ Wpred, const float* __restrict__ bpred,
                 const int* __restrict__ mask, float* __restrict__ out) {
    extern __shared__ float sm[];
    float* xs   = sm;
    float* wbuf = sm + SC_WB_OFF;
    float* bc   = sm + SC_BIAS_OFF;
    float* wpc  = sm + SC_W2_OFF;
    float* red  = wbuf;
    __shared__ int sS[64], sE[64];
    __shared__ float sMask[64], sScore[64];

    const int b   = blockIdx.y;
    const int k0  = blockIdx.x * 64;
    const int tid = threadIdx.x;
    const int tx  = tid & 63;
    const int ty  = tid >> 6;

    if (tid < 64) {
        int n = g_topidx[b * KTOP + k0 + tid];
        int s = g_sarr[n], e = g_earr[n];
        sS[tid] = s; sE[tid] = e;
        sMask[tid] = (mask[b * Tt + s] != 0 && mask[b * Tt + e] != 0) ? 1.f : 0.f;
        float sc = g_topscore[b * KTOP + k0 + tid];
        sScore[tid] = isinf(sc) ? -1.f : sc;
    }
    bc[tid]  = bsec[tid] + g_inj[b * Hh + tid];
    wpc[tid] = Wpred[tid];
    __syncthreads();

    {
        const float* Ab = g_A + b * Tt * Hh + tid;
        const float* Eb = g_E + b * Tt * Hh + tid;
        float* xp = xs + tid * SXST;
        #pragma unroll 4
        for (int r = 0; r < 64; r++)
            xp[r] = Ab[sS[r] * Hh] + Eb[sE[r] * Hh];   // no relu
    }

    const int kk0 = tid >> 6,          c40 = tid & 63;
    const int kk1 = (tid + 256) >> 6,  c41 = tid & 63;
    const int kk2 = (tid + 512) >> 6,  c42 = tid & 63;
    const int kk3 = (tid + 768) >> 6,  c43 = tid & 63;

    float4 pf0 = ((const float4*)(Wsec + kk0 * Hh))[c40];
    float4 pf1 = ((const float4*)(Wsec + kk1 * Hh))[c41];
    float4 pf2 = ((const float4*)(Wsec + kk2 * Hh))[c42];
    float4 pf3 = ((const float4*)(Wsec + kk3 * Hh))[c43];
    {
        float4* dst = (float4*)wbuf;
        dst[kk0 * 64 + c40] = pf0;
        dst[kk1 * 64 + c41] = pf1;
        dst[kk2 * 64 + c42] = pf2;
        dst[kk3 * 64 + c43] = pf3;
    }
    __syncthreads();

    u64 acc[8][4] = {};

    #pragma unroll 1
    for (int kc = 0; kc < 16; kc++) {
        const int buf = kc & 1;
        if (kc < 15) {
            const float* Wn = Wsec + (kc + 1) * SCH * Hh;
            pf0 = ((const float4*)(Wn + kk0 * Hh))[c40];
            pf1 = ((const float4*)(Wn + kk1 * Hh))[c41];
            pf2 = ((const float4*)(Wn + kk2 * Hh))[c42];
            pf3 = ((const float4*)(Wn + kk3 * Hh))[c43];
        }

        const float* xp = xs + (kc * SCH) * SXST + (ty << 4);
        const float* wp = wbuf + buf * (SCH * 256) + (tx << 2);

        #pragma unroll
        for (int k = 0; k < SCH; k++) {
            float4 wv = *(const float4*)(wp + (k << 8));
            u64 e0 = dup2(wv.x), e1 = dup2(wv.y), e2 = dup2(wv.z), e3 = dup2(wv.w);
            const u64* ap = (const u64*)(xp + k * SXST);
            ulonglong2 p0 = *(const ulonglong2*)(ap);
            ulonglong2 p1 = *(const ulonglong2*)(ap + 2);
            ulonglong2 p2 = *(const ulonglong2*)(ap + 4);
            ulonglong2 p3 = *(const ulonglong2*)(ap + 6);
            u64 r0 = p0.x, r1 = p0.y, r2 = p1.x, r3 = p1.y;
            u64 r4 = p2.x, r5 = p2.y, r6 = p3.x, r7 = p3.y;
            fma2(acc[0][0], r0, e0); fma2(acc[0][1], r0, e1);
            fma2(acc[0][2], r0, e2); fma2(acc[0][3], r0, e3);
            fma2(acc[1][0], r1, e0); fma2(acc[1][1], r1, e1);
            fma2(acc[1][2], r1, e2); fma2(acc[1][3], r1, e3);
            fma2(acc[2][0], r2, e0); fma2(acc[2][1], r2, e1);
            fma2(acc[2][2], r2, e2); fma2(acc[2][3], r2, e3);
            fma2(acc[3][0], r3, e0); fma2(acc[3][1], r3, e1);
            fma2(acc[3][2], r3, e2); fma2(acc[3][3], r3, e3);
            fma2(acc[4][0], r4, e0); fma2(acc[4][1], r4, e1);
            fma2(acc[4][2], r4, e2); fma2(acc[4][3], r4, e3);
            fma2(acc[5][0], r5, e0); fma2(acc[5][1], r5, e1);
            fma2(acc[5][2], r5, e2); fma2(acc[5][3], r5, e3);
            fma2(acc[6][0], r6, e0); fma2(acc[6][1], r6, e1);
            fma2(acc[6][2], r6, e2); fma2(acc[6][3], r6, e3);
            fma2(acc[7][0], r7, e0); fma2(acc[7][1], r7, e1);
            fma2(acc[7][2], r7, e2); fma2(acc[7][3], r7, e3);
        }

        if (kc < 15) {
            float4* dst = (float4*)(wbuf + (buf ^ 1) * (SCH * 256));
            dst[kk0 * 64 + c40] = pf0;
            dst[kk1 * 64 + c41] = pf1;
            dst[kk2 * 64 + c42] = pf2;
            dst[kk3 * 64 + c43] = pf3;
        }
        __syncthreads();
    }

    float scacc[16];
    #pragma unroll
    for (int i = 0; i < 16; i++) scacc[i] = 0.f;
    #pragma unroll
    for (int rp = 0; rp < 8; rp++) {
        #pragma unroll
        for (int c = 0; c < 4; c++) {
            float lo, hi; unpack2(lo, hi, acc[rp][c]);
            int cb = (tx << 2) + c;
            float h0 = lo + bc[cb];
            if (h0 > 0.f) scacc[2 * rp]     = fmaf(h0, wpc[cb], scacc[2 * rp]);
            float h1 = hi + bc[cb];
            if (h1 > 0.f) scacc[2 * rp + 1] = fmaf(h1, wpc[cb], scacc[2 * rp + 1]);
        }
    }

    #pragma unroll
    for (int i = 0; i < 16; i++) red[((ty << 4) + i) * 65 + tx] = scacc[i];
    __syncthreads();
    if (tid < 64) {
        float ssum = bpred[0] + sScore[tid];
        const float* rp = red + tid * 65;
        #pragma unroll
        for (int t = 0; t < 64; t++) ssum += rp[t];
        float p = 1.f / (1.f + expf(-ssum));
        out[b * KTOP + k0 + tid] = p * sMask[tid];
    }
}

// ---------------- launch ----------------
extern "C" void kernel_launch(void* const* d_in, const int* in_sizes, int n_in,
                              void* d_out, int out_size) {
    const float* inputs   = (const float*)d_in[0];
    const int*   in_mask  = (const int*)  d_in[1];
    const float* tie      = (const float*)d_in[2];
    const float* W_start  = (const float*)d_in[3];
    const float* b_start  = (const float*)d_in[4];
    const float* W_end    = (const float*)d_in[5];
    const float* b_end    = (const float*)d_in[6];
    const float* W_s1     = (const float*)d_in[7];
    const float* b_s1     = (const float*)d_in[8];
    const float* W_s2     = (const float*)d_in[9];
    const float* b_s2     = (const float*)d_in[10];
    const float* W_inj    = (const float*)d_in[11];
    const float* b_inj    = (const float*)d_in[12];
    const float* W_sec    = (const float*)d_in[13];
    const float* b_sec    = (const float*)d_in[14];
    const float* W_pred   = (const float*)d_in[15];
    const float* b_pred   = (const float*)d_in[16];
    float* out = (float*)d_out;

    cudaFuncSetAttribute(scorer_kernel, cudaFuncAttributeMaxDynamicSharedMemorySize, SC_SMEM_BYTES);
    cudaFuncSetAttribute(head_kernel,   cudaFuncAttributeMaxDynamicSharedMemorySize, SC_SMEM_BYTES);

    build_span_idx_kernel<<<(NSPANS + 255) / 256, 256>>>();
    proj_kernel<<<dim3(Hh / 64, (Bb * Tt) / 128, 2), 256>>>(inputs, W_start, b_start, W_end, b_end);
    inj_kernel<<<Bb, 256>>>(tie, W_inj, b_inj);
    scorer_kernel<<<dim3(NSPANS / 64, Bb), 256, SC_SMEM_BYTES>>>(W_s1, b_s1, W_s2, b_s2);
    topk_kernel<<<Bb, 256>>>(in_mask);
    head_kernel<<<dim3(KTOP / 64, Bb), 256, SC_SMEM_BYTES>>>(W_sec, b_sec, W_pred, b_pred, in_mask, out);
}

// round 14
// speedup vs baseline: 1.4102x; 1.0040x over previous
#include <cuda_runtime.h>
#include <math.h>

#define Bb      64
#define Tt      128
#define Dd      768
#define Hh      256
#define NSPANS  8256
#define KTOP    256
#define XST     68          // proj w stride
#define RST     132         // proj xs row-stride
#define SXST    68          // scorer/head xs row-stride (64 rows + pad, 16B-aligned)
#define SCH     16          // k-chunk size (16 chunks, double-buffered)
#define PCH     32          // proj k-chunk size

typedef unsigned long long u64;

// ---------------- packed fp32x2 helpers (sm_103a FFMA2 path) ----------------
__device__ __forceinline__ u64 dup2(float a) {
    u64 r; asm("mov.b64 %0, {%1, %2};" : "=l"(r) : "f"(a), "f"(a)); return r;
}
__device__ __forceinline__ void fma2(u64& acc, u64 a, u64 b) {
    asm("fma.rn.f32x2 %0, %1, %2, %0;" : "+l"(acc) : "l"(a), "l"(b));
}
__device__ __forceinline__ void unpack2(float& lo, float& hi, u64 v) {
    asm("mov.b64 {%0, %1}, %2;" : "=f"(lo), "=f"(hi) : "l"(v));
}

// ---------------- device scratch ----------------
__device__ float g_A[Bb*Tt*Hh];
__device__ float g_E[Bb*Tt*Hh];
__device__ float g_scores[Bb*NSPANS];
__device__ float g_inj[Bb*Hh];
__device__ int   g_topidx[Bb*KTOP];
__device__ float g_topscore[Bb*KTOP];
__device__ int   g_sarr[NSPANS];
__device__ int   g_earr[NSPANS];

// ---------------- span index decode ----------------
__global__ void build_span_idx_kernel() {
    int n = blockIdx.x * blockDim.x + threadIdx.x;
    if (n >= NSPANS) return;
    int s = 0, off = 0;
    while (n >= off + (Tt - s)) { off += (Tt - s); s++; }
    g_sarr[n] = s;
    g_earr[n] = s + (n - off);
}

// ---------------- projections: X[8192,768]@W[768,256]+b, double-buffered ----------------
// smem: xs[2][PCH][RST] + wsm[2][PCH][XST]
__global__ __launch_bounds__(256)
void proj_kernel(const float* __restrict__ X,
                 const float* __restrict__ Wst, const float* __restrict__ bst,
                 const float* __restrict__ Wen, const float* __restrict__ ben) {
    const float* W    = blockIdx.z ? Wen : Wst;
    const float* bias = blockIdx.z ? ben : bst;
    float*       Out  = blockIdx.z ? g_E : g_A;

    __shared__ float xs[2][PCH * RST];
    __shared__ float wsm[2][PCH * XST];

    const int row0 = blockIdx.y * 128;
    const int col0 = blockIdx.x * 64;
    const int tid  = threadIdx.x;
    const int tx   = tid & 15, ty = tid >> 4;

    // staging coords
    // X: 4 float4 along k per thread; kq = tid&7 (8 quads = 32 k), rX = tid>>3 (+32i)
    const int kq = tid & 7;
    const int rX = tid >> 3;
    // W: 2 float4 along c per thread; cq = tid&15 (16 quads = 64 c), kW = tid>>4 (+16)
    const int cq = tid & 15;
    const int kW = tid >> 4;

    const float* Xb = X + (u64)row0 * Dd + 4 * kq;
    const float* Wb = W + (u64)0 * Hh + col0 + 4 * cq;

    // prefetch chunk 0
    float4 px0 = *(const float4*)(Xb + (u64)(rX)      * Dd);
    float4 px1 = *(const float4*)(Xb + (u64)(rX + 32) * Dd);
    float4 px2 = *(const float4*)(Xb + (u64)(rX + 64) * Dd);
    float4 px3 = *(const float4*)(Xb + (u64)(rX + 96) * Dd);
    float4 pw0 = *(const float4*)(Wb + (u64)kW        * Hh);
    float4 pw1 = *(const float4*)(Wb + (u64)(kW + 16) * Hh);

    // store chunk 0 into buffer 0
    {
        float* xd = xs[0];
        xd[(4*kq+0) * RST + rX] = px0.x; xd[(4*kq+1) * RST + rX] = px0.y;
        xd[(4*kq+2) * RST + rX] = px0.z; xd[(4*kq+3) * RST + rX] = px0.w;
        xd[(4*kq+0) * RST + rX+32] = px1.x; xd[(4*kq+1) * RST + rX+32] = px1.y;
        xd[(4*kq+2) * RST + rX+32] = px1.z; xd[(4*kq+3) * RST + rX+32] = px1.w;
        xd[(4*kq+0) * RST + rX+64] = px2.x; xd[(4*kq+1) * RST + rX+64] = px2.y;
        xd[(4*kq+2) * RST + rX+64] = px2.z; xd[(4*kq+3) * RST + rX+64] = px2.w;
        xd[(4*kq+0) * RST + rX+96] = px3.x; xd[(4*kq+1) * RST + rX+96] = px3.y;
        xd[(4*kq+2) * RST + rX+96] = px3.z; xd[(4*kq+3) * RST + rX+96] = px3.w;
        *(float4*)(wsm[0] + kW * XST + 4 * cq)        = pw0;
        *(float4*)(wsm[0] + (kW + 16) * XST + 4 * cq) = pw1;
    }
    __syncthreads();

    u64 acc[4][4] = {};   // [rowpair][col]

    #pragma unroll 1
    for (int kc = 0; kc < Dd / PCH; kc++) {
        const int buf = kc & 1;
        if (kc < Dd / PCH - 1) {
            const float* Xn = Xb + (kc + 1) * PCH;
            const float* Wn = Wb + (u64)(kc + 1) * PCH * Hh;
            px0 = *(const float4*)(Xn + (u64)(rX)      * Dd);
            px1 = *(const float4*)(Xn + (u64)(rX + 32) * Dd);
            px2 = *(const float4*)(Xn + (u64)(rX + 64) * Dd);
            px3 = *(const float4*)(Xn + (u64)(rX + 96) * Dd);
            pw0 = *(const float4*)(Wn + (u64)kW        * Hh);
            pw1 = *(const float4*)(Wn + (u64)(kW + 16) * Hh);
        }

        const float* xp = xs[buf] + (ty << 3);
        const float* wp = wsm[buf] + (tx << 2);
        #pragma unroll 8
        for (int k = 0; k < PCH; k++) {
            float4 wv = *(const float4*)(wp + k * XST);
            u64 e0 = dup2(wv.x), e1 = dup2(wv.y), e2 = dup2(wv.z), e3 = dup2(wv.w);
            ulonglong2 p0 = *(const ulonglong2*)(xp + k * RST);
            ulonglong2 p1 = *(const ulonglong2*)(xp + k * RST + 4);
            u64 r0 = p0.x, r1 = p0.y, r2 = p1.x, r3 = p1.y;
            fma2(acc[0][0], r0, e0); fma2(acc[0][1], r0, e1);
            fma2(acc[0][2], r0, e2); fma2(acc[0][3], r0, e3);
            fma2(acc[1][0], r1, e0); fma2(acc[1][1], r1, e1);
            fma2(acc[1][2], r1, e2); fma2(acc[1][3], r1, e3);
            fma2(acc[2][0], r2, e0); fma2(acc[2][1], r2, e1);
            fma2(acc[2][2], r2, e2); fma2(acc[2][3], r2, e3);
            fma2(acc[3][0], r3, e0); fma2(acc[3][1], r3, e1);
            fma2(acc[3][2], r3, e2); fma2(acc[3][3], r3, e3);
        }

        if (kc < Dd / PCH - 1) {
            const int nb = buf ^ 1;
            float* xd = xs[nb];
            xd[(4*kq+0) * RST + rX] = px0.x; xd[(4*kq+1) * RST + rX] = px0.y;
            xd[(4*kq+2) * RST + rX] = px0.z; xd[(4*kq+3) * RST + rX] = px0.w;
            xd[(4*kq+0) * RST + rX+32] = px1.x; xd[(4*kq+1) * RST + rX+32] = px1.y;
            xd[(4*kq+2) * RST + rX+32] = px1.z; xd[(4*kq+3) * RST + rX+32] = px1.w;
            xd[(4*kq+0) * RST + rX+64] = px2.x; xd[(4*kq+1) * RST + rX+64] = px2.y;
            xd[(4*kq+2) * RST + rX+64] = px2.z; xd[(4*kq+3) * RST + rX+64] = px2.w;
            xd[(4*kq+0) * RST + rX+96] = px3.x; xd[(4*kq+1) * RST + rX+96] = px3.y;
            xd[(4*kq+2) * RST + rX+96] = px3.z; xd[(4*kq+3) * RST + rX+96] = px3.w;
            *(float4*)(wsm[nb] + kW * XST + 4 * cq)        = pw0;
            *(float4*)(wsm[nb] + (kW + 16) * XST + 4 * cq) = pw1;
        }
        __syncthreads();
    }

    #pragma unroll
    for (int rp = 0; rp < 4; rp++) {
        int row = row0 + (ty << 3) + 2 * rp;
        #pragma unroll
        for (int c = 0; c < 4; c++) {
            float lo, hi; unpack2(lo, hi, acc[rp][c]);
            int col = col0 + (tx << 2) + c;
            Out[row * Hh + col]       = lo + bias[col];
            Out[(row + 1) * Hh + col] = hi + bias[col];
        }
    }
}

// ---------------- injection projection ----------------
__global__ void inj_kernel(const float* __restrict__ tie,
                           const float* __restrict__ Winj, const float* __restrict__ binj) {
    int b = blockIdx.x;
    int j = threadIdx.x;
    __shared__ float t[128];
    if (j < 128) t[j] = tie[b * 128 + j];
    __syncthreads();
    float acc = binj[j];
    #pragma unroll 8
    for (int k = 0; k < 128; k++) acc = fmaf(t[k], Winj[k * Hh + j], acc);
    g_inj[b * Hh + j] = acc;
}

// ---------------- shared smem layout for scorer & head ----------------
#define SC_XS_FLOATS   (256 * SXST)
#define SC_WB_OFF      SC_XS_FLOATS
#define SC_BIAS_OFF    (SC_WB_OFF + 2 * SCH * 256)
#define SC_W2_OFF      (SC_BIAS_OFF + 256)
#define SC_SMEM_FLOATS (SC_W2_OFF + 256)
static const int SC_SMEM_BYTES = SC_SMEM_FLOATS * 4;   // 104,448 B -> 2 CTAs/SM

// ---------------- fused span scorer (round-12, unchanged) ----------------
__global__ __launch_bounds__(256, 2)
void scorer_kernel(const float* __restrict__ Ws1, const float* __restrict__ bs1,
                   const float* __restrict__ Ws2, const float* __restrict__ bs2) {
    extern __shared__ float sm[];
    float* xs   = sm;
    float* wbuf = sm + SC_WB_OFF;
    float* bs1c = sm + SC_BIAS_OFF;
    float* w2c  = sm + SC_W2_OFF;
    float* red  = wbuf;
    __shared__ int sS[64], sE[64];

    const int b   = blockIdx.y;
    const int n0  = blockIdx.x * 64;
    const int tid = threadIdx.x;
    const int tx  = tid & 63;
    const int ty  = tid >> 6;

    if (tid < 64) {
        sS[tid] = g_sarr[n0 + tid]; sE[tid] = g_earr[n0 + tid];
    }
    bs1c[tid] = bs1[tid];
    w2c[tid]  = Ws2[tid];
    __syncthreads();

    {
        const float* Ab = g_A + b * Tt * Hh + tid;
        const float* Eb = g_E + b * Tt * Hh + tid;
        float* xp = xs + tid * SXST;
        #pragma unroll 4
        for (int r = 0; r < 64; r++) {
            float v = Ab[sS[r] * Hh] + Eb[sE[r] * Hh];
            xp[r] = v > 0.f ? v : 0.f;
        }
    }

    const int kk0 = tid >> 6,          c40 = tid & 63;
    const int kk1 = (tid + 256) >> 6,  c41 = tid & 63;
    const int kk2 = (tid + 512) >> 6,  c42 = tid & 63;
    const int kk3 = (tid + 768) >> 6,  c43 = tid & 63;

    float4 pf0 = ((const float4*)(Ws1 + kk0 * Hh))[c40];
    float4 pf1 = ((const float4*)(Ws1 + kk1 * Hh))[c41];
    float4 pf2 = ((const float4*)(Ws1 + kk2 * Hh))[c42];
    float4 pf3 = ((const float4*)(Ws1 + kk3 * Hh))[c43];
    {
        float4* dst = (float4*)wbuf;
        dst[kk0 * 64 + c40] = pf0;
        dst[kk1 * 64 + c41] = pf1;
        dst[kk2 * 64 + c42] = pf2;
        dst[kk3 * 64 + c43] = pf3;
    }
    __syncthreads();

    u64 acc[8][4] = {};

    #pragma unroll 1
    for (int kc = 0; kc < 16; kc++) {
        const int buf = kc & 1;
        if (kc < 15) {
            const float* Wn = Ws1 + (kc + 1) * SCH * Hh;
            pf0 = ((const float4*)(Wn + kk0 * Hh))[c40];
            pf1 = ((const float4*)(Wn + kk1 * Hh))[c41];
            pf2 = ((const float4*)(Wn + kk2 * Hh))[c42];
            pf3 = ((const float4*)(Wn + kk3 * Hh))[c43];
        }

        const float* xp = xs + (kc * SCH) * SXST + (ty << 4);
        const float* wp = wbuf + buf * (SCH * 256) + (tx << 2);

        #pragma unroll
        for (int k = 0; k < SCH; k++) {
            float4 wv = *(const float4*)(wp + (k << 8));
            u64 e0 = dup2(wv.x), e1 = dup2(wv.y), e2 = dup2(wv.z), e3 = dup2(wv.w);
            const u64* ap = (const u64*)(xp + k * SXST);
            ulonglong2 p0 = *(const ulonglong2*)(ap);
            ulonglong2 p1 = *(const ulonglong2*)(ap + 2);
            ulonglong2 p2 = *(const ulonglong2*)(ap + 4);
            ulonglong2 p3 = *(const ulonglong2*)(ap + 6);
            u64 r0 = p0.x, r1 = p0.y, r2 = p1.x, r3 = p1.y;
            u64 r4 = p2.x, r5 = p2.y, r6 = p3.x, r7 = p3.y;
            fma2(acc[0][0], r0, e0); fma2(acc[0][1], r0, e1);
            fma2(acc[0][2], r0, e2); fma2(acc[0][3], r0, e3);
            fma2(acc[1][0], r1, e0); fma2(acc[1][1], r1, e1);
            fma2(acc[1][2], r1, e2); fma2(acc[1][3], r1, e3);
            fma2(acc[2][0], r2, e0); fma2(acc[2][1], r2, e1);
            fma2(acc[2][2], r2, e2); fma2(acc[2][3], r2, e3);
            fma2(acc[3][0], r3, e0); fma2(acc[3][1], r3, e1);
            fma2(acc[3][2], r3, e2); fma2(acc[3][3], r3, e3);
            fma2(acc[4][0], r4, e0); fma2(acc[4][1], r4, e1);
            fma2(acc[4][2], r4, e2); fma2(acc[4][3], r4, e3);
            fma2(acc[5][0], r5, e0); fma2(acc[5][1], r5, e1);
            fma2(acc[5][2], r5, e2); fma2(acc[5][3], r5, e3);
            fma2(acc[6][0], r6, e0); fma2(acc[6][1], r6, e1);
            fma2(acc[6][2], r6, e2); fma2(acc[6][3], r6, e3);
            fma2(acc[7][0], r7, e0); fma2(acc[7][1], r7, e1);
            fma2(acc[7][2], r7, e2); fma2(acc[7][3], r7, e3);
        }

        if (kc < 15) {
            float4* dst = (float4*)(wbuf + (buf ^ 1) * (SCH * 256));
            dst[kk0 * 64 + c40] = pf0;
            dst[kk1 * 64 + c41] = pf1;
            dst[kk2 * 64 + c42] = pf2;
            dst[kk3 * 64 + c43] = pf3;
        }
        __syncthreads();
    }

    float scacc[16];
    #pragma unroll
    for (int i = 0; i < 16; i++) scacc[i] = 0.f;
    #pragma unroll
    for (int rp = 0; rp < 8; rp++) {
        #pragma unroll
        for (int c = 0; c < 4; c++) {
            float lo, hi; unpack2(lo, hi, acc[rp][c]);
            int cb = (tx << 2) + c;
            float h0 = lo + bs1c[cb];
            if (h0 > 0.f) scacc[2 * rp]     = fmaf(h0, w2c[cb], scacc[2 * rp]);
            float h1 = hi + bs1c[cb];
            if (h1 > 0.f) scacc[2 * rp + 1] = fmaf(h1, w2c[cb], scacc[2 * rp + 1]);
        }
    }

    #pragma unroll
    for (int i = 0; i < 16; i++) red[((ty << 4) + i) * 65 + tx] = scacc[i];
    __syncthreads();
    if (tid < 64) {
        float ssum = bs2[0];
        const float* rp = red + tid * 65;
        #pragma unroll
        for (int t = 0; t < 64; t++) ssum += rp[t];
        g_scores[b * NSPANS + n0 + tid] = ssum;
    }
}

// ---------------- block inclusive scan (256 threads) ----------------
__device__ __forceinline__ int block_incl_scan(int v, int tid, int* wsums) {
    __syncthreads();
    int lane = tid & 31, wid = tid >> 5;
    #pragma unroll
    for (int o = 1; o < 32; o <<= 1) {
        int n = __shfl_up_sync(0xffffffffu, v, o);
        if (lane >= o) v += n;
    }
    if (lane == 31) wsums[wid] = v;
    __syncthreads();
    if (tid == 0) {
        int s = 0;
        #pragma unroll
        for (int w = 0; w < 8; w++) { int x = wsums[w]; wsums[w] = s; s += x; }
    }
    __syncthreads();
    return v + wsums[wid];
}

// ---------------- per-batch radix top-k, fully parallel scans ----------------
__global__ void topk_kernel(const int* __restrict__ mask) {
    const int b   = blockIdx.x;
    const int tid = threadIdx.x;
    __shared__ unsigned keys[NSPANS];
    __shared__ int hist[256];
    __shared__ unsigned sh_prefix;
    __shared__ int sh_kk;
    __shared__ int wsums[8];

    const int* mb = mask + b * Tt;
    for (int i = tid; i < NSPANS; i += 256) {
        int s = g_sarr[i], e = g_earr[i];
        float v = (mb[s] != 0 && mb[e] != 0) ? g_scores[b * NSPANS + i]
                                             : __int_as_float(0xff800000);
        unsigned u = __float_as_uint(v);
        keys[i] = (u & 0x80000000u) ? ~u : (u | 0x80000000u);
    }

    unsigned prefix = 0;
    int kk = KTOP;
    for (int level = 3; level >= 0; level--) {
        hist[tid] = 0;
        __syncthreads();
        const unsigned himask = (level == 3) ? 0u : (0xFFFFFFFFu << ((level + 1) * 8));
        for (int i = tid; i < NSPANS; i += 256) {
            unsigned kv = keys[i];
            if ((kv & himask) == (prefix & himask))
                atomicAdd(&hist[(kv >> (level * 8)) & 255], 1);
        }
        __syncthreads();
        int bucket = 255 - tid;
        int v = hist[bucket];
        int S = block_incl_scan(v, tid, wsums);
        if (S >= kk && S - v < kk) {
            sh_prefix = prefix | ((unsigned)bucket << (level * 8));
            sh_kk = kk - (S - v);
        }
        __syncthreads();
        prefix = sh_prefix;
        kk = sh_kk;
        __syncthreads();
    }

    const unsigned Kstar = prefix;
    const int CH = (NSPANS + 255) / 256;
    int lo = tid * CH; if (lo > NSPANS) lo = NSPANS;
    int hi = lo + CH;  if (hi > NSPANS) hi = NSPANS;

    int cgt = 0, ceq = 0;
    for (int i = lo; i < hi; i++) {
        unsigned kv = keys[i];
        cgt += (kv > Kstar);
        ceq += (kv == Kstar);
    }
    int Sg = block_incl_scan(cgt, tid, wsums);
    int Se = block_incl_scan(ceq, tid, wsums);
    int gtb = Sg - cgt, eqb = Se - ceq;

    for (int i = lo; i < hi; i++) {
        unsigned kv = keys[i];
        bool isgt = (kv > Kstar);
        bool iseq = (kv == Kstar);
        if (isgt || (iseq && eqb < kk)) {
            int eqt = eqb < kk ? eqb : kk;
            int pos = gtb + eqt;
            unsigned u = (kv & 0x80000000u) ? (kv & 0x7FFFFFFFu) : ~kv;
            g_topidx[b * KTOP + pos]   = i;
            g_topscore[b * KTOP + pos] = __uint_as_float(u);
        }
        gtb += isgt;
        eqb += iseq;
    }
}

// ---------------- fused head: scorer-clone ----------------
__global__ __launch_bounds__(256, 2)
void head_kernel(const float* __restrict__ Wsec, const float* __restrict__ bsec,
                 const float* __restrict__ Wpred, const float* __restrict__ bpred,
                 const int* __restrict__ mask, float* __restrict__ out) {
    extern __shared__ float sm[];
    float* xs   = sm;
    float* wbuf = sm + SC_WB_OFF;
    float* bc   = sm + SC_BIAS_OFF;
    float* wpc  = sm + SC_W2_OFF;
    float* red  = wbuf;
    __shared__ int sS[64], sE[64];
    __shared__ float sMask[64], sScore[64];

    const int b   = blockIdx.y;
    const int k0  = blockIdx.x * 64;
    const int tid = threadIdx.x;
    const int tx  = tid & 63;
    const int ty  = tid >> 6;

    if (tid < 64) {
        int n = g_topidx[b * KTOP + k0 + tid];
        int s = g_sarr[n], e = g_earr[n];
        sS[tid] = s; sE[tid] = e;
        sMask[tid] = (mask[b * Tt + s] != 0 && mask[b * Tt + e] != 0) ? 1.f : 0.f;
        float sc = g_topscore[b * KTOP + k0 + tid];
        sScore[tid] = isinf(sc) ? -1.f : sc;
    }
    bc[tid]  = bsec[tid] + g_inj[b * Hh + tid];
    wpc[tid] = Wpred[tid];
    __syncthreads();

    {
        const float* Ab = g_A + b * Tt * Hh + tid;
        const float* Eb = g_E + b * Tt * Hh + tid;
        float* xp = xs + tid * SXST;
        #pragma unroll 4
        for (int r = 0; r < 64; r++)
            xp[r] = Ab[sS[r] * Hh] + Eb[sE[r] * Hh];
    }

    const int kk0 = tid >> 6,          c40 = tid & 63;
    const int kk1 = (tid + 256) >> 6,  c41 = tid & 63;
    const int kk2 = (tid + 512) >> 6,  c42 = tid & 63;
    const int kk3 = (tid + 768) >> 6,  c43 = tid & 63;

    float4 pf0 = ((const float4*)(Wsec + kk0 * Hh))[c40];
    float4 pf1 = ((const float4*)(Wsec + kk1 * Hh))[c41];
    float4 pf2 = ((const float4*)(Wsec + kk2 * Hh))[c42];
    float4 pf3 = ((const float4*)(Wsec + kk3 * Hh))[c43];
    {
        float4* dst = (float4*)wbuf;
        dst[kk0 * 64 + c40] = pf0;
        dst[kk1 * 64 + c41] = pf1;
        dst[kk2 * 64 + c42] = pf2;
        dst[kk3 * 64 + c43] = pf3;
    }
    __syncthreads();

    u64 acc[8][4] = {};

    #pragma unroll 1
    for (int kc = 0; kc < 16; kc++) {
        const int buf = kc & 1;
        if (kc < 15) {
            const float* Wn = Wsec + (kc + 1) * SCH * Hh;
            pf0 = ((const float4*)(Wn + kk0 * Hh))[c40];
            pf1 = ((const float4*)(Wn + kk1 * Hh))[c41];
            pf2 = ((const float4*)(Wn + kk2 * Hh))[c42];
            pf3 = ((const float4*)(Wn + kk3 * Hh))[c43];
        }

        const float* xp = xs + (kc * SCH) * SXST + (ty << 4);
        const float* wp = wbuf + buf * (SCH * 256) + (tx << 2);

        #pragma unroll
        for (int k = 0; k < SCH; k++) {
            float4 wv = *(const float4*)(wp + (k << 8));
            u64 e0 = dup2(wv.x), e1 = dup2(wv.y), e2 = dup2(wv.z), e3 = dup2(wv.w);
            const u64* ap = (const u64*)(xp + k * SXST);
            ulonglong2 p0 = *(const ulonglong2*)(ap);
            ulonglong2 p1 = *(const ulonglong2*)(ap + 2);
            ulonglong2 p2 = *(const ulonglong2*)(ap + 4);
            ulonglong2 p3 = *(const ulonglong2*)(ap + 6);
            u64 r0 = p0.x, r1 = p0.y, r2 = p1.x, r3 = p1.y;
            u64 r4 = p2.x, r5 = p2.y, r6 = p3.x, r7 = p3.y;
            fma2(acc[0][0], r0, e0); fma2(acc[0][1], r0, e1);
            fma2(acc[0][2], r0, e2); fma2(acc[0][3], r0, e3);
            fma2(acc[1][0], r1, e0); fma2(acc[1][1], r1, e1);
            fma2(acc[1][2], r1, e2); fma2(acc[1][3], r1, e3);
            fma2(acc[2][0], r2, e0); fma2(acc[2][1], r2, e1);
            fma2(acc[2][2], r2, e2); fma2(acc[2][3], r2, e3);
            fma2(acc[3][0], r3, e0); fma2(acc[3][1], r3, e1);
            fma2(acc[3][2], r3, e2); fma2(acc[3][3], r3, e3);
            fma2(acc[4][0], r4, e0); fma2(acc[4][1], r4, e1);
            fma2(acc[4][2], r4, e2); fma2(acc[4][3], r4, e3);
            fma2(acc[5][0], r5, e0); fma2(acc[5][1], r5, e1);
            fma2(acc[5][2], r5, e2); fma2(acc[5][3], r5, e3);
            fma2(acc[6][0], r6, e0); fma2(acc[6][1], r6, e1);
            fma2(acc[6][2], r6, e2); fma2(acc[6][3], r6, e3);
            fma2(acc[7][0], r7, e0); fma2(acc[7][1], r7, e1);
            fma2(acc[7][2], r7, e2); fma2(acc[7][3], r7, e3);
        }

        if (kc < 15) {
            float4* dst = (float4*)(wbuf + (buf ^ 1) * (SCH * 256));
            dst[kk0 * 64 + c40] = pf0;
            dst[kk1 * 64 + c41] = pf1;
            dst[kk2 * 64 + c42] = pf2;
            dst[kk3 * 64 + c43] = pf3;
        }
        __syncthreads();
    }

    float scacc[16];
    #pragma unroll
    for (int i = 0; i < 16; i++) scacc[i] = 0.f;
    #pragma unroll
    for (int rp = 0; rp < 8; rp++) {
        #pragma unroll
        for (int c = 0; c < 4; c++) {
            float lo, hi; unpack2(lo, hi, acc[rp][c]);
            int cb = (tx << 2) + c;
            float h0 = lo + bc[cb];
            if (h0 > 0.f) scacc[2 * rp]     = fmaf(h0, wpc[cb], scacc[2 * rp]);
            float h1 = hi + bc[cb];
            if (h1 > 0.f) scacc[2 * rp + 1] = fmaf(h1, wpc[cb], scacc[2 * rp + 1]);
        }
    }

    #pragma unroll
    for (int i = 0; i < 16; i++) red[((ty << 4) + i) * 65 + tx] = scacc[i];
    __syncthreads();
    if (tid < 64) {
        float ssum = bpred[0] + sScore[tid];
        const float* rp = red + tid * 65;
        #pragma unroll
        for (int t = 0; t < 64; t++) ssum += rp[t];
        float p = 1.f / (1.f + expf(-ssum));
        out[b * KTOP + k0 + tid] = p * sMask[tid];
    }
}

// ---------------- launch ----------------
extern "C" void kernel_launch(void* const* d_in, const int* in_sizes, int n_in,
                              void* d_out, int out_size) {
    const float* inputs   = (const float*)d_in[0];
    const int*   in_mask  = (const int*)  d_in[1];
    const float* tie      = (const float*)d_in[2];
    const float* W_start  = (const float*)d_in[3];
    const float* b_start  = (const float*)d_in[4];
    const float* W_end    = (const float*)d_in[5];
    const float* b_end    = (const float*)d_in[6];
    const float* W_s1     = (const float*)d_in[7];
    const float* b_s1     = (const float*)d_in[8];
    const float* W_s2     = (const float*)d_in[9];
    const float* b_s2     = (const float*)d_in[10];
    const float* W_inj    = (const float*)d_in[11];
    const float* b_inj    = (const float*)d_in[12];
    const float* W_sec    = (const float*)d_in[13];
    const float* b_sec    = (const float*)d_in[14];
    const float* W_pred   = (const float*)d_in[15];
    const float* b_pred   = (const float*)d_in[16];
    float* out = (float*)d_out;

    cudaFuncSetAttribute(scorer_kernel, cudaFuncAttributeMaxDynamicSharedMemorySize, SC_SMEM_BYTES);
    cudaFuncSetAttribute(head_kernel,   cudaFuncAttributeMaxDynamicSharedMemorySize, SC_SMEM_BYTES);

    build_span_idx_kernel<<<(NSPANS + 255) / 256, 256>>>();
    proj_kernel<<<dim3(Hh / 64, (Bb * Tt) / 128, 2), 256>>>(inputs, W_start, b_start, W_end, b_end);
    inj_kernel<<<Bb, 256>>>(tie, W_inj, b_inj);
    scorer_kernel<<<dim3(NSPANS / 64, Bb), 256, SC_SMEM_BYTES>>>(W_s1, b_s1, W_s2, b_s2);
    topk_kernel<<<Bb, 256>>>(in_mask);
    head_kernel<<<dim3(KTOP / 64, Bb), 256, SC_SMEM_BYTES>>>(W_sec, b_sec, W_pred, b_pred, in_mask, out);
}

// round 15
// speedup vs baseline: 1.4999x; 1.0636x over previous
#include <cuda_runtime.h>
#include <math.h>

#define Bb      64
#define Tt      128
#define Dd      768
#define Hh      256
#define NSPANS  8256
#define KTOP    256
#define XST     68          // proj w stride
#define RST     132         // proj xs row-stride
#define SXST    68          // scorer/head xs row-stride (64 rows + pad, 16B-aligned)
#define SCH     16          // head k-chunk size
#define PCH     32          // proj k-chunk size

typedef unsigned long long u64;

// ---------------- packed fp32x2 helpers (sm_103a FFMA2 path) ----------------
__device__ __forceinline__ u64 dup2(float a) {
    u64 r; asm("mov.b64 %0, {%1, %2};" : "=l"(r) : "f"(a), "f"(a)); return r;
}
__device__ __forceinline__ void fma2(u64& acc, u64 a, u64 b) {
    asm("fma.rn.f32x2 %0, %1, %2, %0;" : "+l"(acc) : "l"(a), "l"(b));
}
__device__ __forceinline__ void unpack2(float& lo, float& hi, u64 v) {
    asm("mov.b64 {%0, %1}, %2;" : "=f"(lo), "=f"(hi) : "l"(v));
}

// ---------------- device scratch ----------------
__device__ float g_A[Bb*Tt*Hh];
__device__ float g_E[Bb*Tt*Hh];
__device__ float g_scores[Bb*NSPANS];
__device__ float g_inj[Bb*Hh];
__device__ int   g_topidx[Bb*KTOP];
__device__ float g_topscore[Bb*KTOP];
__device__ int   g_sarr[NSPANS];
__device__ int   g_earr[NSPANS];

// ---------------- span index decode ----------------
__global__ void build_span_idx_kernel() {
    int n = blockIdx.x * blockDim.x + threadIdx.x;
    if (n >= NSPANS) return;
    int s = 0, off = 0;
    while (n >= off + (Tt - s)) { off += (Tt - s); s++; }
    g_sarr[n] = s;
    g_earr[n] = s + (n - off);
}

// ---------------- projections (round-14, unchanged) ----------------
__global__ __launch_bounds__(256)
void proj_kernel(const float* __restrict__ X,
                 const float* __restrict__ Wst, const float* __restrict__ bst,
                 const float* __restrict__ Wen, const float* __restrict__ ben) {
    const float* W    = blockIdx.z ? Wen : Wst;
    const float* bias = blockIdx.z ? ben : bst;
    float*       Out  = blockIdx.z ? g_E : g_A;

    __shared__ float xs[2][PCH * RST];
    __shared__ float wsm[2][PCH * XST];

    const int row0 = blockIdx.y * 128;
    const int col0 = blockIdx.x * 64;
    const int tid  = threadIdx.x;
    const int tx   = tid & 15, ty = tid >> 4;

    const int kq = tid & 7;
    const int rX = tid >> 3;
    const int cq = tid & 15;
    const int kW = tid >> 4;

    const float* Xb = X + (u64)row0 * Dd + 4 * kq;
    const float* Wb = W + col0 + 4 * cq;

    float4 px0 = *(const float4*)(Xb + (u64)(rX)      * Dd);
    float4 px1 = *(const float4*)(Xb + (u64)(rX + 32) * Dd);
    float4 px2 = *(const float4*)(Xb + (u64)(rX + 64) * Dd);
    float4 px3 = *(const float4*)(Xb + (u64)(rX + 96) * Dd);
    float4 pw0 = *(const float4*)(Wb + (u64)kW        * Hh);
    float4 pw1 = *(const float4*)(Wb + (u64)(kW + 16) * Hh);

    {
        float* xd = xs[0];
        xd[(4*kq+0) * RST + rX] = px0.x; xd[(4*kq+1) * RST + rX] = px0.y;
        xd[(4*kq+2) * RST + rX] = px0.z; xd[(4*kq+3) * RST + rX] = px0.w;
        xd[(4*kq+0) * RST + rX+32] = px1.x; xd[(4*kq+1) * RST + rX+32] = px1.y;
        xd[(4*kq+2) * RST + rX+32] = px1.z; xd[(4*kq+3) * RST + rX+32] = px1.w;
        xd[(4*kq+0) * RST + rX+64] = px2.x; xd[(4*kq+1) * RST + rX+64] = px2.y;
        xd[(4*kq+2) * RST + rX+64] = px2.z; xd[(4*kq+3) * RST + rX+64] = px2.w;
        xd[(4*kq+0) * RST + rX+96] = px3.x; xd[(4*kq+1) * RST + rX+96] = px3.y;
        xd[(4*kq+2) * RST + rX+96] = px3.z; xd[(4*kq+3) * RST + rX+96] = px3.w;
        *(float4*)(wsm[0] + kW * XST + 4 * cq)        = pw0;
        *(float4*)(wsm[0] + (kW + 16) * XST + 4 * cq) = pw1;
    }
    __syncthreads();

    u64 acc[4][4] = {};

    #pragma unroll 1
    for (int kc = 0; kc < Dd / PCH; kc++) {
        const int buf = kc & 1;
        if (kc < Dd / PCH - 1) {
            const float* Xn = Xb + (kc + 1) * PCH;
            const float* Wn = Wb + (u64)(kc + 1) * PCH * Hh;
            px0 = *(const float4*)(Xn + (u64)(rX)      * Dd);
            px1 = *(const float4*)(Xn + (u64)(rX + 32) * Dd);
            px2 = *(const float4*)(Xn + (u64)(rX + 64) * Dd);
            px3 = *(const float4*)(Xn + (u64)(rX + 96) * Dd);
            pw0 = *(const float4*)(Wn + (u64)kW        * Hh);
            pw1 = *(const float4*)(Wn + (u64)(kW + 16) * Hh);
        }

        const float* xp = xs[buf] + (ty << 3);
        const float* wp = wsm[buf] + (tx << 2);
        #pragma unroll 8
        for (int k = 0; k < PCH; k++) {
            float4 wv = *(const float4*)(wp + k * XST);
            u64 e0 = dup2(wv.x), e1 = dup2(wv.y), e2 = dup2(wv.z), e3 = dup2(wv.w);
            ulonglong2 p0 = *(const ulonglong2*)(xp + k * RST);
            ulonglong2 p1 = *(const ulonglong2*)(xp + k * RST + 4);
            u64 r0 = p0.x, r1 = p0.y, r2 = p1.x, r3 = p1.y;
            fma2(acc[0][0], r0, e0); fma2(acc[0][1], r0, e1);
            fma2(acc[0][2], r0, e2); fma2(acc[0][3], r0, e3);
            fma2(acc[1][0], r1, e0); fma2(acc[1][1], r1, e1);
            fma2(acc[1][2], r1, e2); fma2(acc[1][3], r1, e3);
            fma2(acc[2][0], r2, e0); fma2(acc[2][1], r2, e1);
            fma2(acc[2][2], r2, e2); fma2(acc[2][3], r2, e3);
            fma2(acc[3][0], r3, e0); fma2(acc[3][1], r3, e1);
            fma2(acc[3][2], r3, e2); fma2(acc[3][3], r3, e3);
        }

        if (kc < Dd / PCH - 1) {
            const int nb = buf ^ 1;
            float* xd = xs[nb];
            xd[(4*kq+0) * RST + rX] = px0.x; xd[(4*kq+1) * RST + rX] = px0.y;
            xd[(4*kq+2) * RST + rX] = px0.z; xd[(4*kq+3) * RST + rX] = px0.w;
            xd[(4*kq+0) * RST + rX+32] = px1.x; xd[(4*kq+1) * RST + rX+32] = px1.y;
            xd[(4*kq+2) * RST + rX+32] = px1.z; xd[(4*kq+3) * RST + rX+32] = px1.w;
            xd[(4*kq+0) * RST + rX+64] = px2.x; xd[(4*kq+1) * RST + rX+64] = px2.y;
            xd[(4*kq+2) * RST + rX+64] = px2.z; xd[(4*kq+3) * RST + rX+64] = px2.w;
            xd[(4*kq+0) * RST + rX+96] = px3.x; xd[(4*kq+1) * RST + rX+96] = px3.y;
            xd[(4*kq+2) * RST + rX+96] = px3.z; xd[(4*kq+3) * RST + rX+96] = px3.w;
            *(float4*)(wsm[nb] + kW * XST + 4 * cq)        = pw0;
            *(float4*)(wsm[nb] + (kW + 16) * XST + 4 * cq) = pw1;
        }
        __syncthreads();
    }

    #pragma unroll
    for (int rp = 0; rp < 4; rp++) {
        int row = row0 + (ty << 3) + 2 * rp;
        #pragma unroll
        for (int c = 0; c < 4; c++) {
            float lo, hi; unpack2(lo, hi, acc[rp][c]);
            int col = col0 + (tx << 2) + c;
            Out[row * Hh + col]       = lo + bias[col];
            Out[(row + 1) * Hh + col] = hi + bias[col];
        }
    }
}

// ---------------- injection projection ----------------
__global__ void inj_kernel(const float* __restrict__ tie,
                           const float* __restrict__ Winj, const float* __restrict__ binj) {
    int b = blockIdx.x;
    int j = threadIdx.x;
    __shared__ float t[128];
    if (j < 128) t[j] = tie[b * 128 + j];
    __syncthreads();
    float acc = binj[j];
    #pragma unroll 8
    for (int k = 0; k < 128; k++) acc = fmaf(t[k], Winj[k * Hh + j], acc);
    g_inj[b * Hh + j] = acc;
}

// ---------------- NEW scorer: direct-LDG weights, barrier-free mainloop ----------------
// smem floats: xs 256*SXST | bias 256 | w2 256 | red 64*65
#define SN_BIAS_OFF    (256 * SXST)
#define SN_W2_OFF      (SN_BIAS_OFF + 256)
#define SN_RED_OFF     (SN_W2_OFF + 256)
#define SN_SMEM_FLOATS (SN_RED_OFF + 64 * 65)
static const int SN_SMEM_BYTES = SN_SMEM_FLOATS * 4;   // 88,320 B -> 2 CTAs/SM

#define SC_BODY(WV, AP)                                                    \
    {                                                                      \
        u64 e0 = dup2((WV).x), e1 = dup2((WV).y),                          \
            e2 = dup2((WV).z), e3 = dup2((WV).w);                          \
        ulonglong2 p0 = *(const ulonglong2*)(AP);                          \
        ulonglong2 p1 = *(const ulonglong2*)((AP) + 2);                    \
        ulonglong2 p2 = *(const ulonglong2*)((AP) + 4);                    \
        ulonglong2 p3 = *(const ulonglong2*)((AP) + 6);                    \
        u64 r0 = p0.x, r1 = p0.y, r2 = p1.x, r3 = p1.y;                    \
        u64 r4 = p2.x, r5 = p2.y, r6 = p3.x, r7 = p3.y;                    \
        fma2(acc[0][0], r0, e0); fma2(acc[0][1], r0, e1);                  \
        fma2(acc[0][2], r0, e2); fma2(acc[0][3], r0, e3);                  \
        fma2(acc[1][0], r1, e0); fma2(acc[1][1], r1, e1);                  \
        fma2(acc[1][2], r1, e2); fma2(acc[1][3], r1, e3);                  \
        fma2(acc[2][0], r2, e0); fma2(acc[2][1], r2, e1);                  \
        fma2(acc[2][2], r2, e2); fma2(acc[2][3], r2, e3);                  \
        fma2(acc[3][0], r3, e0); fma2(acc[3][1], r3, e1);                  \
        fma2(acc[3][2], r3, e2); fma2(acc[3][3], r3, e3);                  \
        fma2(acc[4][0], r4, e0); fma2(acc[4][1], r4, e1);                  \
        fma2(acc[4][2], r4, e2); fma2(acc[4][3], r4, e3);                  \
        fma2(acc[5][0], r5, e0); fma2(acc[5][1], r5, e1);                  \
        fma2(acc[5][2], r5, e2); fma2(acc[5][3], r5, e3);                  \
        fma2(acc[6][0], r6, e0); fma2(acc[6][1], r6, e1);                  \
        fma2(acc[6][2], r6, e2); fma2(acc[6][3], r6, e3);                  \
        fma2(acc[7][0], r7, e0); fma2(acc[7][1], r7, e1);                  \
        fma2(acc[7][2], r7, e2); fma2(acc[7][3], r7, e3);                  \
    }

__global__ __launch_bounds__(256, 2)
void scorer_kernel(const float* __restrict__ Ws1, const float* __restrict__ bs1,
                   const float* __restrict__ Ws2, const float* __restrict__ bs2) {
    extern __shared__ float sm[];
    float* xs   = sm;                        // [k=256][r, stride SXST]
    float* bs1c = sm + SN_BIAS_OFF;          // 256
    float* w2c  = sm + SN_W2_OFF;            // 256
    float* red  = sm + SN_RED_OFF;           // [64][65]
    __shared__ int sS[64], sE[64];

    const int b   = blockIdx.y;
    const int n0  = blockIdx.x * 64;
    const int tid = threadIdx.x;
    const int tx  = tid & 63;        // 64 col-groups of 4
    const int ty  = tid >> 6;        // 4 row-groups of 16

    if (tid < 64) {
        sS[tid] = g_sarr[n0 + tid]; sE[tid] = g_earr[n0 + tid];
    }
    bs1c[tid] = bs1[tid];
    w2c[tid]  = Ws2[tid];
    __syncthreads();

    // fill xs[k][r] = relu(A[s_r][k] + E[e_r][k]); thread owns column k = tid
    {
        const float* Ab = g_A + b * Tt * Hh + tid;
        const float* Eb = g_E + b * Tt * Hh + tid;
        float* xp = xs + tid * SXST;
        #pragma unroll 4
        for (int r = 0; r < 64; r++) {
            float v = Ab[sS[r] * Hh] + Eb[sE[r] * Hh];
            xp[r] = v > 0.f ? v : 0.f;
        }
    }
    __syncthreads();   // the ONLY mainloop barrier

    // direct-LDG weight stream: thread reads W1[k][4tx..4tx+3] per k (coalesced 512B/warp)
    const float4* Wg = ((const float4*)Ws1) + tx;
    float4 pfa = Wg[0];
    float4 pfb = Wg[64];          // row 1

    const float* xp = xs + (ty << 4);
    u64 acc[8][4] = {};

    #pragma unroll 8
    for (int k = 0; k < 256; k++) {
        float4 wv;
        int kp = (k + 2) & 255;   // wraps to rows 0,1 at tail (loads unused, harmless)
        if (k & 1) { wv = pfb; pfb = Wg[kp << 6]; }
        else       { wv = pfa; pfa = Wg[kp << 6]; }
        const u64* ap = (const u64*)(xp + k * SXST);
        SC_BODY(wv, ap);
    }

    // layer-2 epilogue; acc[rp][c]: lo = row 2rp, hi = row 2rp+1, col = 4tx+c
    float scacc[16];
    #pragma unroll
    for (int i = 0; i < 16; i++) scacc[i] = 0.f;
    #pragma unroll
    for (int rp = 0; rp < 8; rp++) {
        #pragma unroll
        for (int c = 0; c < 4; c++) {
            float lo, hi; unpack2(lo, hi, acc[rp][c]);
            int cb = (tx << 2) + c;
            float h0 = lo + bs1c[cb];
            if (h0 > 0.f) scacc[2 * rp]     = fmaf(h0, w2c[cb], scacc[2 * rp]);
            float h1 = hi + bs1c[cb];
            if (h1 > 0.f) scacc[2 * rp + 1] = fmaf(h1, w2c[cb], scacc[2 * rp + 1]);
        }
    }

    #pragma unroll
    for (int i = 0; i < 16; i++) red[((ty << 4) + i) * 65 + tx] = scacc[i];
    __syncthreads();
    if (tid < 64) {
        float ssum = bs2[0];
        const float* rp = red + tid * 65;
        #pragma unroll
        for (int t = 0; t < 64; t++) ssum += rp[t];
        g_scores[b * NSPANS + n0 + tid] = ssum;
    }
}

// ---------------- block inclusive scan (256 threads) ----------------
__device__ __forceinline__ int block_incl_scan(int v, int tid, int* wsums) {
    __syncthreads();
    int lane = tid & 31, wid = tid >> 5;
    #pragma unroll
    for (int o = 1; o < 32; o <<= 1) {
        int n = __shfl_up_sync(0xffffffffu, v, o);
        if (lane >= o) v += n;
    }
    if (lane == 31) wsums[wid] = v;
    __syncthreads();
    if (tid == 0) {
        int s = 0;
        #pragma unroll
        for (int w = 0; w < 8; w++) { int x = wsums[w]; wsums[w] = s; s += x; }
    }
    __syncthreads();
    return v + wsums[wid];
}

// ---------------- per-batch radix top-k (round-13, unchanged) ----------------
__global__ void topk_kernel(const int* __restrict__ mask) {
    const int b   = blockIdx.x;
    const int tid = threadIdx.x;
    __shared__ unsigned keys[NSPANS];
    __shared__ int hist[256];
    __shared__ unsigned sh_prefix;
    __shared__ int sh_kk;
    __shared__ int wsums[8];

    const int* mb = mask + b * Tt;
    for (int i = tid; i < NSPANS; i += 256) {
        int s = g_sarr[i], e = g_earr[i];
        float v = (mb[s] != 0 && mb[e] != 0) ? g_scores[b * NSPANS + i]
                                             : __int_as_float(0xff800000);
        unsigned u = __float_as_uint(v);
        keys[i] = (u & 0x80000000u) ? ~u : (u | 0x80000000u);
    }

    unsigned prefix = 0;
    int kk = KTOP;
    for (int level = 3; level >= 0; level--) {
        hist[tid] = 0;
        __syncthreads();
        const unsigned himask = (level == 3) ? 0u : (0xFFFFFFFFu << ((level + 1) * 8));
        for (int i = tid; i < NSPANS; i += 256) {
            unsigned kv = keys[i];
            if ((kv & himask) == (prefix & himask))
                atomicAdd(&hist[(kv >> (level * 8)) & 255], 1);
        }
        __syncthreads();
        int bucket = 255 - tid;
        int v = hist[bucket];
        int S = block_incl_scan(v, tid, wsums);
        if (S >= kk && S - v < kk) {
            sh_prefix = prefix | ((unsigned)bucket << (level * 8));
            sh_kk = kk - (S - v);
        }
        __syncthreads();
        prefix = sh_prefix;
        kk = sh_kk;
        __syncthreads();
    }

    const unsigned Kstar = prefix;
    const int CH = (NSPANS + 255) / 256;
    int lo = tid * CH; if (lo > NSPANS) lo = NSPANS;
    int hi = lo + CH;  if (hi > NSPANS) hi = NSPANS;

    int cgt = 0, ceq = 0;
    for (int i = lo; i < hi; i++) {
        unsigned kv = keys[i];
        cgt += (kv > Kstar);
        ceq += (kv == Kstar);
    }
    int Sg = block_incl_scan(cgt, tid, wsums);
    int Se = block_incl_scan(ceq, tid, wsums);
    int gtb = Sg - cgt, eqb = Se - ceq;

    for (int i = lo; i < hi; i++) {
        unsigned kv = keys[i];
        bool isgt = (kv > Kstar);
        bool iseq = (kv == Kstar);
        if (isgt || (iseq && eqb < kk)) {
            int eqt = eqb < kk ? eqb : kk;
            int pos = gtb + eqt;
            unsigned u = (kv & 0x80000000u) ? (kv & 0x7FFFFFFFu) : ~kv;
            g_topidx[b * KTOP + pos]   = i;
            g_topscore[b * KTOP + pos] = __uint_as_float(u);
        }
        gtb += isgt;
        eqb += iseq;
    }
}

// ---------------- fused head (round-14 layout, unchanged) ----------------
#define SC_XS_FLOATS   (256 * SXST)
#define SC_WB_OFF      SC_XS_FLOATS
#define SC_BIAS_OFF    (SC_WB_OFF + 2 * SCH * 256)
#define SC_W2_OFF      (SC_BIAS_OFF + 256)
#define SC_SMEM_FLOATS (SC_W2_OFF + 256)
static const int SC_SMEM_BYTES = SC_SMEM_FLOATS * 4;

__global__ __launch_bounds__(256, 2)
void head_kernel(const float* __restrict__ Wsec, const float* __restrict__ bsec,
                 const float* __restrict__ Wpred, const float* __restrict__ bpred,
                 const int* __restrict__ mask, float* __restrict__ out) {
    extern __shared__ float sm[];
    float* xs   = sm;
    float* wbuf = sm + SC_WB_OFF;
    float* bc   = sm + SC_BIAS_OFF;
    float* wpc  = sm + SC_W2_OFF;
    float* red  = wbuf;
    __shared__ int sS[64], sE[64];
    __shared__ float sMask[64], sScore[64];

    const int b   = blockIdx.y;
    const int k0  = blockIdx.x * 64;
    const int tid = threadIdx.x;
    const int tx  = tid & 63;
    const int ty  = tid >> 6;

    if (tid < 64) {
        int n = g_topidx[b * KTOP + k0 + tid];
        int s = g_sarr[n], e = g_earr[n];
        sS[tid] = s; sE[tid] = e;
        sMask[tid] = (mask[b * Tt + s] != 0 && mask[b * Tt + e] != 0) ? 1.f : 0.f;
        float sc = g_topscore[b * KTOP + k0 + tid];
        sScore[tid] = isinf(sc) ? -1.f : sc;
    }
    bc[tid]  = bsec[tid] + g_inj[b * Hh + tid];
    wpc[tid] = Wpred[tid];
    __syncthreads();

    {
        const float* Ab = g_A + b * Tt * Hh + tid;
        const float* Eb = g_E + b * Tt * Hh + tid;
        float* xp = xs + tid * SXST;
        #pragma unroll 4
        for (int r = 0; r < 64; r++)
            xp[r] = Ab[sS[r] * Hh] + Eb[sE[r] * Hh];
    }

    const int kk0 = tid >> 6,          c40 = tid & 63;
    const int kk1 = (tid + 256) >> 6,  c41 = tid & 63;
    const int kk2 = (tid + 512) >> 6,  c42 = tid & 63;
    const int kk3 = (tid + 768) >> 6,  c43 = tid & 63;

    float4 pf0 = ((const float4*)(Wsec + kk0 * Hh))[c40];
    float4 pf1 = ((const float4*)(Wsec + kk1 * Hh))[c41];
    float4 pf2 = ((const float4*)(Wsec + kk2 * Hh))[c42];
    float4 pf3 = ((const float4*)(Wsec + kk3 * Hh))[c43];
    {
        float4* dst = (float4*)wbuf;
        dst[kk0 * 64 + c40] = pf0;
        dst[kk1 * 64 + c41] = pf1;
        dst[kk2 * 64 + c42] = pf2;
        dst[kk3 * 64 + c43] = pf3;
    }
    __syncthreads();

    u64 acc[8][4] = {};

    #pragma unroll 1
    for (int kc = 0; kc < 16; kc++) {
        const int buf = kc & 1;
        if (kc < 15) {
            const float* Wn = Wsec + (kc + 1) * SCH * Hh;
            pf0 = ((const float4*)(Wn + kk0 * Hh))[c40];
            pf1 = ((const float4*)(Wn + kk1 * Hh))[c41];
            pf2 = ((const float4*)(Wn + kk2 * Hh))[c42];
            pf3 = ((const float4*)(Wn + kk3 * Hh))[c43];
        }

        const float* xp = xs + (kc * SCH) * SXST + (ty << 4);
        const float* wp = wbuf + buf * (SCH * 256) + (tx << 2);

        #pragma unroll
        for (int k = 0; k < SCH; k++) {
            float4 wv = *(const float4*)(wp + (k << 8));
            const u64* ap = (const u64*)(xp + k * SXST);
            SC_BODY(wv, ap);
        }

        if (kc < 15) {
            float4* dst = (float4*)(wbuf + (buf ^ 1) * (SCH * 256));
            dst[kk0 * 64 + c40] = pf0;
            dst[kk1 * 64 + c41] = pf1;
            dst[kk2 * 64 + c42] = pf2;
            dst[kk3 * 64 + c43] = pf3;
        }
        __syncthreads();
    }

    float scacc[16];
    #pragma unroll
    for (int i = 0; i < 16; i++) scacc[i] = 0.f;
    #pragma unroll
    for (int rp = 0; rp < 8; rp++) {
        #pragma unroll
        for (int c = 0; c < 4; c++) {
            float lo, hi; unpack2(lo, hi, acc[rp][c]);
            int cb = (tx << 2) + c;
            float h0 = lo + bc[cb];
            if (h0 > 0.f) scacc[2 * rp]     = fmaf(h0, wpc[cb], scacc[2 * rp]);
            float h1 = hi + bc[cb];
            if (h1 > 0.f) scacc[2 * rp + 1] = fmaf(h1, wpc[cb], scacc[2 * rp + 1]);
        }
    }

    #pragma unroll
    for (int i = 0; i < 16; i++) red[((ty << 4) + i) * 65 + tx] = scacc[i];
    __syncthreads();
    if (tid < 64) {
        float ssum = bpred[0] + sScore[tid];
        const float* rp = red + tid * 65;
        #pragma unroll
        for (int t = 0; t < 64; t++) ssum += rp[t];
        float p = 1.f / (1.f + expf(-ssum));
        out[b * KTOP + k0 + tid] = p * sMask[tid];
    }
}

// ---------------- launch ----------------
extern "C" void kernel_launch(void* const* d_in, const int* in_sizes, int n_in,
                              void* d_out, int out_size) {
    const float* inputs   = (const float*)d_in[0];
    const int*   in_mask  = (const int*)  d_in[1];
    const float* tie      = (const float*)d_in[2];
    const float* W_start  = (const float*)d_in[3];
    const float* b_start  = (const float*)d_in[4];
    const float* W_end    = (const float*)d_in[5];
    const float* b_end    = (const float*)d_in[6];
    const float* W_s1     = (const float*)d_in[7];
    const float* b_s1     = (const float*)d_in[8];
    const float* W_s2     = (const float*)d_in[9];
    const float* b_s2     = (const float*)d_in[10];
    const float* W_inj    = (const float*)d_in[11];
    const float* b_inj    = (const float*)d_in[12];
    const float* W_sec    = (const float*)d_in[13];
    const float* b_sec    = (const float*)d_in[14];
    const float* W_pred   = (const float*)d_in[15];
    const float* b_pred   = (const float*)d_in[16];
    float* out = (float*)d_out;

    cudaFuncSetAttribute(scorer_kernel, cudaFuncAttributeMaxDynamicSharedMemorySize, SN_SMEM_BYTES);
    cudaFuncSetAttribute(head_kernel,   cudaFuncAttributeMaxDynamicSharedMemorySize, SC_SMEM_BYTES);

    build_span_idx_kernel<<<(NSPANS + 255) / 256, 256>>>();
    proj_kernel<<<dim3(Hh / 64, (Bb * Tt) / 128, 2), 256>>>(inputs, W_start, b_start, W_end, b_end);
    inj_kernel<<<Bb, 256>>>(tie, W_inj, b_inj);
    scorer_kernel<<<dim3(NSPANS / 64, Bb), 256, SN_SMEM_BYTES>>>(W_s1, b_s1, W_s2, b_s2);
    topk_kernel<<<Bb, 256>>>(in_mask);
    head_kernel<<<dim3(KTOP / 64, Bb), 256, SC_SMEM_BYTES>>>(W_sec, b_sec, W_pred, b_pred, in_mask, out);
}

// round 16
// speedup vs baseline: 1.4999x; 1.0000x over previous
#include <cuda_runtime.h>
#include <math.h>

#define Bb      64
#define Tt      128
#define Dd      768
#define Hh      256
#define NSPANS  8256
#define KTOP    256
#define XST     68          // proj w stride
#define RST     132         // proj xs row-stride
#define SXST    68          // scorer/head xs row-stride (64 rows + pad, 16B-aligned)
#define PCH     32          // proj k-chunk size

typedef unsigned long long u64;

// ---------------- packed fp32x2 helpers (sm_103a FFMA2 path) ----------------
__device__ __forceinline__ u64 dup2(float a) {
    u64 r; asm("mov.b64 %0, {%1, %2};" : "=l"(r) : "f"(a), "f"(a)); return r;
}
__device__ __forceinline__ void fma2(u64& acc, u64 a, u64 b) {
    asm("fma.rn.f32x2 %0, %1, %2, %0;" : "+l"(acc) : "l"(a), "l"(b));
}
__device__ __forceinline__ void unpack2(float& lo, float& hi, u64 v) {
    asm("mov.b64 {%0, %1}, %2;" : "=f"(lo), "=f"(hi) : "l"(v));
}

// ---------------- device scratch ----------------
__device__ float g_A[Bb*Tt*Hh];
__device__ float g_E[Bb*Tt*Hh];
__device__ float g_scores[Bb*NSPANS];
__device__ float g_inj[Bb*Hh];
__device__ int   g_topidx[Bb*KTOP];
__device__ float g_topscore[Bb*KTOP];
__device__ int   g_sarr[NSPANS];
__device__ int   g_earr[NSPANS];

// ---------------- span index decode ----------------
__global__ void build_span_idx_kernel() {
    int n = blockIdx.x * blockDim.x + threadIdx.x;
    if (n >= NSPANS) return;
    int s = 0, off = 0;
    while (n >= off + (Tt - s)) { off += (Tt - s); s++; }
    g_sarr[n] = s;
    g_earr[n] = s + (n - off);
}

// ---------------- projections (round-14, unchanged) ----------------
__global__ __launch_bounds__(256)
void proj_kernel(const float* __restrict__ X,
                 const float* __restrict__ Wst, const float* __restrict__ bst,
                 const float* __restrict__ Wen, const float* __restrict__ ben) {
    const float* W    = blockIdx.z ? Wen : Wst;
    const float* bias = blockIdx.z ? ben : bst;
    float*       Out  = blockIdx.z ? g_E : g_A;

    __shared__ float xs[2][PCH * RST];
    __shared__ float wsm[2][PCH * XST];

    const int row0 = blockIdx.y * 128;
    const int col0 = blockIdx.x * 64;
    const int tid  = threadIdx.x;
    const int tx   = tid & 15, ty = tid >> 4;

    const int kq = tid & 7;
    const int rX = tid >> 3;
    const int cq = tid & 15;
    const int kW = tid >> 4;

    const float* Xb = X + (u64)row0 * Dd + 4 * kq;
    const float* Wb = W + col0 + 4 * cq;

    float4 px0 = *(const float4*)(Xb + (u64)(rX)      * Dd);
    float4 px1 = *(const float4*)(Xb + (u64)(rX + 32) * Dd);
    float4 px2 = *(const float4*)(Xb + (u64)(rX + 64) * Dd);
    float4 px3 = *(const float4*)(Xb + (u64)(rX + 96) * Dd);
    float4 pw0 = *(const float4*)(Wb + (u64)kW        * Hh);
    float4 pw1 = *(const float4*)(Wb + (u64)(kW + 16) * Hh);

    {
        float* xd = xs[0];
        xd[(4*kq+0) * RST + rX] = px0.x; xd[(4*kq+1) * RST + rX] = px0.y;
        xd[(4*kq+2) * RST + rX] = px0.z; xd[(4*kq+3) * RST + rX] = px0.w;
        xd[(4*kq+0) * RST + rX+32] = px1.x; xd[(4*kq+1) * RST + rX+32] = px1.y;
        xd[(4*kq+2) * RST + rX+32] = px1.z; xd[(4*kq+3) * RST + rX+32] = px1.w;
        xd[(4*kq+0) * RST + rX+64] = px2.x; xd[(4*kq+1) * RST + rX+64] = px2.y;
        xd[(4*kq+2) * RST + rX+64] = px2.z; xd[(4*kq+3) * RST + rX+64] = px2.w;
        xd[(4*kq+0) * RST + rX+96] = px3.x; xd[(4*kq+1) * RST + rX+96] = px3.y;
        xd[(4*kq+2) * RST + rX+96] = px3.z; xd[(4*kq+3) * RST + rX+96] = px3.w;
        *(float4*)(wsm[0] + kW * XST + 4 * cq)        = pw0;
        *(float4*)(wsm[0] + (kW + 16) * XST + 4 * cq) = pw1;
    }
    __syncthreads();

    u64 acc[4][4] = {};

    #pragma unroll 1
    for (int kc = 0; kc < Dd / PCH; kc++) {
        const int buf = kc & 1;
        if (kc < Dd / PCH - 1) {
            const float* Xn = Xb + (kc + 1) * PCH;
            const float* Wn = Wb + (u64)(kc + 1) * PCH * Hh;
            px0 = *(const float4*)(Xn + (u64)(rX)      * Dd);
            px1 = *(const float4*)(Xn + (u64)(rX + 32) * Dd);
            px2 = *(const float4*)(Xn + (u64)(rX + 64) * Dd);
            px3 = *(const float4*)(Xn + (u64)(rX + 96) * Dd);
            pw0 = *(const float4*)(Wn + (u64)kW        * Hh);
            pw1 = *(const float4*)(Wn + (u64)(kW + 16) * Hh);
        }

        const float* xp = xs[buf] + (ty << 3);
        const float* wp = wsm[buf] + (tx << 2);
        #pragma unroll 8
        for (int k = 0; k < PCH; k++) {
            float4 wv = *(const float4*)(wp + k * XST);
            u64 e0 = dup2(wv.x), e1 = dup2(wv.y), e2 = dup2(wv.z), e3 = dup2(wv.w);
            ulonglong2 p0 = *(const ulonglong2*)(xp + k * RST);
            ulonglong2 p1 = *(const ulonglong2*)(xp + k * RST + 4);
            u64 r0 = p0.x, r1 = p0.y, r2 = p1.x, r3 = p1.y;
            fma2(acc[0][0], r0, e0); fma2(acc[0][1], r0, e1);
            fma2(acc[0][2], r0, e2); fma2(acc[0][3], r0, e3);
            fma2(acc[1][0], r1, e0); fma2(acc[1][1], r1, e1);
            fma2(acc[1][2], r1, e2); fma2(acc[1][3], r1, e3);
            fma2(acc[2][0], r2, e0); fma2(acc[2][1], r2, e1);
            fma2(acc[2][2], r2, e2); fma2(acc[2][3], r2, e3);
            fma2(acc[3][0], r3, e0); fma2(acc[3][1], r3, e1);
            fma2(acc[3][2], r3, e2); fma2(acc[3][3], r3, e3);
        }

        if (kc < Dd / PCH - 1) {
            const int nb = buf ^ 1;
            float* xd = xs[nb];
            xd[(4*kq+0) * RST + rX] = px0.x; xd[(4*kq+1) * RST + rX] = px0.y;
            xd[(4*kq+2) * RST + rX] = px0.z; xd[(4*kq+3) * RST + rX] = px0.w;
            xd[(4*kq+0) * RST + rX+32] = px1.x; xd[(4*kq+1) * RST + rX+32] = px1.y;
            xd[(4*kq+2) * RST + rX+32] = px1.z; xd[(4*kq+3) * RST + rX+32] = px1.w;
            xd[(4*kq+0) * RST + rX+64] = px2.x; xd[(4*kq+1) * RST + rX+64] = px2.y;
            xd[(4*kq+2) * RST + rX+64] = px2.z; xd[(4*kq+3) * RST + rX+64] = px2.w;
            xd[(4*kq+0) * RST + rX+96] = px3.x; xd[(4*kq+1) * RST + rX+96] = px3.y;
            xd[(4*kq+2) * RST + rX+96] = px3.z; xd[(4*kq+3) * RST + rX+96] = px3.w;
            *(float4*)(wsm[nb] + kW * XST + 4 * cq)        = pw0;
            *(float4*)(wsm[nb] + (kW + 16) * XST + 4 * cq) = pw1;
        }
        __syncthreads();
    }

    #pragma unroll
    for (int rp = 0; rp < 4; rp++) {
        int row = row0 + (ty << 3) + 2 * rp;
        #pragma unroll
        for (int c = 0; c < 4; c++) {
            float lo, hi; unpack2(lo, hi, acc[rp][c]);
            int col = col0 + (tx << 2) + c;
            Out[row * Hh + col]       = lo + bias[col];
            Out[(row + 1) * Hh + col] = hi + bias[col];
        }
    }
}

// ---------------- injection projection ----------------
__global__ void inj_kernel(const float* __restrict__ tie,
                           const float* __restrict__ Winj, const float* __restrict__ binj) {
    int b = blockIdx.x;
    int j = threadIdx.x;
    __shared__ float t[128];
    if (j < 128) t[j] = tie[b * 128 + j];
    __syncthreads();
    float acc = binj[j];
    #pragma unroll 8
    for (int k = 0; k < 128; k++) acc = fmaf(t[k], Winj[k * Hh + j], acc);
    g_inj[b * Hh + j] = acc;
}

// ---------------- common smem layout (scorer & head) ----------------
#define SN_BIAS_OFF    (256 * SXST)
#define SN_W2_OFF      (SN_BIAS_OFF + 256)
#define SN_RED_OFF     (SN_W2_OFF + 256)
#define SN_SMEM_FLOATS (SN_RED_OFF + 64 * 65)
static const int SN_SMEM_BYTES = SN_SMEM_FLOATS * 4;   // 88,320 B -> 2 CTAs/SM

#define SC_BODY(WV, AP)                                                    \
    {                                                                      \
        u64 e0 = dup2((WV).x), e1 = dup2((WV).y),                          \
            e2 = dup2((WV).z), e3 = dup2((WV).w);                          \
        ulonglong2 p0 = *(const ulonglong2*)(AP);                          \
        ulonglong2 p1 = *(const ulonglong2*)((AP) + 2);                    \
        ulonglong2 p2 = *(const ulonglong2*)((AP) + 4);                    \
        ulonglong2 p3 = *(const ulonglong2*)((AP) + 6);                    \
        u64 r0 = p0.x, r1 = p0.y, r2 = p1.x, r3 = p1.y;                    \
        u64 r4 = p2.x, r5 = p2.y, r6 = p3.x, r7 = p3.y;                    \
        fma2(acc[0][0], r0, e0); fma2(acc[0][1], r0, e1);                  \
        fma2(acc[0][2], r0, e2); fma2(acc[0][3], r0, e3);                  \
        fma2(acc[1][0], r1, e0); fma2(acc[1][1], r1, e1);                  \
        fma2(acc[1][2], r1, e2); fma2(acc[1][3], r1, e3);                  \
        fma2(acc[2][0], r2, e0); fma2(acc[2][1], r2, e1);                  \
        fma2(acc[2][2], r2, e2); fma2(acc[2][3], r2, e3);                  \
        fma2(acc[3][0], r3, e0); fma2(acc[3][1], r3, e1);                  \
        fma2(acc[3][2], r3, e2); fma2(acc[3][3], r3, e3);                  \
        fma2(acc[4][0], r4, e0); fma2(acc[4][1], r4, e1);                  \
        fma2(acc[4][2], r4, e2); fma2(acc[4][3], r4, e3);                  \
        fma2(acc[5][0], r5, e0); fma2(acc[5][1], r5, e1);                  \
        fma2(acc[5][2], r5, e2); fma2(acc[5][3], r5, e3);                  \
        fma2(acc[6][0], r6, e0); fma2(acc[6][1], r6, e1);                  \
        fma2(acc[6][2], r6, e2); fma2(acc[6][3], r6, e3);                  \
        fma2(acc[7][0], r7, e0); fma2(acc[7][1], r7, e1);                  \
        fma2(acc[7][2], r7, e2); fma2(acc[7][3], r7, e3);                  \
    }

// ---------------- scorer (round-15, unchanged) ----------------
__global__ __launch_bounds__(256, 2)
void scorer_kernel(const float* __restrict__ Ws1, const float* __restrict__ bs1,
                   const float* __restrict__ Ws2, const float* __restrict__ bs2) {
    extern __shared__ float sm[];
    float* xs   = sm;
    float* bs1c = sm + SN_BIAS_OFF;
    float* w2c  = sm + SN_W2_OFF;
    float* red  = sm + SN_RED_OFF;
    __shared__ int sS[64], sE[64];

    const int b   = blockIdx.y;
    const int n0  = blockIdx.x * 64;
    const int tid = threadIdx.x;
    const int tx  = tid & 63;
    const int ty  = tid >> 6;

    if (tid < 64) {
        sS[tid] = g_sarr[n0 + tid]; sE[tid] = g_earr[n0 + tid];
    }
    bs1c[tid] = bs1[tid];
    w2c[tid]  = Ws2[tid];
    __syncthreads();

    {
        const float* Ab = g_A + b * Tt * Hh + tid;
        const float* Eb = g_E + b * Tt * Hh + tid;
        float* xp = xs + tid * SXST;
        #pragma unroll 4
        for (int r = 0; r < 64; r++) {
            float v = Ab[sS[r] * Hh] + Eb[sE[r] * Hh];
            xp[r] = v > 0.f ? v : 0.f;
        }
    }
    __syncthreads();

    const float4* Wg = ((const float4*)Ws1) + tx;
    float4 pfa = Wg[0];
    float4 pfb = Wg[64];

    const float* xp = xs + (ty << 4);
    u64 acc[8][4] = {};

    #pragma unroll 8
    for (int k = 0; k < 256; k++) {
        float4 wv;
        int kp = (k + 2) & 255;
        if (k & 1) { wv = pfb; pfb = Wg[kp << 6]; }
        else       { wv = pfa; pfa = Wg[kp << 6]; }
        const u64* ap = (const u64*)(xp + k * SXST);
        SC_BODY(wv, ap);
    }

    float scacc[16];
    #pragma unroll
    for (int i = 0; i < 16; i++) scacc[i] = 0.f;
    #pragma unroll
    for (int rp = 0; rp < 8; rp++) {
        #pragma unroll
        for (int c = 0; c < 4; c++) {
            float lo, hi; unpack2(lo, hi, acc[rp][c]);
            int cb = (tx << 2) + c;
            float h0 = lo + bs1c[cb];
            if (h0 > 0.f) scacc[2 * rp]     = fmaf(h0, w2c[cb], scacc[2 * rp]);
            float h1 = hi + bs1c[cb];
            if (h1 > 0.f) scacc[2 * rp + 1] = fmaf(h1, w2c[cb], scacc[2 * rp + 1]);
        }
    }

    #pragma unroll
    for (int i = 0; i < 16; i++) red[((ty << 4) + i) * 65 + tx] = scacc[i];
    __syncthreads();
    if (tid < 64) {
        float ssum = bs2[0];
        const float* rp = red + tid * 65;
        #pragma unroll
        for (int t = 0; t < 64; t++) ssum += rp[t];
        g_scores[b * NSPANS + n0 + tid] = ssum;
    }
}

// ---------------- block inclusive scan (256 threads) ----------------
__device__ __forceinline__ int block_incl_scan(int v, int tid, int* wsums) {
    __syncthreads();
    int lane = tid & 31, wid = tid >> 5;
    #pragma unroll
    for (int o = 1; o < 32; o <<= 1) {
        int n = __shfl_up_sync(0xffffffffu, v, o);
        if (lane >= o) v += n;
    }
    if (lane == 31) wsums[wid] = v;
    __syncthreads();
    if (tid == 0) {
        int s = 0;
        #pragma unroll
        for (int w = 0; w < 8; w++) { int x = wsums[w]; wsums[w] = s; s += x; }
    }
    __syncthreads();
    return v + wsums[wid];
}

// ---------------- per-batch radix top-k (round-13, unchanged) ----------------
__global__ void topk_kernel(const int* __restrict__ mask) {
    const int b   = blockIdx.x;
    const int tid = threadIdx.x;
    __shared__ unsigned keys[NSPANS];
    __shared__ int hist[256];
    __shared__ unsigned sh_prefix;
    __shared__ int sh_kk;
    __shared__ int wsums[8];

    const int* mb = mask + b * Tt;
    for (int i = tid; i < NSPANS; i += 256) {
        int s = g_sarr[i], e = g_earr[i];
        float v = (mb[s] != 0 && mb[e] != 0) ? g_scores[b * NSPANS + i]
                                             : __int_as_float(0xff800000);
        unsigned u = __float_as_uint(v);
        keys[i] = (u & 0x80000000u) ? ~u : (u | 0x80000000u);
    }

    unsigned prefix = 0;
    int kk = KTOP;
    for (int level = 3; level >= 0; level--) {
        hist[tid] = 0;
        __syncthreads();
        const unsigned himask = (level == 3) ? 0u : (0xFFFFFFFFu << ((level + 1) * 8));
        for (int i = tid; i < NSPANS; i += 256) {
            unsigned kv = keys[i];
            if ((kv & himask) == (prefix & himask))
                atomicAdd(&hist[(kv >> (level * 8)) & 255], 1);
        }
        __syncthreads();
        int bucket = 255 - tid;
        int v = hist[bucket];
        int S = block_incl_scan(v, tid, wsums);
        if (S >= kk && S - v < kk) {
            sh_prefix = prefix | ((unsigned)bucket << (level * 8));
            sh_kk = kk - (S - v);
        }
        __syncthreads();
        prefix = sh_prefix;
        kk = sh_kk;
        __syncthreads();
    }

    const unsigned Kstar = prefix;
    const int CH = (NSPANS + 255) / 256;
    int lo = tid * CH; if (lo > NSPANS) lo = NSPANS;
    int hi = lo + CH;  if (hi > NSPANS) hi = NSPANS;

    int cgt = 0, ceq = 0;
    for (int i = lo; i < hi; i++) {
        unsigned kv = keys[i];
        cgt += (kv > Kstar);
        ceq += (kv == Kstar);
    }
    int Sg = block_incl_scan(cgt, tid, wsums);
    int Se = block_incl_scan(ceq, tid, wsums);
    int gtb = Sg - cgt, eqb = Se - ceq;

    for (int i = lo; i < hi; i++) {
        unsigned kv = keys[i];
        bool isgt = (kv > Kstar);
        bool iseq = (kv == Kstar);
        if (isgt || (iseq && eqb < kk)) {
            int eqt = eqb < kk ? eqb : kk;
            int pos = gtb + eqt;
            unsigned u = (kv & 0x80000000u) ? (kv & 0x7FFFFFFFu) : ~kv;
            g_topidx[b * KTOP + pos]   = i;
            g_topscore[b * KTOP + pos] = __uint_as_float(u);
        }
        gtb += isgt;
        eqb += iseq;
    }
}

// ---------------- head: direct-LDG barrier-free clone of the scorer ----------------
__global__ __launch_bounds__(256, 2)
void head_kernel(const float* __restrict__ Wsec, const float* __restrict__ bsec,
                 const float* __restrict__ Wpred, const float* __restrict__ bpred,
                 const int* __restrict__ mask, float* __restrict__ out) {
    extern __shared__ float sm[];
    float* xs  = sm;
    float* bc  = sm + SN_BIAS_OFF;
    float* wpc = sm + SN_W2_OFF;
    float* red = sm + SN_RED_OFF;
    __shared__ int sS[64], sE[64];
    __shared__ float sMask[64], sScore[64];

    const int b   = blockIdx.y;
    const int k0  = blockIdx.x * 64;
    const int tid = threadIdx.x;
    const int tx  = tid & 63;
    const int ty  = tid >> 6;

    if (tid < 64) {
        int n = g_topidx[b * KTOP + k0 + tid];
        int s = g_sarr[n], e = g_earr[n];
        sS[tid] = s; sE[tid] = e;
        sMask[tid] = (mask[b * Tt + s] != 0 && mask[b * Tt + e] != 0) ? 1.f : 0.f;
        float sc = g_topscore[b * KTOP + k0 + tid];
        sScore[tid] = isinf(sc) ? -1.f : sc;
    }
    bc[tid]  = bsec[tid] + g_inj[b * Hh + tid];
    wpc[tid] = Wpred[tid];
    __syncthreads();

    {
        const float* Ab = g_A + b * Tt * Hh + tid;
        const float* Eb = g_E + b * Tt * Hh + tid;
        float* xp = xs + tid * SXST;
        #pragma unroll 4
        for (int r = 0; r < 64; r++)
            xp[r] = Ab[sS[r] * Hh] + Eb[sE[r] * Hh];   // no relu
    }
    __syncthreads();

    const float4* Wg = ((const float4*)Wsec) + tx;
    float4 pfa = Wg[0];
    float4 pfb = Wg[64];

    const float* xp = xs + (ty << 4);
    u64 acc[8][4] = {};

    #pragma unroll 8
    for (int k = 0; k < 256; k++) {
        float4 wv;
        int kp = (k + 2) & 255;
        if (k & 1) { wv = pfb; pfb = Wg[kp << 6]; }
        else       { wv = pfa; pfa = Wg[kp << 6]; }
        const u64* ap = (const u64*)(xp + k * SXST);
        SC_BODY(wv, ap);
    }

    float scacc[16];
    #pragma unroll
    for (int i = 0; i < 16; i++) scacc[i] = 0.f;
    #pragma unroll
    for (int rp = 0; rp < 8; rp++) {
        #pragma unroll
        for (int c = 0; c < 4; c++) {
            float lo, hi; unpack2(lo, hi, acc[rp][c]);
            int cb = (tx << 2) + c;
            float h0 = lo + bc[cb];
            if (h0 > 0.f) scacc[2 * rp]     = fmaf(h0, wpc[cb], scacc[2 * rp]);
            float h1 = hi + bc[cb];
            if (h1 > 0.f) scacc[2 * rp + 1] = fmaf(h1, wpc[cb], scacc[2 * rp + 1]);
        }
    }

    #pragma unroll
    for (int i = 0; i < 16; i++) red[((ty << 4) + i) * 65 + tx] = scacc[i];
    __syncthreads();
    if (tid < 64) {
        float ssum = bpred[0] + sScore[tid];
        const float* rp = red + tid * 65;
        #pragma unroll
        for (int t = 0; t < 64; t++) ssum += rp[t];
        float p = 1.f / (1.f + expf(-ssum));
        out[b * KTOP + k0 + tid] = p * sMask[tid];
    }
}

// ---------------- launch ----------------
extern "C" void kernel_launch(void* const* d_in, const int* in_sizes, int n_in,
                              void* d_out, int out_size) {
    const float* inputs   = (const float*)d_in[0];
    const int*   in_mask  = (const int*)  d_in[1];
    const float* tie      = (const float*)d_in[2];
    const float* W_start  = (const float*)d_in[3];
    const float* b_start  = (const float*)d_in[4];
    const float* W_end    = (const float*)d_in[5];
    const float* b_end    = (const float*)d_in[6];
    const float* W_s1     = (const float*)d_in[7];
    const float* b_s1     = (const float*)d_in[8];
    const float* W_s2     = (const float*)d_in[9];
    const float* b_s2     = (const float*)d_in[10];
    const float* W_inj    = (const float*)d_in[11];
    const float* b_inj    = (const float*)d_in[12];
    const float* W_sec    = (const float*)d_in[13];
    const float* b_sec    = (const float*)d_in[14];
    const float* W_pred   = (const float*)d_in[15];
    const float* b_pred   = (const float*)d_in[16];
    float* out = (float*)d_out;

    cudaFuncSetAttribute(scorer_kernel, cudaFuncAttributeMaxDynamicSharedMemorySize, SN_SMEM_BYTES);
    cudaFuncSetAttribute(head_kernel,   cudaFuncAttributeMaxDynamicSharedMemorySize, SN_SMEM_BYTES);

    build_span_idx_kernel<<<(NSPANS + 255) / 256, 256>>>();
    proj_kernel<<<dim3(Hh / 64, (Bb * Tt) / 128, 2), 256>>>(inputs, W_start, b_start, W_end, b_end);
    inj_kernel<<<Bb, 256>>>(tie, W_inj, b_inj);
    scorer_kernel<<<dim3(NSPANS / 64, Bb), 256, SN_SMEM_BYTES>>>(W_s1, b_s1, W_s2, b_s2);
    topk_kernel<<<Bb, 256>>>(in_mask);
    head_kernel<<<dim3(KTOP / 64, Bb), 256, SN_SMEM_BYTES>>>(W_sec, b_sec, W_pred, b_pred, in_mask, out);
}